// round 3
// baseline (speedup 1.0000x reference)
#include <cuda_runtime.h>
#include <cuda_bf16.h>
#include <cstring>
#include <cstdint>

#define TLEN   4096
#define DMODEL 1024
#define NHEADS 16
#define HDIM   64

// ---------------- device scratch (static: allocation-free) ----------------
__device__ __nv_bfloat16 g_xh[TLEN * DMODEL], g_xl[TLEN * DMODEL];
__device__ __nv_bfloat16 g_wh[4 * DMODEL * DMODEL], g_wl[4 * DMODEL * DMODEL];
__device__ __nv_bfloat16 g_qh[NHEADS * TLEN * HDIM], g_ql[NHEADS * TLEN * HDIM];
__device__ __nv_bfloat16 g_kh[NHEADS * TLEN * HDIM], g_kl[NHEADS * TLEN * HDIM];
__device__ __nv_bfloat16 g_vh[NHEADS * TLEN * HDIM], g_vl[NHEADS * TLEN * HDIM];
__device__ __nv_bfloat16 g_oh[TLEN * DMODEL], g_ol[TLEN * DMODEL];

// ---------------- fastexp_gist: exact Schraudolph semantics ----------------
__device__ __forceinline__ float fastexp_g(float x) {
    const float GA = (float)12102203.17133801;
    const float GB = (float)1064986823.010288;
    const float GC = 8388608.0f;
    const float GD = 2139095040.0f;
    float y = __fadd_rn(__fmul_rn(GA, x), GB);
    int yi = (y < GC || y > GD) ? 0 : __float2int_rz(y);
    return __int_as_float(yi);
}

// ---------------- MMA / LDSM helpers ----------------
__device__ __forceinline__ uint32_t sptr(const char* p) {
    return (uint32_t)__cvta_generic_to_shared(p);
}
__device__ __forceinline__ void ldsm4(uint32_t a, uint32_t& r0, uint32_t& r1,
                                      uint32_t& r2, uint32_t& r3) {
    asm volatile("ldmatrix.sync.aligned.m8n8.x4.shared.b16 {%0,%1,%2,%3}, [%4];"
                 : "=r"(r0), "=r"(r1), "=r"(r2), "=r"(r3) : "r"(a));
}
__device__ __forceinline__ void ldsm4t(uint32_t a, uint32_t& r0, uint32_t& r1,
                                       uint32_t& r2, uint32_t& r3) {
    asm volatile("ldmatrix.sync.aligned.m8n8.x4.trans.shared.b16 {%0,%1,%2,%3}, [%4];"
                 : "=r"(r0), "=r"(r1), "=r"(r2), "=r"(r3) : "r"(a));
}
__device__ __forceinline__ void mma16816(float* c, const uint32_t* a,
                                         uint32_t b0, uint32_t b1) {
    asm volatile(
        "mma.sync.aligned.m16n8k16.row.col.f32.bf16.bf16.f32 "
        "{%0,%1,%2,%3}, {%4,%5,%6,%7}, {%8,%9}, {%0,%1,%2,%3};"
        : "+f"(c[0]), "+f"(c[1]), "+f"(c[2]), "+f"(c[3])
        : "r"(a[0]), "r"(a[1]), "r"(a[2]), "r"(a[3]), "r"(b0), "r"(b1));
}

// byte offset of the 16B chunk (row, ch) in a 64-col bf16 tile (128B rows), swizzled
__device__ __forceinline__ int sw128B(int row, int ch) {
    return (row << 7) + ((ch ^ (row & 7)) << 4);
}
// byte offset in a 128-col bf16 tile (256B rows), swizzled (16 chunks)
__device__ __forceinline__ int sw256B(int row, int ch) {
    return (row << 8) + (((ch & 8) | ((ch & 7) ^ (row & 7))) << 4);
}

__device__ __forceinline__ void split2(float v0, float v1, uint32_t& ph, uint32_t& pl) {
    __nv_bfloat16 h0 = __float2bfloat16(v0), h1 = __float2bfloat16(v1);
    __nv_bfloat16 l0 = __float2bfloat16(v0 - __bfloat162float(h0));
    __nv_bfloat16 l1 = __float2bfloat16(v1 - __bfloat162float(h1));
    ph = (uint32_t)__bfloat16_as_ushort(h0) | ((uint32_t)__bfloat16_as_ushort(h1) << 16);
    pl = (uint32_t)__bfloat16_as_ushort(l0) | ((uint32_t)__bfloat16_as_ushort(l1) << 16);
}

// ---------------- split (fp32 -> bf16 hi/lo planes) ----------------
__global__ void split_kernel(const float* __restrict__ src, int sel, int n) {
    __nv_bfloat16 *hi, *lo;
    switch (sel) {
        case 0:  hi = g_xh; lo = g_xl; break;
        case 1:  hi = g_wh; lo = g_wl; break;
        case 2:  hi = g_wh + 1 * DMODEL * DMODEL; lo = g_wl + 1 * DMODEL * DMODEL; break;
        case 3:  hi = g_wh + 2 * DMODEL * DMODEL; lo = g_wl + 2 * DMODEL * DMODEL; break;
        default: hi = g_wh + 3 * DMODEL * DMODEL; lo = g_wl + 3 * DMODEL * DMODEL; break;
    }
    for (int i = blockIdx.x * blockDim.x + threadIdx.x; i < n;
         i += gridDim.x * blockDim.x) {
        float v = src[i];
        __nv_bfloat16 h = __float2bfloat16(v);
        hi[i] = h;
        lo[i] = __float2bfloat16(v - __bfloat162float(h));
    }
}

// ============================================================================
// Split-bf16 tensor GEMM: C[4096,1024] = A @ W^T (+bias)
// 128x128 block tile, kc=64, 256 threads (8 warps, 2x4), m16n8k16 bf16 mma.
// c_sel 0/1/2 -> q/k/v head-major split-bf16; 3 -> fp32 dout.
// ============================================================================
#define GEMM_SMEM 65536

__global__ __launch_bounds__(256, 1)
void gemm_bf16(int a_sel, int w_idx, const float* __restrict__ bias,
               float* __restrict__ dout, int c_sel)
{
    extern __shared__ char sm[];
    char* sAh = sm;
    char* sAl = sm + 16384;
    char* sWh = sm + 32768;
    char* sWl = sm + 49152;

    const __nv_bfloat16* Ah = a_sel ? g_oh : g_xh;
    const __nv_bfloat16* Al = a_sel ? g_ol : g_xl;
    const __nv_bfloat16* Wh = g_wh + (size_t)w_idx * DMODEL * DMODEL;
    const __nv_bfloat16* Wl = g_wl + (size_t)w_idx * DMODEL * DMODEL;

    const int tid = threadIdx.x;
    const int lane = tid & 31, wid = tid >> 5;
    const int g = lane >> 2, tg = lane & 3;
    const int wm = wid >> 2, wn = wid & 3;
    const int m0 = blockIdx.y * 128, n0 = blockIdx.x * 128;

    float c[4][4][4];
    #pragma unroll
    for (int i = 0; i < 4; i++)
        #pragma unroll
        for (int j = 0; j < 4; j++)
            #pragma unroll
            for (int e = 0; e < 4; e++) c[i][j][e] = 0.f;

    for (int k0 = 0; k0 < DMODEL; k0 += 64) {
        __syncthreads();
        #pragma unroll
        for (int p = 0; p < 4; p++) {
            int idx = p * 256 + tid;
            int r = idx >> 3, ch = idx & 7;
            size_t ga = (size_t)(m0 + r) * DMODEL + k0 + ch * 8;
            size_t gw = (size_t)(n0 + r) * DMODEL + k0 + ch * 8;
            *(uint4*)(sAh + sw128B(r, ch)) = *(const uint4*)(Ah + ga);
            *(uint4*)(sAl + sw128B(r, ch)) = *(const uint4*)(Al + ga);
            *(uint4*)(sWh + sw128B(r, ch)) = *(const uint4*)(Wh + gw);
            *(uint4*)(sWl + sw128B(r, ch)) = *(const uint4*)(Wl + gw);
        }
        __syncthreads();

        #pragma unroll
        for (int kt = 0; kt < 4; kt++) {
            uint32_t ah[4][4], al[4][4];
            const int ar = (lane & 8) + (lane & 7);
            const int ac = kt * 2 + (lane >> 4);
            #pragma unroll
            for (int mi = 0; mi < 4; mi++) {
                int r = wm * 64 + mi * 16 + ar;
                ldsm4(sptr(sAh + sw128B(r, ac)), ah[mi][0], ah[mi][1], ah[mi][2], ah[mi][3]);
                ldsm4(sptr(sAl + sw128B(r, ac)), al[mi][0], al[mi][1], al[mi][2], al[mi][3]);
            }
            uint32_t bh[2][4], bl[2][4];
            const int br = ((lane >> 4) << 3) + (lane & 7);
            const int bc = kt * 2 + ((lane >> 3) & 1);
            #pragma unroll
            for (int pr = 0; pr < 2; pr++) {
                int r = wn * 32 + pr * 16 + br;
                ldsm4(sptr(sWh + sw128B(r, bc)), bh[pr][0], bh[pr][1], bh[pr][2], bh[pr][3]);
                ldsm4(sptr(sWl + sw128B(r, bc)), bl[pr][0], bl[pr][1], bl[pr][2], bl[pr][3]);
            }
            #pragma unroll
            for (int mi = 0; mi < 4; mi++)
                #pragma unroll
                for (int ni = 0; ni < 4; ni++) {
                    uint32_t b0h = bh[ni >> 1][(ni & 1) * 2], b1h = bh[ni >> 1][(ni & 1) * 2 + 1];
                    uint32_t b0l = bl[ni >> 1][(ni & 1) * 2], b1l = bl[ni >> 1][(ni & 1) * 2 + 1];
                    mma16816(c[mi][ni], ah[mi], b0h, b1h);
                    mma16816(c[mi][ni], ah[mi], b0l, b1l);
                    mma16816(c[mi][ni], al[mi], b0h, b1h);
                }
        }
    }

    // epilogue
    __nv_bfloat16 *dsth = nullptr, *dstl = nullptr;
    if (c_sel == 0) { dsth = g_qh; dstl = g_ql; }
    else if (c_sel == 1) { dsth = g_kh; dstl = g_kl; }
    else if (c_sel == 2) { dsth = g_vh; dstl = g_vl; }

    #pragma unroll
    for (int mi = 0; mi < 4; mi++)
        #pragma unroll
        for (int ni = 0; ni < 4; ni++)
            #pragma unroll
            for (int inst = 0; inst < 2; inst++) {
                int m = m0 + wm * 64 + mi * 16 + inst * 8 + g;
                int n = n0 + wn * 32 + ni * 8 + 2 * tg;
                float b0 = bias ? bias[n] : 0.f;
                float b1 = bias ? bias[n + 1] : 0.f;
                float v0 = c[mi][ni][inst * 2] + b0;
                float v1 = c[mi][ni][inst * 2 + 1] + b1;
                if (c_sel < 3) {
                    uint32_t ph, pl;
                    split2(v0, v1, ph, pl);
                    size_t addr = ((size_t)(n >> 6) * TLEN + m) * HDIM + (n & 63);
                    *(uint32_t*)(dsth + addr) = ph;
                    *(uint32_t*)(dstl + addr) = pl;
                } else {
                    float2 r; r.x = v0; r.y = v1;
                    *(float2*)(dout + (size_t)m * DMODEL + n) = r;
                }
            }
}

// ============================================================================
// Tensor-core two-pass attention. Per (head, 128-query block), 256 threads.
// Pass 1: rowmax of scaled scores. Pass 2: recompute, fastexp, split-E, PV.
// ============================================================================
#define ATTN_SMEM 166912

__global__ __launch_bounds__(256, 1)
void attn_kernel(float scaling)
{
    extern __shared__ char sm[];
    char* sQh = sm;
    char* sQl = sm + 16384;
    char* sKh = sm + 32768;
    char* sKl = sm + 49152;
    char* sVh = sm + 65536;
    char* sVl = sm + 81920;
    char* sEh = sm + 98304;
    char* sEl = sm + 131072;
    float* red    = (float*)(sm + 163840);          // [4][128]
    float* rowmax = (float*)(sm + 163840 + 2048);   // [128]
    float* rowsum = rowmax + 128;                   // [128]

    const int tid = threadIdx.x;
    const int lane = tid & 31, wid = tid >> 5;
    const int g = lane >> 2, tg = lane & 3;
    const int wm = wid >> 2, wn = wid & 3;
    const int h = blockIdx.y;
    const int t0 = blockIdx.x * 128;

    const __nv_bfloat16* Qh = g_qh + ((size_t)h * TLEN + t0) * HDIM;
    const __nv_bfloat16* Qlp = g_ql + ((size_t)h * TLEN + t0) * HDIM;
    const __nv_bfloat16* Kh = g_kh + (size_t)h * TLEN * HDIM;
    const __nv_bfloat16* Klp = g_kl + (size_t)h * TLEN * HDIM;
    const __nv_bfloat16* Vh = g_vh + (size_t)h * TLEN * HDIM;
    const __nv_bfloat16* Vlp = g_vl + (size_t)h * TLEN * HDIM;

    // ---- load Q tile ----
    #pragma unroll
    for (int p = 0; p < 4; p++) {
        int idx = p * 256 + tid;
        int r = idx >> 3, ch = idx & 7;
        size_t go = (size_t)r * HDIM + ch * 8;
        *(uint4*)(sQh + sw128B(r, ch)) = *(const uint4*)(Qh + go);
        *(uint4*)(sQl + sw128B(r, ch)) = *(const uint4*)(Qlp + go);
    }

    float rmax[4][2];
    #pragma unroll
    for (int i = 0; i < 4; i++) { rmax[i][0] = -3.402823466e38f; rmax[i][1] = -3.402823466e38f; }

    const int ar = (lane & 8) + (lane & 7);
    const int br = ((lane >> 4) << 3) + (lane & 7);

    // ======================= pass 1: row max =======================
    for (int st = 0; st < TLEN / 128; st++) {
        __syncthreads();
        #pragma unroll
        for (int p = 0; p < 4; p++) {
            int idx = p * 256 + tid;
            int r = idx >> 3, ch = idx & 7;
            size_t go = (size_t)(st * 128 + r) * HDIM + ch * 8;
            *(uint4*)(sKh + sw128B(r, ch)) = *(const uint4*)(Kh + go);
            *(uint4*)(sKl + sw128B(r, ch)) = *(const uint4*)(Klp + go);
        }
        __syncthreads();

        float c[4][4][4];
        #pragma unroll
        for (int i = 0; i < 4; i++)
            #pragma unroll
            for (int j = 0; j < 4; j++)
                #pragma unroll
                for (int e = 0; e < 4; e++) c[i][j][e] = 0.f;

        #pragma unroll
        for (int kt = 0; kt < 4; kt++) {
            uint32_t ah[4][4], al[4][4];
            const int ac = kt * 2 + (lane >> 4);
            #pragma unroll
            for (int mi = 0; mi < 4; mi++) {
                int r = wm * 64 + mi * 16 + ar;
                ldsm4(sptr(sQh + sw128B(r, ac)), ah[mi][0], ah[mi][1], ah[mi][2], ah[mi][3]);
                ldsm4(sptr(sQl + sw128B(r, ac)), al[mi][0], al[mi][1], al[mi][2], al[mi][3]);
            }
            uint32_t bh[2][4], bl[2][4];
            const int bc = kt * 2 + ((lane >> 3) & 1);
            #pragma unroll
            for (int pr = 0; pr < 2; pr++) {
                int r = wn * 32 + pr * 16 + br;
                ldsm4(sptr(sKh + sw128B(r, bc)), bh[pr][0], bh[pr][1], bh[pr][2], bh[pr][3]);
                ldsm4(sptr(sKl + sw128B(r, bc)), bl[pr][0], bl[pr][1], bl[pr][2], bl[pr][3]);
            }
            #pragma unroll
            for (int mi = 0; mi < 4; mi++)
                #pragma unroll
                for (int ni = 0; ni < 4; ni++) {
                    uint32_t b0h = bh[ni >> 1][(ni & 1) * 2], b1h = bh[ni >> 1][(ni & 1) * 2 + 1];
                    uint32_t b0l = bl[ni >> 1][(ni & 1) * 2], b1l = bl[ni >> 1][(ni & 1) * 2 + 1];
                    mma16816(c[mi][ni], ah[mi], b0h, b1h);
                    mma16816(c[mi][ni], ah[mi], b0l, b1l);
                    mma16816(c[mi][ni], al[mi], b0h, b1h);
                }
        }
        #pragma unroll
        for (int mi = 0; mi < 4; mi++)
            #pragma unroll
            for (int ni = 0; ni < 4; ni++)
                #pragma unroll
                for (int e = 0; e < 4; e++)
                    rmax[mi][e >> 1] = fmaxf(rmax[mi][e >> 1], __fmul_rn(c[mi][ni][e], scaling));
    }

    // ---- cross-lane/warp rowmax reduce ----
    #pragma unroll
    for (int mi = 0; mi < 4; mi++)
        #pragma unroll
        for (int inst = 0; inst < 2; inst++) {
            float v = rmax[mi][inst];
            v = fmaxf(v, __shfl_xor_sync(0xffffffff, v, 1));
            v = fmaxf(v, __shfl_xor_sync(0xffffffff, v, 2));
            if (tg == 0) red[wn * 128 + wm * 64 + mi * 16 + inst * 8 + g] = v;
        }
    __syncthreads();
    if (tid < 128) {
        float v = red[tid];
        v = fmaxf(v, red[128 + tid]);
        v = fmaxf(v, red[256 + tid]);
        v = fmaxf(v, red[384 + tid]);
        rowmax[tid] = v;
    }
    __syncthreads();
    float rm[4][2];
    #pragma unroll
    for (int mi = 0; mi < 4; mi++)
        #pragma unroll
        for (int inst = 0; inst < 2; inst++)
            rm[mi][inst] = rowmax[wm * 64 + mi * 16 + inst * 8 + g];

    float o[4][2][4];
    #pragma unroll
    for (int i = 0; i < 4; i++)
        #pragma unroll
        for (int j = 0; j < 2; j++)
            #pragma unroll
            for (int e = 0; e < 4; e++) o[i][j][e] = 0.f;
    float rs[4][2];
    #pragma unroll
    for (int i = 0; i < 4; i++) { rs[i][0] = 0.f; rs[i][1] = 0.f; }

    // ======================= pass 2 =======================
    for (int st = 0; st < TLEN / 128; st++) {
        __syncthreads();
        #pragma unroll
        for (int p = 0; p < 4; p++) {
            int idx = p * 256 + tid;
            int r = idx >> 3, ch = idx & 7;
            size_t go = (size_t)(st * 128 + r) * HDIM + ch * 8;
            *(uint4*)(sKh + sw128B(r, ch)) = *(const uint4*)(Kh + go);
            *(uint4*)(sKl + sw128B(r, ch)) = *(const uint4*)(Klp + go);
            *(uint4*)(sVh + sw128B(r, ch)) = *(const uint4*)(Vh + go);
            *(uint4*)(sVl + sw128B(r, ch)) = *(const uint4*)(Vlp + go);
        }
        __syncthreads();

        float c[4][4][4];
        #pragma unroll
        for (int i = 0; i < 4; i++)
            #pragma unroll
            for (int j = 0; j < 4; j++)
                #pragma unroll
                for (int e = 0; e < 4; e++) c[i][j][e] = 0.f;

        #pragma unroll
        for (int kt = 0; kt < 4; kt++) {
            uint32_t ah[4][4], al[4][4];
            const int ac = kt * 2 + (lane >> 4);
            #pragma unroll
            for (int mi = 0; mi < 4; mi++) {
                int r = wm * 64 + mi * 16 + ar;
                ldsm4(sptr(sQh + sw128B(r, ac)), ah[mi][0], ah[mi][1], ah[mi][2], ah[mi][3]);
                ldsm4(sptr(sQl + sw128B(r, ac)), al[mi][0], al[mi][1], al[mi][2], al[mi][3]);
            }
            uint32_t bh[2][4], bl[2][4];
            const int bc = kt * 2 + ((lane >> 3) & 1);
            #pragma unroll
            for (int pr = 0; pr < 2; pr++) {
                int r = wn * 32 + pr * 16 + br;
                ldsm4(sptr(sKh + sw128B(r, bc)), bh[pr][0], bh[pr][1], bh[pr][2], bh[pr][3]);
                ldsm4(sptr(sKl + sw128B(r, bc)), bl[pr][0], bl[pr][1], bl[pr][2], bl[pr][3]);
            }
            #pragma unroll
            for (int mi = 0; mi < 4; mi++)
                #pragma unroll
                for (int ni = 0; ni < 4; ni++) {
                    uint32_t b0h = bh[ni >> 1][(ni & 1) * 2], b1h = bh[ni >> 1][(ni & 1) * 2 + 1];
                    uint32_t b0l = bl[ni >> 1][(ni & 1) * 2], b1l = bl[ni >> 1][(ni & 1) * 2 + 1];
                    mma16816(c[mi][ni], ah[mi], b0h, b1h);
                    mma16816(c[mi][ni], ah[mi], b0l, b1l);
                    mma16816(c[mi][ni], al[mi], b0h, b1h);
                }
        }

        // exp + split E into SMEM
        #pragma unroll
        for (int mi = 0; mi < 4; mi++)
            #pragma unroll
            for (int ni = 0; ni < 4; ni++)
                #pragma unroll
                for (int inst = 0; inst < 2; inst++) {
                    float e0 = fastexp_g(__fmul_rn(c[mi][ni][inst * 2], scaling) - rm[mi][inst]);
                    float e1 = fastexp_g(__fmul_rn(c[mi][ni][inst * 2 + 1], scaling) - rm[mi][inst]);
                    rs[mi][inst] += e0;
                    rs[mi][inst] += e1;
                    uint32_t ph, pl;
                    split2(e0, e1, ph, pl);
                    int r = wm * 64 + mi * 16 + inst * 8 + g;
                    int col = wn * 32 + ni * 8 + 2 * tg;
                    int byt = sw256B(r, col >> 3) + (col & 7) * 2;
                    *(uint32_t*)(sEh + byt) = ph;
                    *(uint32_t*)(sEl + byt) = pl;
                }
        __syncthreads();

        // PV: O += E @ V
        #pragma unroll
        for (int kt = 0; kt < 8; kt++) {
            uint32_t eh[4][4], el[4][4];
            const int ac = kt * 2 + (lane >> 4);
            #pragma unroll
            for (int mi = 0; mi < 4; mi++) {
                int r = wm * 64 + mi * 16 + ar;
                ldsm4(sptr(sEh + sw256B(r, ac)), eh[mi][0], eh[mi][1], eh[mi][2], eh[mi][3]);
                ldsm4(sptr(sEl + sw256B(r, ac)), el[mi][0], el[mi][1], el[mi][2], el[mi][3]);
            }
            uint32_t vh[4], vl[4];
            int vr = kt * 16 + (lane & 8) + (lane & 7);
            int vc = wn * 2 + (lane >> 4);
            ldsm4t(sptr(sVh + sw128B(vr, vc)), vh[0], vh[1], vh[2], vh[3]);
            ldsm4t(sptr(sVl + sw128B(vr, vc)), vl[0], vl[1], vl[2], vl[3]);
            #pragma unroll
            for (int mi = 0; mi < 4; mi++)
                #pragma unroll
                for (int ni2 = 0; ni2 < 2; ni2++) {
                    mma16816(o[mi][ni2], eh[mi], vh[ni2 * 2], vh[ni2 * 2 + 1]);
                    mma16816(o[mi][ni2], eh[mi], vl[ni2 * 2], vl[ni2 * 2 + 1]);
                    mma16816(o[mi][ni2], el[mi], vh[ni2 * 2], vh[ni2 * 2 + 1]);
                }
        }
    }

    // ---- rowsum reduce ----
    #pragma unroll
    for (int mi = 0; mi < 4; mi++)
        #pragma unroll
        for (int inst = 0; inst < 2; inst++) {
            float v = rs[mi][inst];
            v += __shfl_xor_sync(0xffffffff, v, 1);
            v += __shfl_xor_sync(0xffffffff, v, 2);
            if (tg == 0) red[wn * 128 + wm * 64 + mi * 16 + inst * 8 + g] = v;
        }
    __syncthreads();
    if (tid < 128)
        rowsum[tid] = red[tid] + red[128 + tid] + red[256 + tid] + red[384 + tid];
    __syncthreads();

    // ---- normalize + split-store O ----
    #pragma unroll
    for (int mi = 0; mi < 4; mi++)
        #pragma unroll
        for (int inst = 0; inst < 2; inst++) {
            int r = wm * 64 + mi * 16 + inst * 8 + g;
            float inv = 1.0f / rowsum[r];
            #pragma unroll
            for (int ni2 = 0; ni2 < 2; ni2++) {
                float v0 = o[mi][ni2][inst * 2] * inv;
                float v1 = o[mi][ni2][inst * 2 + 1] * inv;
                uint32_t ph, pl;
                split2(v0, v1, ph, pl);
                int d = wn * 16 + ni2 * 8 + 2 * tg;
                size_t addr = (size_t)(t0 + r) * DMODEL + h * HDIM + d;
                *(uint32_t*)(g_oh + addr) = ph;
                *(uint32_t*)(g_ol + addr) = pl;
            }
        }
}

// ============================================================================
extern "C" void kernel_launch(void* const* d_in, const int* in_sizes, int n_in,
                              void* d_out, int out_size)
{
    const float* x  = (const float*)d_in[0];
    const float* Wq = (const float*)d_in[1];
    const float* bq = (const float*)d_in[2];
    const float* Wk = (const float*)d_in[3];
    const float* bk = (const float*)d_in[4];
    const float* Wv = (const float*)d_in[5];
    const float* bv = (const float*)d_in[6];
    const float* Wo = (const float*)d_in[7];
    float* out = (float*)d_out;

    // Quake q_rsqrt(HEAD_DIM=64) exact fp32 step order
    float xq = 64.0f;
    int ib;
    memcpy(&ib, &xq, 4);
    ib = 0x5f3759df - (ib >> 1);
    float y;
    memcpy(&y, &ib, 4);
    float t = 0.5f * xq;
    t = t * y;
    t = t * y;
    float scaling = y * (1.5f - t);

    cudaFuncSetAttribute(attn_kernel, cudaFuncAttributeMaxDynamicSharedMemorySize, ATTN_SMEM);
    cudaFuncSetAttribute(gemm_bf16, cudaFuncAttributeMaxDynamicSharedMemorySize, GEMM_SMEM);

    split_kernel<<<2048, 256>>>(x,  0, TLEN * DMODEL);
    split_kernel<<<1024, 256>>>(Wq, 1, DMODEL * DMODEL);
    split_kernel<<<1024, 256>>>(Wk, 2, DMODEL * DMODEL);
    split_kernel<<<1024, 256>>>(Wv, 3, DMODEL * DMODEL);
    split_kernel<<<1024, 256>>>(Wo, 4, DMODEL * DMODEL);

    dim3 pgrid(DMODEL / 128, TLEN / 128);
    gemm_bf16<<<pgrid, 256, GEMM_SMEM>>>(0, 0, bq, out, 0);
    gemm_bf16<<<pgrid, 256, GEMM_SMEM>>>(0, 1, bk, out, 1);
    gemm_bf16<<<pgrid, 256, GEMM_SMEM>>>(0, 2, bv, out, 2);

    attn_kernel<<<dim3(TLEN / 128, NHEADS), 256, ATTN_SMEM>>>(scaling);

    gemm_bf16<<<pgrid, 256, GEMM_SMEM>>>(1, 3, nullptr, out, 3);
}

// round 5
// speedup vs baseline: 1.3535x; 1.3535x over previous
#include <cuda_runtime.h>
#include <cuda_bf16.h>
#include <cstring>
#include <cstdint>

#define TLEN   4096
#define DMODEL 1024
#define NHEADS 16
#define HDIM   64
#define NT     32

// ---------------- device scratch ----------------
__device__ __nv_bfloat16 g_xh[TLEN * DMODEL], g_xl[TLEN * DMODEL];
__device__ __nv_bfloat16 g_wh[4 * DMODEL * DMODEL], g_wl[4 * DMODEL * DMODEL];
__device__ __nv_bfloat16 g_qh[NHEADS * TLEN * HDIM], g_ql[NHEADS * TLEN * HDIM];
__device__ __nv_bfloat16 g_kh[NHEADS * TLEN * HDIM], g_kl[NHEADS * TLEN * HDIM];
__device__ __nv_bfloat16 g_vh[NHEADS * TLEN * HDIM], g_vl[NHEADS * TLEN * HDIM];
__device__ __nv_bfloat16 g_oh[TLEN * DMODEL], g_ol[TLEN * DMODEL];

// ---------------- fastexp_gist ----------------
__device__ __forceinline__ float fastexp_g(float x) {
    const float GA = (float)12102203.17133801;
    const float GB = (float)1064986823.010288;
    float y = __fadd_rn(__fmul_rn(GA, x), GB);
    int yi = (y < 8388608.0f || y > 2139095040.0f) ? 0 : __float2int_rz(y);
    return __int_as_float(yi);
}

// ---------------- helpers ----------------
__device__ __forceinline__ uint32_t sptr(const void* p) {
    return (uint32_t)__cvta_generic_to_shared(p);
}
__device__ __forceinline__ void ldsm4(uint32_t a, uint32_t& r0, uint32_t& r1,
                                      uint32_t& r2, uint32_t& r3) {
    asm volatile("ldmatrix.sync.aligned.m8n8.x4.shared.b16 {%0,%1,%2,%3}, [%4];"
                 : "=r"(r0), "=r"(r1), "=r"(r2), "=r"(r3) : "r"(a));
}
__device__ __forceinline__ void ldsm4t(uint32_t a, uint32_t& r0, uint32_t& r1,
                                       uint32_t& r2, uint32_t& r3) {
    asm volatile("ldmatrix.sync.aligned.m8n8.x4.trans.shared.b16 {%0,%1,%2,%3}, [%4];"
                 : "=r"(r0), "=r"(r1), "=r"(r2), "=r"(r3) : "r"(a));
}
__device__ __forceinline__ void mma16816(float* c, const uint32_t* a,
                                         uint32_t b0, uint32_t b1) {
    asm volatile(
        "mma.sync.aligned.m16n8k16.row.col.f32.bf16.bf16.f32 "
        "{%0,%1,%2,%3}, {%4,%5,%6,%7}, {%8,%9}, {%0,%1,%2,%3};"
        : "+f"(c[0]), "+f"(c[1]), "+f"(c[2]), "+f"(c[3])
        : "r"(a[0]), "r"(a[1]), "r"(a[2]), "r"(a[3]), "r"(b0), "r"(b1));
}
__device__ __forceinline__ int sw128B(int row, int ch) {
    return (row << 7) + ((ch ^ (row & 7)) << 4);
}
__device__ __forceinline__ int sw256B(int row, int ch) {
    return (row << 8) + (((ch & 8) | ((ch & 7) ^ (row & 7))) << 4);
}
__device__ __forceinline__ void split2(float v0, float v1, uint32_t& ph, uint32_t& pl) {
    __nv_bfloat16 h0 = __float2bfloat16(v0), h1 = __float2bfloat16(v1);
    __nv_bfloat16 l0 = __float2bfloat16(v0 - __bfloat162float(h0));
    __nv_bfloat16 l1 = __float2bfloat16(v1 - __bfloat162float(h1));
    ph = (uint32_t)__bfloat16_as_ushort(h0) | ((uint32_t)__bfloat16_as_ushort(h1) << 16);
    pl = (uint32_t)__bfloat16_as_ushort(l0) | ((uint32_t)__bfloat16_as_ushort(l1) << 16);
}
// cp.async
__device__ __forceinline__ void cp16(uint32_t s, const void* g) {
    asm volatile("cp.async.cg.shared.global [%0], [%1], 16;" :: "r"(s), "l"(g));
}
#define CP_COMMIT() asm volatile("cp.async.commit_group;" ::: "memory")
#define CP_WAIT(n)  asm volatile("cp.async.wait_group %0;" :: "n"(n) : "memory")

// async-load one 128x64 bf16 plane into SW128 smem
__device__ __forceinline__ void cp_tile(uint32_t sdst, const __nv_bfloat16* g, int tid) {
    #pragma unroll
    for (int p = 0; p < 4; p++) {
        int idx = p * 256 + tid;
        int r = idx >> 3, ch = idx & 7;
        cp16(sdst + sw128B(r, ch), g + (size_t)r * HDIM + ch * 8);
    }
}

// ---------------- fused split (fp32 -> bf16 hi/lo) ----------------
__global__ void split_all(const float* __restrict__ x, const float* __restrict__ wq,
                          const float* __restrict__ wk, const float* __restrict__ wv,
                          const float* __restrict__ wo) {
    const int total = TLEN * DMODEL + 4 * DMODEL * DMODEL;
    for (int i = blockIdx.x * blockDim.x + threadIdx.x; i < total;
         i += gridDim.x * blockDim.x) {
        const float* src;
        __nv_bfloat16 *hi, *lo;
        int off;
        if (i < TLEN * DMODEL) {
            src = x; hi = g_xh; lo = g_xl; off = i;
        } else {
            int j = i - TLEN * DMODEL;
            int w = j >> 20;
            off = j & ((1 << 20) - 1);
            src = (w == 0) ? wq : (w == 1) ? wk : (w == 2) ? wv : wo;
            hi = g_wh + ((size_t)w << 20);
            lo = g_wl + ((size_t)w << 20);
        }
        float v = src[off];
        __nv_bfloat16 h = __float2bfloat16(v);
        hi[off] = h;
        lo[off] = __float2bfloat16(v - __bfloat162float(h));
    }
}

// ============================================================================
// Split-bf16 mma.sync GEMM, cp.async double-buffered.
// ============================================================================
#define GEMM_SMEM 131072

__device__ __forceinline__ void gemm_prefetch(char* sm, int s, int kc,
                                              const __nv_bfloat16* Ah, const __nv_bfloat16* Al,
                                              const __nv_bfloat16* Wh, const __nv_bfloat16* Wl,
                                              int m0, int n0, int tid) {
    char* base = sm + s * 65536;
    #pragma unroll
    for (int p = 0; p < 4; p++) {
        int idx = p * 256 + tid;
        int r = idx >> 3, ch = idx & 7;
        size_t ga = (size_t)(m0 + r) * DMODEL + kc * 64 + ch * 8;
        size_t gw = (size_t)(n0 + r) * DMODEL + kc * 64 + ch * 8;
        uint32_t so = sw128B(r, ch);
        cp16(sptr(base) + so,          Ah + ga);
        cp16(sptr(base) + 16384 + so,  Al + ga);
        cp16(sptr(base) + 32768 + so,  Wh + gw);
        cp16(sptr(base) + 49152 + so,  Wl + gw);
    }
}

__global__ __launch_bounds__(256, 1)
void gemm_bf16(int a_sel, int w_idx, const float* __restrict__ bias,
               float* __restrict__ dout, int c_sel)
{
    extern __shared__ char sm[];
    const __nv_bfloat16* Ah = a_sel ? g_oh : g_xh;
    const __nv_bfloat16* Al = a_sel ? g_ol : g_xl;
    const __nv_bfloat16* Wh = g_wh + (size_t)w_idx * DMODEL * DMODEL;
    const __nv_bfloat16* Wl = g_wl + (size_t)w_idx * DMODEL * DMODEL;

    const int tid = threadIdx.x;
    const int lane = tid & 31, wid = tid >> 5;
    const int g = lane >> 2, tg = lane & 3;
    const int wm = wid >> 2, wn = wid & 3;
    const int m0 = blockIdx.y * 128, n0 = blockIdx.x * 128;

    float c[4][4][4];
    #pragma unroll
    for (int i = 0; i < 4; i++)
        #pragma unroll
        for (int j = 0; j < 4; j++)
            #pragma unroll
            for (int e = 0; e < 4; e++) c[i][j][e] = 0.f;

    gemm_prefetch(sm, 0, 0, Ah, Al, Wh, Wl, m0, n0, tid);
    CP_COMMIT();

    for (int kc = 0; kc < 16; kc++) {
        int s = kc & 1;
        if (kc + 1 < 16) {
            gemm_prefetch(sm, s ^ 1, kc + 1, Ah, Al, Wh, Wl, m0, n0, tid);
            CP_COMMIT();
            CP_WAIT(1);
        } else CP_WAIT(0);
        __syncthreads();

        char* sAh = sm + s * 65536;
        char* sAl = sAh + 16384;
        char* sWh = sAh + 32768;
        char* sWl = sAh + 49152;

        #pragma unroll
        for (int kt = 0; kt < 4; kt++) {
            uint32_t ah[4][4], al[4][4];
            const int ar = (lane & 8) + (lane & 7);
            const int ac = kt * 2 + (lane >> 4);
            #pragma unroll
            for (int mi = 0; mi < 4; mi++) {
                int r = wm * 64 + mi * 16 + ar;
                ldsm4(sptr(sAh + sw128B(r, ac)), ah[mi][0], ah[mi][1], ah[mi][2], ah[mi][3]);
                ldsm4(sptr(sAl + sw128B(r, ac)), al[mi][0], al[mi][1], al[mi][2], al[mi][3]);
            }
            uint32_t bh[2][4], bl[2][4];
            const int br = ((lane >> 4) << 3) + (lane & 7);
            const int bc = kt * 2 + ((lane >> 3) & 1);
            #pragma unroll
            for (int pr = 0; pr < 2; pr++) {
                int r = wn * 32 + pr * 16 + br;
                ldsm4(sptr(sWh + sw128B(r, bc)), bh[pr][0], bh[pr][1], bh[pr][2], bh[pr][3]);
                ldsm4(sptr(sWl + sw128B(r, bc)), bl[pr][0], bl[pr][1], bl[pr][2], bl[pr][3]);
            }
            #pragma unroll
            for (int mi = 0; mi < 4; mi++)
                #pragma unroll
                for (int ni = 0; ni < 4; ni++) {
                    uint32_t b0h = bh[ni >> 1][(ni & 1) * 2], b1h = bh[ni >> 1][(ni & 1) * 2 + 1];
                    uint32_t b0l = bl[ni >> 1][(ni & 1) * 2], b1l = bl[ni >> 1][(ni & 1) * 2 + 1];
                    mma16816(c[mi][ni], ah[mi], b0h, b1h);
                    mma16816(c[mi][ni], ah[mi], b0l, b1l);
                    mma16816(c[mi][ni], al[mi], b0h, b1h);
                }
        }
        __syncthreads();
    }

    __nv_bfloat16 *dsth = nullptr, *dstl = nullptr;
    if (c_sel == 0) { dsth = g_qh; dstl = g_ql; }
    else if (c_sel == 1) { dsth = g_kh; dstl = g_kl; }
    else if (c_sel == 2) { dsth = g_vh; dstl = g_vl; }

    #pragma unroll
    for (int mi = 0; mi < 4; mi++)
        #pragma unroll
        for (int ni = 0; ni < 4; ni++)
            #pragma unroll
            for (int inst = 0; inst < 2; inst++) {
                int m = m0 + wm * 64 + mi * 16 + inst * 8 + g;
                int n = n0 + wn * 32 + ni * 8 + 2 * tg;
                float b0 = bias ? bias[n] : 0.f;
                float b1 = bias ? bias[n + 1] : 0.f;
                float v0 = c[mi][ni][inst * 2] + b0;
                float v1 = c[mi][ni][inst * 2 + 1] + b1;
                if (c_sel < 3) {
                    uint32_t ph, pl;
                    split2(v0, v1, ph, pl);
                    size_t addr = ((size_t)(n >> 6) * TLEN + m) * HDIM + (n & 63);
                    *(uint32_t*)(dsth + addr) = ph;
                    *(uint32_t*)(dstl + addr) = pl;
                } else {
                    float2 r; r.x = v0; r.y = v1;
                    *(float2*)(dout + (size_t)m * DMODEL + n) = r;
                }
            }
}

// ============================================================================
// Two-pass attention, mma.sync, cp.async double-buffered.
// Pass 1: hi-only QK^T -> rowmax. Pass 2: full split QK, fastexp, split-E, PV.
// SMEM: QH 0 | QL 16K | K stage s: 32K+32K*s (hi)/(+16K lo) | V stage s: 96K+32K*s
//       E: 160K (hi) 192K (lo) | reductions aliased inside E region.
// ============================================================================
#define AT_QH    0
#define AT_QL    16384
#define AT_KH(s) (32768 + (s) * 32768)
#define AT_KL(s) (32768 + (s) * 32768 + 16384)
#define AT_VH(s) (98304 + (s) * 32768)
#define AT_VL(s) (98304 + (s) * 32768 + 16384)
#define AT_EH    163840
#define AT_EL    196608
#define ATTN_SMEM 229376

__global__ __launch_bounds__(256, 1)
void attn_kernel(float scaling)
{
    extern __shared__ char sm[];
    uint32_t sb = sptr(sm);
    float* red    = (float*)(sm + AT_EH);          // 512 floats (aliases E)
    float* rowmax = (float*)(sm + AT_EH + 2048);   // 128
    float* rowsum = (float*)(sm + AT_EH + 2560);   // 128

    const int tid = threadIdx.x;
    const int lane = tid & 31, wid = tid >> 5;
    const int g = lane >> 2, tg = lane & 3;
    const int wm = wid >> 2, wn = wid & 3;
    const int h = blockIdx.y;
    const int t0 = blockIdx.x * 128;

    const __nv_bfloat16* Qh  = g_qh + ((size_t)h * TLEN + t0) * HDIM;
    const __nv_bfloat16* Qlp = g_ql + ((size_t)h * TLEN + t0) * HDIM;
    const __nv_bfloat16* Kh  = g_kh + (size_t)h * TLEN * HDIM;
    const __nv_bfloat16* Klp = g_kl + (size_t)h * TLEN * HDIM;
    const __nv_bfloat16* Vh  = g_vh + (size_t)h * TLEN * HDIM;
    const __nv_bfloat16* Vlp = g_vl + (size_t)h * TLEN * HDIM;

    const int ar = (lane & 8) + (lane & 7);
    const int br = ((lane >> 4) << 3) + (lane & 7);

    // Q + first K (hi) prefetch
    cp_tile(sb + AT_QH, Qh, tid);
    cp_tile(sb + AT_QL, Qlp, tid);
    cp_tile(sb + AT_KH(0), Kh, tid);
    CP_COMMIT();

    float rmax[4][2];
    #pragma unroll
    for (int i = 0; i < 4; i++) { rmax[i][0] = -3.402823466e38f; rmax[i][1] = -3.402823466e38f; }

    // ======================= pass 1: rowmax (hi-only QK) =======================
    for (int st = 0; st < NT; st++) {
        int b = st & 1;
        if (st + 1 < NT) {
            cp_tile(sb + AT_KH(b ^ 1), Kh + (size_t)(st + 1) * 128 * HDIM, tid);
            CP_COMMIT();
            CP_WAIT(1);
        } else CP_WAIT(0);
        __syncthreads();

        char* sQh = sm + AT_QH;
        char* sKh = sm + AT_KH(b);

        float c[4][4][4];
        #pragma unroll
        for (int i = 0; i < 4; i++)
            #pragma unroll
            for (int j = 0; j < 4; j++)
                #pragma unroll
                for (int e = 0; e < 4; e++) c[i][j][e] = 0.f;

        #pragma unroll
        for (int kt = 0; kt < 4; kt++) {
            uint32_t ah[4][4];
            const int ac = kt * 2 + (lane >> 4);
            #pragma unroll
            for (int mi = 0; mi < 4; mi++) {
                int r = wm * 64 + mi * 16 + ar;
                ldsm4(sptr(sQh + sw128B(r, ac)), ah[mi][0], ah[mi][1], ah[mi][2], ah[mi][3]);
            }
            uint32_t bh[2][4];
            const int bc = kt * 2 + ((lane >> 3) & 1);
            #pragma unroll
            for (int pr = 0; pr < 2; pr++) {
                int r = wn * 32 + pr * 16 + br;
                ldsm4(sptr(sKh + sw128B(r, bc)), bh[pr][0], bh[pr][1], bh[pr][2], bh[pr][3]);
            }
            #pragma unroll
            for (int mi = 0; mi < 4; mi++)
                #pragma unroll
                for (int ni = 0; ni < 4; ni++)
                    mma16816(c[mi][ni], ah[mi], bh[ni >> 1][(ni & 1) * 2], bh[ni >> 1][(ni & 1) * 2 + 1]);
        }
        #pragma unroll
        for (int mi = 0; mi < 4; mi++)
            #pragma unroll
            for (int ni = 0; ni < 4; ni++)
                #pragma unroll
                for (int e = 0; e < 4; e++)
                    rmax[mi][e >> 1] = fmaxf(rmax[mi][e >> 1], __fmul_rn(c[mi][ni][e], scaling));
        __syncthreads();
    }

    // ---- cross-lane/warp rowmax reduce ----
    #pragma unroll
    for (int mi = 0; mi < 4; mi++)
        #pragma unroll
        for (int inst = 0; inst < 2; inst++) {
            float v = rmax[mi][inst];
            v = fmaxf(v, __shfl_xor_sync(0xffffffff, v, 1));
            v = fmaxf(v, __shfl_xor_sync(0xffffffff, v, 2));
            if (tg == 0) red[wn * 128 + wm * 64 + mi * 16 + inst * 8 + g] = v;
        }
    __syncthreads();
    if (tid < 128) {
        float v = red[tid];
        v = fmaxf(v, red[128 + tid]);
        v = fmaxf(v, red[256 + tid]);
        v = fmaxf(v, red[384 + tid]);
        rowmax[tid] = v;
    }
    __syncthreads();
    float rm[4][2];
    #pragma unroll
    for (int mi = 0; mi < 4; mi++)
        #pragma unroll
        for (int inst = 0; inst < 2; inst++)
            rm[mi][inst] = rowmax[wm * 64 + mi * 16 + inst * 8 + g];

    float o[4][2][4];
    #pragma unroll
    for (int i = 0; i < 4; i++)
        #pragma unroll
        for (int j = 0; j < 2; j++)
            #pragma unroll
            for (int e = 0; e < 4; e++) o[i][j][e] = 0.f;
    float rs[4][2];
    #pragma unroll
    for (int i = 0; i < 4; i++) { rs[i][0] = 0.f; rs[i][1] = 0.f; }

    // prefetch tile 0 (K hi/lo + V hi/lo) into stage 0
    cp_tile(sb + AT_KH(0), Kh, tid);
    cp_tile(sb + AT_KL(0), Klp, tid);
    cp_tile(sb + AT_VH(0), Vh, tid);
    cp_tile(sb + AT_VL(0), Vlp, tid);
    CP_COMMIT();

    // ======================= pass 2 =======================
    for (int st = 0; st < NT; st++) {
        int b = st & 1;
        if (st + 1 < NT) {
            size_t go = (size_t)(st + 1) * 128 * HDIM;
            cp_tile(sb + AT_KH(b ^ 1), Kh + go, tid);
            cp_tile(sb + AT_KL(b ^ 1), Klp + go, tid);
            cp_tile(sb + AT_VH(b ^ 1), Vh + go, tid);
            cp_tile(sb + AT_VL(b ^ 1), Vlp + go, tid);
            CP_COMMIT();
            CP_WAIT(1);
        } else CP_WAIT(0);
        __syncthreads();

        char* sQh = sm + AT_QH;
        char* sQl = sm + AT_QL;
        char* sKh = sm + AT_KH(b);
        char* sKl = sm + AT_KL(b);
        char* sVh = sm + AT_VH(b);
        char* sVl = sm + AT_VL(b);
        char* sEh = sm + AT_EH;
        char* sEl = sm + AT_EL;

        float c[4][4][4];
        #pragma unroll
        for (int i = 0; i < 4; i++)
            #pragma unroll
            for (int j = 0; j < 4; j++)
                #pragma unroll
                for (int e = 0; e < 4; e++) c[i][j][e] = 0.f;

        #pragma unroll
        for (int kt = 0; kt < 4; kt++) {
            uint32_t ah[4][4], al[4][4];
            const int ac = kt * 2 + (lane >> 4);
            #pragma unroll
            for (int mi = 0; mi < 4; mi++) {
                int r = wm * 64 + mi * 16 + ar;
                ldsm4(sptr(sQh + sw128B(r, ac)), ah[mi][0], ah[mi][1], ah[mi][2], ah[mi][3]);
                ldsm4(sptr(sQl + sw128B(r, ac)), al[mi][0], al[mi][1], al[mi][2], al[mi][3]);
            }
            uint32_t bh[2][4], bl[2][4];
            const int bc = kt * 2 + ((lane >> 3) & 1);
            #pragma unroll
            for (int pr = 0; pr < 2; pr++) {
                int r = wn * 32 + pr * 16 + br;
                ldsm4(sptr(sKh + sw128B(r, bc)), bh[pr][0], bh[pr][1], bh[pr][2], bh[pr][3]);
                ldsm4(sptr(sKl + sw128B(r, bc)), bl[pr][0], bl[pr][1], bl[pr][2], bl[pr][3]);
            }
            #pragma unroll
            for (int mi = 0; mi < 4; mi++)
                #pragma unroll
                for (int ni = 0; ni < 4; ni++) {
                    uint32_t b0h = bh[ni >> 1][(ni & 1) * 2], b1h = bh[ni >> 1][(ni & 1) * 2 + 1];
                    uint32_t b0l = bl[ni >> 1][(ni & 1) * 2], b1l = bl[ni >> 1][(ni & 1) * 2 + 1];
                    mma16816(c[mi][ni], ah[mi], b0h, b1h);
                    mma16816(c[mi][ni], ah[mi], b0l, b1l);
                    mma16816(c[mi][ni], al[mi], b0h, b1h);
                }
        }

        // exp + split E into SMEM
        #pragma unroll
        for (int mi = 0; mi < 4; mi++)
            #pragma unroll
            for (int ni = 0; ni < 4; ni++)
                #pragma unroll
                for (int inst = 0; inst < 2; inst++) {
                    float e0 = fastexp_g(__fmul_rn(c[mi][ni][inst * 2], scaling) - rm[mi][inst]);
                    float e1 = fastexp_g(__fmul_rn(c[mi][ni][inst * 2 + 1], scaling) - rm[mi][inst]);
                    rs[mi][inst] += e0;
                    rs[mi][inst] += e1;
                    uint32_t ph, pl;
                    split2(e0, e1, ph, pl);
                    int r = wm * 64 + mi * 16 + inst * 8 + g;
                    int col = wn * 32 + ni * 8 + 2 * tg;
                    int byt = sw256B(r, col >> 3) + (col & 7) * 2;
                    *(uint32_t*)(sEh + byt) = ph;
                    *(uint32_t*)(sEl + byt) = pl;
                }
        __syncthreads();

        // PV: O += E @ V
        #pragma unroll
        for (int kt = 0; kt < 8; kt++) {
            uint32_t eh[4][4], el[4][4];
            const int ac = kt * 2 + (lane >> 4);
            #pragma unroll
            for (int mi = 0; mi < 4; mi++) {
                int r = wm * 64 + mi * 16 + ar;
                ldsm4(sptr(sEh + sw256B(r, ac)), eh[mi][0], eh[mi][1], eh[mi][2], eh[mi][3]);
                ldsm4(sptr(sEl + sw256B(r, ac)), el[mi][0], el[mi][1], el[mi][2], el[mi][3]);
            }
            uint32_t vh[4], vl[4];
            int vr = kt * 16 + (lane & 8) + (lane & 7);
            int vc = wn * 2 + (lane >> 4);
            ldsm4t(sptr(sVh + sw128B(vr, vc)), vh[0], vh[1], vh[2], vh[3]);
            ldsm4t(sptr(sVl + sw128B(vr, vc)), vl[0], vl[1], vl[2], vl[3]);
            #pragma unroll
            for (int mi = 0; mi < 4; mi++)
                #pragma unroll
                for (int ni2 = 0; ni2 < 2; ni2++) {
                    mma16816(o[mi][ni2], eh[mi], vh[ni2 * 2], vh[ni2 * 2 + 1]);
                    mma16816(o[mi][ni2], eh[mi], vl[ni2 * 2], vl[ni2 * 2 + 1]);
                    mma16816(o[mi][ni2], el[mi], vh[ni2 * 2], vh[ni2 * 2 + 1]);
                }
        }
        __syncthreads();
    }

    // ---- rowsum reduce (E region free now) ----
    #pragma unroll
    for (int mi = 0; mi < 4; mi++)
        #pragma unroll
        for (int inst = 0; inst < 2; inst++) {
            float v = rs[mi][inst];
            v += __shfl_xor_sync(0xffffffff, v, 1);
            v += __shfl_xor_sync(0xffffffff, v, 2);
            if (tg == 0) red[wn * 128 + wm * 64 + mi * 16 + inst * 8 + g] = v;
        }
    __syncthreads();
    if (tid < 128)
        rowsum[tid] = red[tid] + red[128 + tid] + red[256 + tid] + red[384 + tid];
    __syncthreads();

    // ---- normalize + split-store O ----
    #pragma unroll
    for (int mi = 0; mi < 4; mi++)
        #pragma unroll
        for (int inst = 0; inst < 2; inst++) {
            int r = wm * 64 + mi * 16 + inst * 8 + g;
            float inv = 1.0f / rowsum[r];
            #pragma unroll
            for (int ni2 = 0; ni2 < 2; ni2++) {
                float v0 = o[mi][ni2][inst * 2] * inv;
                float v1 = o[mi][ni2][inst * 2 + 1] * inv;
                uint32_t ph, pl;
                split2(v0, v1, ph, pl);
                int d = wn * 16 + ni2 * 8 + 2 * tg;
                size_t addr = (size_t)(t0 + r) * DMODEL + h * HDIM + d;
                *(uint32_t*)(g_oh + addr) = ph;
                *(uint32_t*)(g_ol + addr) = pl;
            }
        }
}

// ============================================================================
extern "C" void kernel_launch(void* const* d_in, const int* in_sizes, int n_in,
                              void* d_out, int out_size)
{
    const float* x  = (const float*)d_in[0];
    const float* Wq = (const float*)d_in[1];
    const float* bq = (const float*)d_in[2];
    const float* Wk = (const float*)d_in[3];
    const float* bk = (const float*)d_in[4];
    const float* Wv = (const float*)d_in[5];
    const float* bv = (const float*)d_in[6];
    const float* Wo = (const float*)d_in[7];
    float* out = (float*)d_out;

    // Quake q_rsqrt(64) exact fp32 step order
    float xq = 64.0f;
    int ib;
    memcpy(&ib, &xq, 4);
    ib = 0x5f3759df - (ib >> 1);
    float y;
    memcpy(&y, &ib, 4);
    float t = 0.5f * xq;
    t = t * y;
    t = t * y;
    float scaling = y * (1.5f - t);

    cudaFuncSetAttribute(gemm_bf16, cudaFuncAttributeMaxDynamicSharedMemorySize, GEMM_SMEM);
    cudaFuncSetAttribute(attn_kernel, cudaFuncAttributeMaxDynamicSharedMemorySize, ATTN_SMEM);

    split_all<<<4096, 256>>>(x, Wq, Wk, Wv, Wo);

    dim3 pgrid(DMODEL / 128, TLEN / 128);
    gemm_bf16<<<pgrid, 256, GEMM_SMEM>>>(0, 0, bq, out, 0);
    gemm_bf16<<<pgrid, 256, GEMM_SMEM>>>(0, 1, bk, out, 1);
    gemm_bf16<<<pgrid, 256, GEMM_SMEM>>>(0, 2, bv, out, 2);

    attn_kernel<<<dim3(TLEN / 128, NHEADS), 256, ATTN_SMEM>>>(scaling);

    gemm_bf16<<<pgrid, 256, GEMM_SMEM>>>(1, 3, nullptr, out, 3);
}

// round 6
// speedup vs baseline: 1.5319x; 1.1318x over previous
#include <cuda_runtime.h>
#include <cuda_bf16.h>
#include <cstring>
#include <cstdint>

#define TLEN   4096
#define DMODEL 1024
#define NHEADS 16
#define HDIM   64
#define NT     32

// ---------------- device scratch ----------------
__device__ __nv_bfloat16 g_xh[TLEN * DMODEL], g_xl[TLEN * DMODEL];
__device__ __nv_bfloat16 g_wh[4 * DMODEL * DMODEL], g_wl[4 * DMODEL * DMODEL];
__device__ __nv_bfloat16 g_qh[NHEADS * TLEN * HDIM], g_ql[NHEADS * TLEN * HDIM];
__device__ __nv_bfloat16 g_kh[NHEADS * TLEN * HDIM], g_kl[NHEADS * TLEN * HDIM];
__device__ __nv_bfloat16 g_vh[NHEADS * TLEN * HDIM], g_vl[NHEADS * TLEN * HDIM];
__device__ __nv_bfloat16 g_oh[TLEN * DMODEL], g_ol[TLEN * DMODEL];

// ---------------- fastexp_gist ----------------
__device__ __forceinline__ float fastexp_g(float x) {
    const float GA = (float)12102203.17133801;
    const float GB = (float)1064986823.010288;
    float y = __fadd_rn(__fmul_rn(GA, x), GB);
    int yi = (y < 8388608.0f || y > 2139095040.0f) ? 0 : __float2int_rz(y);
    return __int_as_float(yi);
}

// ---------------- helpers ----------------
__device__ __forceinline__ uint32_t sptr(const void* p) {
    return (uint32_t)__cvta_generic_to_shared(p);
}
__device__ __forceinline__ void ldsm4(uint32_t a, uint32_t* r) {
    asm volatile("ldmatrix.sync.aligned.m8n8.x4.shared.b16 {%0,%1,%2,%3}, [%4];"
                 : "=r"(r[0]), "=r"(r[1]), "=r"(r[2]), "=r"(r[3]) : "r"(a));
}
__device__ __forceinline__ void ldsm4t(uint32_t a, uint32_t* r) {
    asm volatile("ldmatrix.sync.aligned.m8n8.x4.trans.shared.b16 {%0,%1,%2,%3}, [%4];"
                 : "=r"(r[0]), "=r"(r[1]), "=r"(r[2]), "=r"(r[3]) : "r"(a));
}
__device__ __forceinline__ void mma16816(float* c, const uint32_t* a,
                                         uint32_t b0, uint32_t b1) {
    asm volatile(
        "mma.sync.aligned.m16n8k16.row.col.f32.bf16.bf16.f32 "
        "{%0,%1,%2,%3}, {%4,%5,%6,%7}, {%8,%9}, {%0,%1,%2,%3};"
        : "+f"(c[0]), "+f"(c[1]), "+f"(c[2]), "+f"(c[3])
        : "r"(a[0]), "r"(a[1]), "r"(a[2]), "r"(a[3]), "r"(b0), "r"(b1));
}
__device__ __forceinline__ int sw128B(int row, int ch) {
    return (row << 7) + ((ch ^ (row & 7)) << 4);
}
// fast split: packed bf16x2 cvt
__device__ __forceinline__ void split2(float v0, float v1, uint32_t& ph, uint32_t& pl) {
    uint32_t h;
    asm("cvt.rn.bf16x2.f32 %0, %1, %2;" : "=r"(h) : "f"(v1), "f"(v0));
    float h0 = __uint_as_float(h << 16);
    float h1 = __uint_as_float(h & 0xffff0000u);
    uint32_t l;
    float r0 = v0 - h0, r1 = v1 - h1;
    asm("cvt.rn.bf16x2.f32 %0, %1, %2;" : "=r"(l) : "f"(r1), "f"(r0));
    ph = h; pl = l;
}
// cp.async
__device__ __forceinline__ void cp16(uint32_t s, const void* g) {
    asm volatile("cp.async.cg.shared.global [%0], [%1], 16;" :: "r"(s), "l"(g));
}
#define CP_COMMIT() asm volatile("cp.async.commit_group;" ::: "memory")
#define CP_WAIT(n)  asm volatile("cp.async.wait_group %0;" :: "n"(n) : "memory")

// async-load one 128x64 bf16 plane into SW128 smem
__device__ __forceinline__ void cp_tile(uint32_t sdst, const __nv_bfloat16* g, int tid) {
    #pragma unroll
    for (int p = 0; p < 4; p++) {
        int idx = p * 256 + tid;
        int r = idx >> 3, ch = idx & 7;
        cp16(sdst + sw128B(r, ch), g + (size_t)r * HDIM + ch * 8);
    }
}

// ---------------- fused split (fp32 -> bf16 hi/lo) ----------------
__global__ void split_all(const float* __restrict__ x, const float* __restrict__ wq,
                          const float* __restrict__ wk, const float* __restrict__ wv,
                          const float* __restrict__ wo) {
    const int total = TLEN * DMODEL + 4 * DMODEL * DMODEL;
    for (int i = blockIdx.x * blockDim.x + threadIdx.x; i < total;
         i += gridDim.x * blockDim.x) {
        const float* src;
        __nv_bfloat16 *hi, *lo;
        int off;
        if (i < TLEN * DMODEL) {
            src = x; hi = g_xh; lo = g_xl; off = i;
        } else {
            int j = i - TLEN * DMODEL;
            int w = j >> 20;
            off = j & ((1 << 20) - 1);
            src = (w == 0) ? wq : (w == 1) ? wk : (w == 2) ? wv : wo;
            hi = g_wh + ((size_t)w << 20);
            lo = g_wl + ((size_t)w << 20);
        }
        float v = src[off];
        __nv_bfloat16 h = __float2bfloat16(v);
        hi[off] = h;
        lo[off] = __float2bfloat16(v - __bfloat162float(h));
    }
}

// ============================================================================
// Split-bf16 mma.sync GEMM, cp.async double-buffered.
// w_fixed < 0: QKV fused (blockIdx.z selects weight + destination).
// ============================================================================
#define GEMM_SMEM 131072

__device__ __forceinline__ void gemm_prefetch(char* sm, int s, int kc,
                                              const __nv_bfloat16* Ah, const __nv_bfloat16* Al,
                                              const __nv_bfloat16* Wh, const __nv_bfloat16* Wl,
                                              int m0, int n0, int tid) {
    char* base = sm + s * 65536;
    #pragma unroll
    for (int p = 0; p < 4; p++) {
        int idx = p * 256 + tid;
        int r = idx >> 3, ch = idx & 7;
        size_t ga = (size_t)(m0 + r) * DMODEL + kc * 64 + ch * 8;
        size_t gw = (size_t)(n0 + r) * DMODEL + kc * 64 + ch * 8;
        uint32_t so = sw128B(r, ch);
        cp16(sptr(base) + so,          Ah + ga);
        cp16(sptr(base) + 16384 + so,  Al + ga);
        cp16(sptr(base) + 32768 + so,  Wh + gw);
        cp16(sptr(base) + 49152 + so,  Wl + gw);
    }
}

__global__ __launch_bounds__(256, 1)
void gemm_bf16(int a_sel, int w_fixed, const float* __restrict__ bq,
               const float* __restrict__ bk, const float* __restrict__ bv,
               float* __restrict__ dout)
{
    extern __shared__ char sm[];
    const int c_sel = (w_fixed < 0) ? (int)blockIdx.z : 3;
    const int w_idx = (w_fixed < 0) ? (int)blockIdx.z : w_fixed;
    const float* bias = (c_sel == 0) ? bq : (c_sel == 1) ? bk : (c_sel == 2) ? bv : nullptr;

    const __nv_bfloat16* Ah = a_sel ? g_oh : g_xh;
    const __nv_bfloat16* Al = a_sel ? g_ol : g_xl;
    const __nv_bfloat16* Wh = g_wh + (size_t)w_idx * DMODEL * DMODEL;
    const __nv_bfloat16* Wl = g_wl + (size_t)w_idx * DMODEL * DMODEL;

    const int tid = threadIdx.x;
    const int lane = tid & 31, wid = tid >> 5;
    const int g = lane >> 2, tg = lane & 3;
    const int wm = wid >> 2, wn = wid & 3;
    const int m0 = blockIdx.y * 128, n0 = blockIdx.x * 128;

    float c[4][4][4];
    #pragma unroll
    for (int i = 0; i < 4; i++)
        #pragma unroll
        for (int j = 0; j < 4; j++)
            #pragma unroll
            for (int e = 0; e < 4; e++) c[i][j][e] = 0.f;

    gemm_prefetch(sm, 0, 0, Ah, Al, Wh, Wl, m0, n0, tid);
    CP_COMMIT();

    for (int kc = 0; kc < 16; kc++) {
        int s = kc & 1;
        if (kc + 1 < 16) {
            gemm_prefetch(sm, s ^ 1, kc + 1, Ah, Al, Wh, Wl, m0, n0, tid);
            CP_COMMIT();
            CP_WAIT(1);
        } else CP_WAIT(0);
        __syncthreads();

        char* sAh = sm + s * 65536;
        char* sAl = sAh + 16384;
        char* sWh = sAh + 32768;
        char* sWl = sAh + 49152;

        #pragma unroll
        for (int kt = 0; kt < 4; kt++) {
            uint32_t ah[4][4], al[4][4];
            const int ar = lane & 15;
            const int ac = kt * 2 + (lane >> 4);
            #pragma unroll
            for (int mi = 0; mi < 4; mi++) {
                int r = wm * 64 + mi * 16 + ar;
                ldsm4(sptr(sAh + sw128B(r, ac)), ah[mi]);
                ldsm4(sptr(sAl + sw128B(r, ac)), al[mi]);
            }
            uint32_t bh[2][4], bl[2][4];
            const int br = ((lane >> 4) << 3) + (lane & 7);
            const int bc = kt * 2 + ((lane >> 3) & 1);
            #pragma unroll
            for (int pr = 0; pr < 2; pr++) {
                int r = wn * 32 + pr * 16 + br;
                ldsm4(sptr(sWh + sw128B(r, bc)), bh[pr]);
                ldsm4(sptr(sWl + sw128B(r, bc)), bl[pr]);
            }
            #pragma unroll
            for (int mi = 0; mi < 4; mi++)
                #pragma unroll
                for (int ni = 0; ni < 4; ni++) {
                    uint32_t b0h = bh[ni >> 1][(ni & 1) * 2], b1h = bh[ni >> 1][(ni & 1) * 2 + 1];
                    uint32_t b0l = bl[ni >> 1][(ni & 1) * 2], b1l = bl[ni >> 1][(ni & 1) * 2 + 1];
                    mma16816(c[mi][ni], ah[mi], b0h, b1h);
                    mma16816(c[mi][ni], ah[mi], b0l, b1l);
                    mma16816(c[mi][ni], al[mi], b0h, b1h);
                }
        }
        __syncthreads();
    }

    __nv_bfloat16 *dsth = nullptr, *dstl = nullptr;
    if (c_sel == 0) { dsth = g_qh; dstl = g_ql; }
    else if (c_sel == 1) { dsth = g_kh; dstl = g_kl; }
    else if (c_sel == 2) { dsth = g_vh; dstl = g_vl; }

    #pragma unroll
    for (int mi = 0; mi < 4; mi++)
        #pragma unroll
        for (int ni = 0; ni < 4; ni++)
            #pragma unroll
            for (int inst = 0; inst < 2; inst++) {
                int m = m0 + wm * 64 + mi * 16 + inst * 8 + g;
                int n = n0 + wn * 32 + ni * 8 + 2 * tg;
                float b0 = bias ? bias[n] : 0.f;
                float b1 = bias ? bias[n + 1] : 0.f;
                float v0 = c[mi][ni][inst * 2] + b0;
                float v1 = c[mi][ni][inst * 2 + 1] + b1;
                if (c_sel < 3) {
                    uint32_t ph, pl;
                    split2(v0, v1, ph, pl);
                    size_t addr = ((size_t)(n >> 6) * TLEN + m) * HDIM + (n & 63);
                    *(uint32_t*)(dsth + addr) = ph;
                    *(uint32_t*)(dstl + addr) = pl;
                } else {
                    float2 r; r.x = v0; r.y = v1;
                    *(float2*)(dout + (size_t)m * DMODEL + n) = r;
                }
            }
}

// ============================================================================
// Warp-strip attention: warp w owns Q rows [w*16, w*16+16) x all 128 keys.
// Q fragments hoisted to registers. Scores stay in registers; E fragments
// built in registers (C->A layout identity) and fed straight to PV mma.
// Rowmax/rowsum: shfl-only. SMEM: Q 32K | K 2x32K | V 2x32K = 160KB.
// ============================================================================
#define AT_QH    0
#define AT_QL    16384
#define AT_KH(s) (32768 + (s) * 32768)
#define AT_KL(s) (32768 + (s) * 32768 + 16384)
#define AT_VH(s) (98304 + (s) * 32768)
#define AT_VL(s) (98304 + (s) * 32768 + 16384)
#define ATTN_SMEM 163840

__global__ __launch_bounds__(256, 1)
void attn_kernel(float scaling)
{
    extern __shared__ char sm[];
    uint32_t sb = sptr(sm);
    const int tid = threadIdx.x;
    const int lane = tid & 31, wid = tid >> 5;
    const int tg = lane & 3;
    const int h = blockIdx.y;
    const int t0 = blockIdx.x * 128;

    const __nv_bfloat16* Kh  = g_kh + (size_t)h * TLEN * HDIM;
    const __nv_bfloat16* Klp = g_kl + (size_t)h * TLEN * HDIM;
    const __nv_bfloat16* Vh  = g_vh + (size_t)h * TLEN * HDIM;
    const __nv_bfloat16* Vlp = g_vl + (size_t)h * TLEN * HDIM;

    const int ar = lane & 15;
    const int br = ((lane >> 4) << 3) + (lane & 7);

    // ---- load Q and first K(hi); hoist Q fragments into registers ----
    cp_tile(sb + AT_QH, g_qh + ((size_t)h * TLEN + t0) * HDIM, tid);
    cp_tile(sb + AT_QL, g_ql + ((size_t)h * TLEN + t0) * HDIM, tid);
    cp_tile(sb + AT_KH(0), Kh, tid);
    CP_COMMIT();
    CP_WAIT(0);
    __syncthreads();

    uint32_t qh[4][4], ql[4][4];
    #pragma unroll
    for (int kt = 0; kt < 4; kt++) {
        int ac = kt * 2 + (lane >> 4);
        ldsm4(sb + AT_QH + sw128B(wid * 16 + ar, ac), qh[kt]);
        ldsm4(sb + AT_QL + sw128B(wid * 16 + ar, ac), ql[kt]);
    }

    // =================== pass 1: rowmax (hi-only QK) ===================
    float rm0 = -3.402823466e38f, rm1 = -3.402823466e38f;
    for (int st = 0; st < NT; st++) {
        int b = st & 1;
        if (st + 1 < NT) {
            cp_tile(sb + AT_KH(b ^ 1), Kh + (size_t)(st + 1) * 128 * HDIM, tid);
            CP_COMMIT();
            CP_WAIT(1);
        } else CP_WAIT(0);
        __syncthreads();
        uint32_t sKh = sb + AT_KH(b);

        #pragma unroll
        for (int n2 = 0; n2 < 8; n2++) {
            float c[2][4] = {{0.f, 0.f, 0.f, 0.f}, {0.f, 0.f, 0.f, 0.f}};
            #pragma unroll
            for (int kt = 0; kt < 4; kt++) {
                uint32_t bh[4];
                ldsm4(sKh + sw128B(n2 * 16 + br, kt * 2 + ((lane >> 3) & 1)), bh);
                mma16816(c[0], qh[kt], bh[0], bh[1]);
                mma16816(c[1], qh[kt], bh[2], bh[3]);
            }
            #pragma unroll
            for (int u = 0; u < 2; u++) {
                rm0 = fmaxf(rm0, fmaxf(__fmul_rn(c[u][0], scaling), __fmul_rn(c[u][1], scaling)));
                rm1 = fmaxf(rm1, fmaxf(__fmul_rn(c[u][2], scaling), __fmul_rn(c[u][3], scaling)));
            }
        }
        __syncthreads();
    }
    rm0 = fmaxf(rm0, __shfl_xor_sync(0xffffffff, rm0, 1));
    rm0 = fmaxf(rm0, __shfl_xor_sync(0xffffffff, rm0, 2));
    rm1 = fmaxf(rm1, __shfl_xor_sync(0xffffffff, rm1, 1));
    rm1 = fmaxf(rm1, __shfl_xor_sync(0xffffffff, rm1, 2));

    // =================== pass 2: exp + PV (E in registers) ===================
    float o[8][4];
    #pragma unroll
    for (int i = 0; i < 8; i++)
        #pragma unroll
        for (int e = 0; e < 4; e++) o[i][e] = 0.f;
    float rs0 = 0.f, rs1 = 0.f;

    cp_tile(sb + AT_KH(0), Kh, tid);
    cp_tile(sb + AT_KL(0), Klp, tid);
    cp_tile(sb + AT_VH(0), Vh, tid);
    cp_tile(sb + AT_VL(0), Vlp, tid);
    CP_COMMIT();

    for (int st = 0; st < NT; st++) {
        int b = st & 1;
        if (st + 1 < NT) {
            size_t go = (size_t)(st + 1) * 128 * HDIM;
            cp_tile(sb + AT_KH(b ^ 1), Kh + go, tid);
            cp_tile(sb + AT_KL(b ^ 1), Klp + go, tid);
            cp_tile(sb + AT_VH(b ^ 1), Vh + go, tid);
            cp_tile(sb + AT_VL(b ^ 1), Vlp + go, tid);
            CP_COMMIT();
            CP_WAIT(1);
        } else CP_WAIT(0);
        __syncthreads();

        uint32_t sKh = sb + AT_KH(b), sKl = sb + AT_KL(b);
        uint32_t sVh = sb + AT_VH(b), sVl = sb + AT_VL(b);

        #pragma unroll
        for (int n2 = 0; n2 < 8; n2++) {
            // --- scores for 16 keys (2 n-tiles), 3 split terms ---
            float c[2][4] = {{0.f, 0.f, 0.f, 0.f}, {0.f, 0.f, 0.f, 0.f}};
            #pragma unroll
            for (int kt = 0; kt < 4; kt++) {
                uint32_t bh[4], bl[4];
                int soff = sw128B(n2 * 16 + br, kt * 2 + ((lane >> 3) & 1));
                ldsm4(sKh + soff, bh);
                ldsm4(sKl + soff, bl);
                mma16816(c[0], qh[kt], bh[0], bh[1]);
                mma16816(c[0], qh[kt], bl[0], bl[1]);
                mma16816(c[0], ql[kt], bh[0], bh[1]);
                mma16816(c[1], qh[kt], bh[2], bh[3]);
                mma16816(c[1], qh[kt], bl[2], bl[3]);
                mma16816(c[1], ql[kt], bh[2], bh[3]);
            }
            // --- fastexp + build E fragments in registers ---
            float e00 = fastexp_g(__fmul_rn(c[0][0], scaling) - rm0);
            float e01 = fastexp_g(__fmul_rn(c[0][1], scaling) - rm0);
            float e02 = fastexp_g(__fmul_rn(c[0][2], scaling) - rm1);
            float e03 = fastexp_g(__fmul_rn(c[0][3], scaling) - rm1);
            float e10 = fastexp_g(__fmul_rn(c[1][0], scaling) - rm0);
            float e11 = fastexp_g(__fmul_rn(c[1][1], scaling) - rm0);
            float e12 = fastexp_g(__fmul_rn(c[1][2], scaling) - rm1);
            float e13 = fastexp_g(__fmul_rn(c[1][3], scaling) - rm1);
            rs0 += e00 + e01 + e10 + e11;
            rs1 += e02 + e03 + e12 + e13;
            uint32_t eh[4], el[4];
            split2(e00, e01, eh[0], el[0]);
            split2(e02, e03, eh[1], el[1]);
            split2(e10, e11, eh[2], el[2]);
            split2(e12, e13, eh[3], el[3]);
            // --- PV for this 16-key chunk ---
            #pragma unroll
            for (int dg = 0; dg < 4; dg++) {
                uint32_t vh[4], vl[4];
                int voff = sw128B(n2 * 16 + ar, dg * 2 + (lane >> 4));
                ldsm4t(sVh + voff, vh);
                ldsm4t(sVl + voff, vl);
                mma16816(o[dg * 2],     eh, vh[0], vh[1]);
                mma16816(o[dg * 2],     eh, vl[0], vl[1]);
                mma16816(o[dg * 2],     el, vh[0], vh[1]);
                mma16816(o[dg * 2 + 1], eh, vh[2], vh[3]);
                mma16816(o[dg * 2 + 1], eh, vl[2], vl[3]);
                mma16816(o[dg * 2 + 1], el, vh[2], vh[3]);
            }
        }
        __syncthreads();
    }

    // ---- rowsum reduce (shfl-only) + normalize + split-store O ----
    rs0 += __shfl_xor_sync(0xffffffff, rs0, 1);
    rs0 += __shfl_xor_sync(0xffffffff, rs0, 2);
    rs1 += __shfl_xor_sync(0xffffffff, rs1, 1);
    rs1 += __shfl_xor_sync(0xffffffff, rs1, 2);
    float inv0 = 1.0f / rs0, inv1 = 1.0f / rs1;

    int r0 = t0 + wid * 16 + (lane >> 2);
    #pragma unroll
    for (int dn = 0; dn < 8; dn++) {
        int d = h * HDIM + dn * 8 + 2 * tg;
        uint32_t ph, pl;
        split2(o[dn][0] * inv0, o[dn][1] * inv0, ph, pl);
        *(uint32_t*)(g_oh + (size_t)r0 * DMODEL + d) = ph;
        *(uint32_t*)(g_ol + (size_t)r0 * DMODEL + d) = pl;
        split2(o[dn][2] * inv1, o[dn][3] * inv1, ph, pl);
        *(uint32_t*)(g_oh + (size_t)(r0 + 8) * DMODEL + d) = ph;
        *(uint32_t*)(g_ol + (size_t)(r0 + 8) * DMODEL + d) = pl;
    }
}

// ============================================================================
extern "C" void kernel_launch(void* const* d_in, const int* in_sizes, int n_in,
                              void* d_out, int out_size)
{
    const float* x  = (const float*)d_in[0];
    const float* Wq = (const float*)d_in[1];
    const float* bq = (const float*)d_in[2];
    const float* Wk = (const float*)d_in[3];
    const float* bk = (const float*)d_in[4];
    const float* Wv = (const float*)d_in[5];
    const float* bv = (const float*)d_in[6];
    const float* Wo = (const float*)d_in[7];
    float* out = (float*)d_out;

    // Quake q_rsqrt(64) exact fp32 step order
    float xq = 64.0f;
    int ib;
    memcpy(&ib, &xq, 4);
    ib = 0x5f3759df - (ib >> 1);
    float y;
    memcpy(&y, &ib, 4);
    float t = 0.5f * xq;
    t = t * y;
    t = t * y;
    float scaling = y * (1.5f - t);

    cudaFuncSetAttribute(gemm_bf16, cudaFuncAttributeMaxDynamicSharedMemorySize, GEMM_SMEM);
    cudaFuncSetAttribute(attn_kernel, cudaFuncAttributeMaxDynamicSharedMemorySize, ATTN_SMEM);

    split_all<<<4096, 256>>>(x, Wq, Wk, Wv, Wo);

    // fused QKV projections (z = 0,1,2)
    dim3 qkv_grid(DMODEL / 128, TLEN / 128, 3);
    gemm_bf16<<<qkv_grid, 256, GEMM_SMEM>>>(0, -1, bq, bk, bv, out);

    attn_kernel<<<dim3(TLEN / 128, NHEADS), 256, ATTN_SMEM>>>(scaling);

    // output projection
    dim3 o_grid(DMODEL / 128, TLEN / 128, 1);
    gemm_bf16<<<o_grid, 256, GEMM_SMEM>>>(1, 3, nullptr, nullptr, nullptr, out);
}

// round 8
// speedup vs baseline: 1.5505x; 1.0122x over previous
#include <cuda_runtime.h>
#include <cuda_bf16.h>
#include <cstring>
#include <cstdint>

#define TLEN   4096
#define DMODEL 1024
#define NHEADS 16
#define HDIM   64

// ---------------- device scratch ----------------
__device__ __nv_bfloat16 g_xh[TLEN * DMODEL], g_xl[TLEN * DMODEL];
__device__ __nv_bfloat16 g_wh[4 * DMODEL * DMODEL], g_wl[4 * DMODEL * DMODEL];
__device__ __nv_bfloat16 g_qh[NHEADS * TLEN * HDIM], g_ql[NHEADS * TLEN * HDIM];
__device__ __nv_bfloat16 g_kh[NHEADS * TLEN * HDIM], g_kl[NHEADS * TLEN * HDIM];
__device__ __nv_bfloat16 g_vh[NHEADS * TLEN * HDIM], g_vl[NHEADS * TLEN * HDIM];
__device__ __nv_bfloat16 g_oh[TLEN * DMODEL], g_ol[TLEN * DMODEL];

// ---------------- fastexp_gist ----------------
__device__ __forceinline__ float fastexp_g(float x) {
    const float GA = (float)12102203.17133801;
    const float GB = (float)1064986823.010288;
    float y = __fadd_rn(__fmul_rn(GA, x), GB);
    int yi = (y < 8388608.0f || y > 2139095040.0f) ? 0 : __float2int_rz(y);
    return __int_as_float(yi);
}

// ---------------- helpers ----------------
__device__ __forceinline__ uint32_t sptr(const void* p) {
    return (uint32_t)__cvta_generic_to_shared(p);
}
__device__ __forceinline__ void ldsm4(uint32_t a, uint32_t* r) {
    asm volatile("ldmatrix.sync.aligned.m8n8.x4.shared.b16 {%0,%1,%2,%3}, [%4];"
                 : "=r"(r[0]), "=r"(r[1]), "=r"(r[2]), "=r"(r[3]) : "r"(a));
}
__device__ __forceinline__ void ldsm4t(uint32_t a, uint32_t* r) {
    asm volatile("ldmatrix.sync.aligned.m8n8.x4.trans.shared.b16 {%0,%1,%2,%3}, [%4];"
                 : "=r"(r[0]), "=r"(r[1]), "=r"(r[2]), "=r"(r[3]) : "r"(a));
}
__device__ __forceinline__ void mma16816(float* c, const uint32_t* a,
                                         uint32_t b0, uint32_t b1) {
    asm volatile(
        "mma.sync.aligned.m16n8k16.row.col.f32.bf16.bf16.f32 "
        "{%0,%1,%2,%3}, {%4,%5,%6,%7}, {%8,%9}, {%0,%1,%2,%3};"
        : "+f"(c[0]), "+f"(c[1]), "+f"(c[2]), "+f"(c[3])
        : "r"(a[0]), "r"(a[1]), "r"(a[2]), "r"(a[3]), "r"(b0), "r"(b1));
}
__device__ __forceinline__ int sw128B(int row, int ch) {
    return (row << 7) + ((ch ^ (row & 7)) << 4);
}
// fast split: packed bf16x2 cvt
__device__ __forceinline__ void split2(float v0, float v1, uint32_t& ph, uint32_t& pl) {
    uint32_t h;
    asm("cvt.rn.bf16x2.f32 %0, %1, %2;" : "=r"(h) : "f"(v1), "f"(v0));
    float h0 = __uint_as_float(h << 16);
    float h1 = __uint_as_float(h & 0xffff0000u);
    uint32_t l;
    float r0 = v0 - h0, r1 = v1 - h1;
    asm("cvt.rn.bf16x2.f32 %0, %1, %2;" : "=r"(l) : "f"(r1), "f"(r0));
    ph = h; pl = l;
}
// cp.async
__device__ __forceinline__ void cp16(uint32_t s, const void* g) {
    asm volatile("cp.async.cg.shared.global [%0], [%1], 16;" :: "r"(s), "l"(g));
}
#define CP_COMMIT() asm volatile("cp.async.commit_group;" ::: "memory")
#define CP_WAIT(n)  asm volatile("cp.async.wait_group %0;" :: "n"(n) : "memory")

// async-load one 64x64 bf16 plane (64 rows x 128B = 8 chunks/row) -- FIXED:
// 512 cp16s (2 per thread), full 8-chunk coverage per row.
__device__ __forceinline__ void cp_tile64(uint32_t sdst, const __nv_bfloat16* g, int tid) {
    #pragma unroll
    for (int p = 0; p < 2; p++) {
        int idx = p * 256 + tid;
        int r = idx >> 3, ch = idx & 7;
        cp16(sdst + sw128B(r, ch), g + (size_t)r * HDIM + ch * 8);
    }
}
// async-load one 128x64 bf16 plane
__device__ __forceinline__ void cp_tile128(uint32_t sdst, const __nv_bfloat16* g, int tid) {
    #pragma unroll
    for (int p = 0; p < 4; p++) {
        int idx = p * 256 + tid;
        int r = idx >> 3, ch = idx & 7;
        cp16(sdst + sw128B(r, ch), g + (size_t)r * HDIM + ch * 8);
    }
}

// ---------------- fused split (fp32 -> bf16 hi/lo) ----------------
__global__ void split_all(const float* __restrict__ x, const float* __restrict__ wq,
                          const float* __restrict__ wk, const float* __restrict__ wv,
                          const float* __restrict__ wo) {
    const int total = TLEN * DMODEL + 4 * DMODEL * DMODEL;
    for (int i = blockIdx.x * blockDim.x + threadIdx.x; i < total;
         i += gridDim.x * blockDim.x) {
        const float* src;
        __nv_bfloat16 *hi, *lo;
        int off;
        if (i < TLEN * DMODEL) {
            src = x; hi = g_xh; lo = g_xl; off = i;
        } else {
            int j = i - TLEN * DMODEL;
            int w = j >> 20;
            off = j & ((1 << 20) - 1);
            src = (w == 0) ? wq : (w == 1) ? wk : (w == 2) ? wv : wo;
            hi = g_wh + ((size_t)w << 20);
            lo = g_wl + ((size_t)w << 20);
        }
        float v = src[off];
        __nv_bfloat16 h = __float2bfloat16(v);
        hi[off] = h;
        lo[off] = __float2bfloat16(v - __bfloat162float(h));
    }
}

// ============================================================================
// Split-bf16 mma.sync GEMM. KC=32 k-chunks; 128x32 logical tiles folded into
// 64x64 physical SW128 tiles (phys row = r&63, phys chunk = (r>>6)*4+ch).
// 2 stages x 32KB = 64KB smem -> 2 CTAs/SM.
// ============================================================================
#define GEMM_SMEM 65536

// folded smem offset for logical row r (0..127), 16B chunk ch (0..3)
__device__ __forceinline__ int fold_off(int r, int ch) {
    int pr = r & 63;
    int pc = ((r >> 6) << 2) + ch;
    return (pr << 7) + ((pc ^ (pr & 7)) << 4);
}

__device__ __forceinline__ void gemm_prefetch(uint32_t sb, int s, int kc,
                                              const __nv_bfloat16* Ah, const __nv_bfloat16* Al,
                                              const __nv_bfloat16* Wh, const __nv_bfloat16* Wl,
                                              int m0, int n0, int tid) {
    uint32_t base = sb + s * 32768;
    #pragma unroll
    for (int p = 0; p < 2; p++) {
        int idx = p * 256 + tid;
        int r = idx >> 2, ch = idx & 3;
        size_t ga = (size_t)(m0 + r) * DMODEL + kc * 32 + ch * 8;
        size_t gw = (size_t)(n0 + r) * DMODEL + kc * 32 + ch * 8;
        uint32_t so = fold_off(r, ch);
        cp16(base + so,          Ah + ga);
        cp16(base + 8192 + so,   Al + ga);
        cp16(base + 16384 + so,  Wh + gw);
        cp16(base + 24576 + so,  Wl + gw);
    }
}

__global__ __launch_bounds__(256, 2)
void gemm_bf16(int a_sel, int w_fixed, const float* __restrict__ bq,
               const float* __restrict__ bk, const float* __restrict__ bv,
               float* __restrict__ dout)
{
    extern __shared__ char sm[];
    uint32_t sb = sptr(sm);
    const int c_sel = (w_fixed < 0) ? (int)blockIdx.z : 3;
    const int w_idx = (w_fixed < 0) ? (int)blockIdx.z : w_fixed;
    const float* bias = (c_sel == 0) ? bq : (c_sel == 1) ? bk : (c_sel == 2) ? bv : nullptr;

    const __nv_bfloat16* Ah = a_sel ? g_oh : g_xh;
    const __nv_bfloat16* Al = a_sel ? g_ol : g_xl;
    const __nv_bfloat16* Wh = g_wh + (size_t)w_idx * DMODEL * DMODEL;
    const __nv_bfloat16* Wl = g_wl + (size_t)w_idx * DMODEL * DMODEL;

    const int tid = threadIdx.x;
    const int lane = tid & 31, wid = tid >> 5;
    const int g = lane >> 2, tg = lane & 3;
    const int wm = wid >> 2, wn = wid & 3;
    const int m0 = blockIdx.y * 128, n0 = blockIdx.x * 128;

    float c[4][4][4];
    #pragma unroll
    for (int i = 0; i < 4; i++)
        #pragma unroll
        for (int j = 0; j < 4; j++)
            #pragma unroll
            for (int e = 0; e < 4; e++) c[i][j][e] = 0.f;

    gemm_prefetch(sb, 0, 0, Ah, Al, Wh, Wl, m0, n0, tid);
    CP_COMMIT();

    const int ar = lane & 15;
    const int br = ((lane >> 4) << 3) + (lane & 7);

    for (int kc = 0; kc < 32; kc++) {
        int s = kc & 1;
        if (kc + 1 < 32) {
            gemm_prefetch(sb, s ^ 1, kc + 1, Ah, Al, Wh, Wl, m0, n0, tid);
            CP_COMMIT();
            CP_WAIT(1);
        } else CP_WAIT(0);
        __syncthreads();

        uint32_t sAh = sb + s * 32768;
        uint32_t sAl = sAh + 8192;
        uint32_t sWh = sAh + 16384;
        uint32_t sWl = sAh + 24576;

        #pragma unroll
        for (int kt = 0; kt < 2; kt++) {
            uint32_t ah[4][4], al[4][4];
            const int ac = kt * 2 + (lane >> 4);           // logical chunk 0..3
            #pragma unroll
            for (int mi = 0; mi < 4; mi++) {
                int r = wm * 64 + mi * 16 + ar;
                int off = fold_off(r, ac);
                ldsm4(sAh + off, ah[mi]);
                ldsm4(sAl + off, al[mi]);
            }
            uint32_t bh[2][4], bl[2][4];
            const int bc = kt * 2 + ((lane >> 3) & 1);
            #pragma unroll
            for (int pr = 0; pr < 2; pr++) {
                int r = wn * 32 + pr * 16 + br;
                int off = fold_off(r, bc);
                ldsm4(sWh + off, bh[pr]);
                ldsm4(sWl + off, bl[pr]);
            }
            #pragma unroll
            for (int mi = 0; mi < 4; mi++)
                #pragma unroll
                for (int ni = 0; ni < 4; ni++) {
                    uint32_t b0h = bh[ni >> 1][(ni & 1) * 2], b1h = bh[ni >> 1][(ni & 1) * 2 + 1];
                    uint32_t b0l = bl[ni >> 1][(ni & 1) * 2], b1l = bl[ni >> 1][(ni & 1) * 2 + 1];
                    mma16816(c[mi][ni], ah[mi], b0h, b1h);
                    mma16816(c[mi][ni], ah[mi], b0l, b1l);
                    mma16816(c[mi][ni], al[mi], b0h, b1h);
                }
        }
        __syncthreads();
    }

    __nv_bfloat16 *dsth = nullptr, *dstl = nullptr;
    if (c_sel == 0) { dsth = g_qh; dstl = g_ql; }
    else if (c_sel == 1) { dsth = g_kh; dstl = g_kl; }
    else if (c_sel == 2) { dsth = g_vh; dstl = g_vl; }

    #pragma unroll
    for (int mi = 0; mi < 4; mi++)
        #pragma unroll
        for (int ni = 0; ni < 4; ni++)
            #pragma unroll
            for (int inst = 0; inst < 2; inst++) {
                int m = m0 + wm * 64 + mi * 16 + inst * 8 + g;
                int n = n0 + wn * 32 + ni * 8 + 2 * tg;
                float b0 = bias ? bias[n] : 0.f;
                float b1 = bias ? bias[n + 1] : 0.f;
                float v0 = c[mi][ni][inst * 2] + b0;
                float v1 = c[mi][ni][inst * 2 + 1] + b1;
                if (c_sel < 3) {
                    uint32_t ph, pl;
                    split2(v0, v1, ph, pl);
                    size_t addr = ((size_t)(n >> 6) * TLEN + m) * HDIM + (n & 63);
                    *(uint32_t*)(dsth + addr) = ph;
                    *(uint32_t*)(dstl + addr) = pl;
                } else {
                    float2 r; r.x = v0; r.y = v1;
                    *(float2*)(dout + (size_t)m * DMODEL + n) = r;
                }
            }
}

// ============================================================================
// Warp-strip attention: warp w owns Q rows [w*16, w*16+16) x all keys.
// K/V staged in 64-key tiles (stage 32KB, 2 stages) -> 96KB smem, 2 CTAs/SM.
// ============================================================================
#define AT_QH    0
#define AT_QL    16384
#define AT_S(s)  (32768 + (s) * 32768)   // KH +0 | KL +8K | VH +16K | VL +24K
#define ATTN_SMEM 98304
#define NT64     64                       // 64-key tiles

__global__ __launch_bounds__(256, 2)
void attn_kernel(float scaling)
{
    extern __shared__ char sm[];
    uint32_t sb = sptr(sm);
    const int tid = threadIdx.x;
    const int lane = tid & 31, wid = tid >> 5;
    const int tg = lane & 3;
    const int h = blockIdx.y;
    const int t0 = blockIdx.x * 128;

    const __nv_bfloat16* Kh  = g_kh + (size_t)h * TLEN * HDIM;
    const __nv_bfloat16* Klp = g_kl + (size_t)h * TLEN * HDIM;
    const __nv_bfloat16* Vh  = g_vh + (size_t)h * TLEN * HDIM;
    const __nv_bfloat16* Vlp = g_vl + (size_t)h * TLEN * HDIM;

    const int ar = lane & 15;
    const int br = ((lane >> 4) << 3) + (lane & 7);

    // ---- load Q and first K(hi); hoist Q fragments into registers ----
    cp_tile128(sb + AT_QH, g_qh + ((size_t)h * TLEN + t0) * HDIM, tid);
    cp_tile128(sb + AT_QL, g_ql + ((size_t)h * TLEN + t0) * HDIM, tid);
    cp_tile64(sb + AT_S(0), Kh, tid);
    CP_COMMIT();
    CP_WAIT(0);
    __syncthreads();

    uint32_t qh[4][4], ql[4][4];
    #pragma unroll
    for (int kt = 0; kt < 4; kt++) {
        int ac = kt * 2 + (lane >> 4);
        ldsm4(sb + AT_QH + sw128B(wid * 16 + ar, ac), qh[kt]);
        ldsm4(sb + AT_QL + sw128B(wid * 16 + ar, ac), ql[kt]);
    }

    // =================== pass 1: rowmax (hi-only QK) ===================
    float rm0 = -3.402823466e38f, rm1 = -3.402823466e38f;
    for (int st = 0; st < NT64; st++) {
        int b = st & 1;
        if (st + 1 < NT64) {
            cp_tile64(sb + AT_S(b ^ 1), Kh + (size_t)(st + 1) * 64 * HDIM, tid);
            CP_COMMIT();
            CP_WAIT(1);
        } else CP_WAIT(0);
        __syncthreads();
        uint32_t sKh = sb + AT_S(b);

        #pragma unroll
        for (int n2 = 0; n2 < 4; n2++) {
            float c[2][4] = {{0.f, 0.f, 0.f, 0.f}, {0.f, 0.f, 0.f, 0.f}};
            #pragma unroll
            for (int kt = 0; kt < 4; kt++) {
                uint32_t bh[4];
                ldsm4(sKh + sw128B(n2 * 16 + br, kt * 2 + ((lane >> 3) & 1)), bh);
                mma16816(c[0], qh[kt], bh[0], bh[1]);
                mma16816(c[1], qh[kt], bh[2], bh[3]);
            }
            #pragma unroll
            for (int u = 0; u < 2; u++) {
                rm0 = fmaxf(rm0, fmaxf(__fmul_rn(c[u][0], scaling), __fmul_rn(c[u][1], scaling)));
                rm1 = fmaxf(rm1, fmaxf(__fmul_rn(c[u][2], scaling), __fmul_rn(c[u][3], scaling)));
            }
        }
        __syncthreads();
    }
    rm0 = fmaxf(rm0, __shfl_xor_sync(0xffffffff, rm0, 1));
    rm0 = fmaxf(rm0, __shfl_xor_sync(0xffffffff, rm0, 2));
    rm1 = fmaxf(rm1, __shfl_xor_sync(0xffffffff, rm1, 1));
    rm1 = fmaxf(rm1, __shfl_xor_sync(0xffffffff, rm1, 2));

    // =================== pass 2: exp + PV (E in registers) ===================
    float o[8][4];
    #pragma unroll
    for (int i = 0; i < 8; i++)
        #pragma unroll
        for (int e = 0; e < 4; e++) o[i][e] = 0.f;
    float rs0 = 0.f, rs1 = 0.f;

    cp_tile64(sb + AT_S(0),         Kh, tid);
    cp_tile64(sb + AT_S(0) + 8192,  Klp, tid);
    cp_tile64(sb + AT_S(0) + 16384, Vh, tid);
    cp_tile64(sb + AT_S(0) + 24576, Vlp, tid);
    CP_COMMIT();

    for (int st = 0; st < NT64; st++) {
        int b = st & 1;
        if (st + 1 < NT64) {
            size_t go = (size_t)(st + 1) * 64 * HDIM;
            cp_tile64(sb + AT_S(b ^ 1),         Kh + go, tid);
            cp_tile64(sb + AT_S(b ^ 1) + 8192,  Klp + go, tid);
            cp_tile64(sb + AT_S(b ^ 1) + 16384, Vh + go, tid);
            cp_tile64(sb + AT_S(b ^ 1) + 24576, Vlp + go, tid);
            CP_COMMIT();
            CP_WAIT(1);
        } else CP_WAIT(0);
        __syncthreads();

        uint32_t sKh = sb + AT_S(b), sKl = sKh + 8192;
        uint32_t sVh = sKh + 16384,  sVl = sKh + 24576;

        #pragma unroll
        for (int n2 = 0; n2 < 4; n2++) {
            // --- scores for 16 keys, 3 split terms ---
            float c[2][4] = {{0.f, 0.f, 0.f, 0.f}, {0.f, 0.f, 0.f, 0.f}};
            #pragma unroll
            for (int kt = 0; kt < 4; kt++) {
                uint32_t bh[4], bl[4];
                int soff = sw128B(n2 * 16 + br, kt * 2 + ((lane >> 3) & 1));
                ldsm4(sKh + soff, bh);
                ldsm4(sKl + soff, bl);
                mma16816(c[0], qh[kt], bh[0], bh[1]);
                mma16816(c[0], qh[kt], bl[0], bl[1]);
                mma16816(c[0], ql[kt], bh[0], bh[1]);
                mma16816(c[1], qh[kt], bh[2], bh[3]);
                mma16816(c[1], qh[kt], bl[2], bl[3]);
                mma16816(c[1], ql[kt], bh[2], bh[3]);
            }
            // --- fastexp + build E fragments in registers ---
            float e00 = fastexp_g(__fmul_rn(c[0][0], scaling) - rm0);
            float e01 = fastexp_g(__fmul_rn(c[0][1], scaling) - rm0);
            float e02 = fastexp_g(__fmul_rn(c[0][2], scaling) - rm1);
            float e03 = fastexp_g(__fmul_rn(c[0][3], scaling) - rm1);
            float e10 = fastexp_g(__fmul_rn(c[1][0], scaling) - rm0);
            float e11 = fastexp_g(__fmul_rn(c[1][1], scaling) - rm0);
            float e12 = fastexp_g(__fmul_rn(c[1][2], scaling) - rm1);
            float e13 = fastexp_g(__fmul_rn(c[1][3], scaling) - rm1);
            rs0 += e00 + e01 + e10 + e11;
            rs1 += e02 + e03 + e12 + e13;
            uint32_t eh[4], el[4];
            split2(e00, e01, eh[0], el[0]);
            split2(e02, e03, eh[1], el[1]);
            split2(e10, e11, eh[2], el[2]);
            split2(e12, e13, eh[3], el[3]);
            // --- PV for this 16-key chunk ---
            #pragma unroll
            for (int dg = 0; dg < 4; dg++) {
                uint32_t vh[4], vl[4];
                int voff = sw128B(n2 * 16 + ar, dg * 2 + (lane >> 4));
                ldsm4t(sVh + voff, vh);
                ldsm4t(sVl + voff, vl);
                mma16816(o[dg * 2],     eh, vh[0], vh[1]);
                mma16816(o[dg * 2],     eh, vl[0], vl[1]);
                mma16816(o[dg * 2],     el, vh[0], vh[1]);
                mma16816(o[dg * 2 + 1], eh, vh[2], vh[3]);
                mma16816(o[dg * 2 + 1], eh, vl[2], vl[3]);
                mma16816(o[dg * 2 + 1], el, vh[2], vh[3]);
            }
        }
        __syncthreads();
    }

    // ---- rowsum reduce (shfl-only) + normalize + split-store O ----
    rs0 += __shfl_xor_sync(0xffffffff, rs0, 1);
    rs0 += __shfl_xor_sync(0xffffffff, rs0, 2);
    rs1 += __shfl_xor_sync(0xffffffff, rs1, 1);
    rs1 += __shfl_xor_sync(0xffffffff, rs1, 2);
    float inv0 = 1.0f / rs0, inv1 = 1.0f / rs1;

    int r0 = t0 + wid * 16 + (lane >> 2);
    #pragma unroll
    for (int dn = 0; dn < 8; dn++) {
        int d = h * HDIM + dn * 8 + 2 * tg;
        uint32_t ph, pl;
        split2(o[dn][0] * inv0, o[dn][1] * inv0, ph, pl);
        *(uint32_t*)(g_oh + (size_t)r0 * DMODEL + d) = ph;
        *(uint32_t*)(g_ol + (size_t)r0 * DMODEL + d) = pl;
        split2(o[dn][2] * inv1, o[dn][3] * inv1, ph, pl);
        *(uint32_t*)(g_oh + (size_t)(r0 + 8) * DMODEL + d) = ph;
        *(uint32_t*)(g_ol + (size_t)(r0 + 8) * DMODEL + d) = pl;
    }
}

// ============================================================================
extern "C" void kernel_launch(void* const* d_in, const int* in_sizes, int n_in,
                              void* d_out, int out_size)
{
    const float* x  = (const float*)d_in[0];
    const float* Wq = (const float*)d_in[1];
    const float* bq = (const float*)d_in[2];
    const float* Wk = (const float*)d_in[3];
    const float* bk = (const float*)d_in[4];
    const float* Wv = (const float*)d_in[5];
    const float* bv = (const float*)d_in[6];
    const float* Wo = (const float*)d_in[7];
    float* out = (float*)d_out;

    // Quake q_rsqrt(64) exact fp32 step order
    float xq = 64.0f;
    int ib;
    memcpy(&ib, &xq, 4);
    ib = 0x5f3759df - (ib >> 1);
    float y;
    memcpy(&y, &ib, 4);
    float t = 0.5f * xq;
    t = t * y;
    t = t * y;
    float scaling = y * (1.5f - t);

    cudaFuncSetAttribute(gemm_bf16, cudaFuncAttributeMaxDynamicSharedMemorySize, GEMM_SMEM);
    cudaFuncSetAttribute(attn_kernel, cudaFuncAttributeMaxDynamicSharedMemorySize, ATTN_SMEM);

    split_all<<<4096, 256>>>(x, Wq, Wk, Wv, Wo);

    // fused QKV projections (z = 0,1,2)
    dim3 qkv_grid(DMODEL / 128, TLEN / 128, 3);
    gemm_bf16<<<qkv_grid, 256, GEMM_SMEM>>>(0, -1, bq, bk, bv, out);

    attn_kernel<<<dim3(TLEN / 128, NHEADS), 256, ATTN_SMEM>>>(scaling);

    // output projection
    dim3 o_grid(DMODEL / 128, TLEN / 128, 1);
    gemm_bf16<<<o_grid, 256, GEMM_SMEM>>>(1, 3, nullptr, nullptr, nullptr, out);
}

// round 9
// speedup vs baseline: 1.5700x; 1.0125x over previous
#include <cuda_runtime.h>
#include <cuda_bf16.h>
#include <cstring>
#include <cstdint>

#define TLEN   4096
#define DMODEL 1024
#define NHEADS 16
#define HDIM   64

// ---------------- device scratch ----------------
__device__ __nv_bfloat16 g_xh[TLEN * DMODEL], g_xl[TLEN * DMODEL];
__device__ __nv_bfloat16 g_wh[4 * DMODEL * DMODEL], g_wl[4 * DMODEL * DMODEL];
__device__ __nv_bfloat16 g_qh[NHEADS * TLEN * HDIM], g_ql[NHEADS * TLEN * HDIM];
__device__ __nv_bfloat16 g_kh[NHEADS * TLEN * HDIM], g_kl[NHEADS * TLEN * HDIM];
__device__ __nv_bfloat16 g_vh[NHEADS * TLEN * HDIM], g_vl[NHEADS * TLEN * HDIM];
__device__ __nv_bfloat16 g_oh[TLEN * DMODEL], g_ol[TLEN * DMODEL];

// ---------------- fastexp_gist ----------------
__device__ __forceinline__ float fastexp_g(float x) {
    const float GA = (float)12102203.17133801;
    const float GB = (float)1064986823.010288;
    float y = __fadd_rn(__fmul_rn(GA, x), GB);
    int yi = (y < 8388608.0f || y > 2139095040.0f) ? 0 : __float2int_rz(y);
    return __int_as_float(yi);
}

// ---------------- helpers ----------------
__device__ __forceinline__ uint32_t sptr(const void* p) {
    return (uint32_t)__cvta_generic_to_shared(p);
}
__device__ __forceinline__ void ldsm4(uint32_t a, uint32_t* r) {
    asm volatile("ldmatrix.sync.aligned.m8n8.x4.shared.b16 {%0,%1,%2,%3}, [%4];"
                 : "=r"(r[0]), "=r"(r[1]), "=r"(r[2]), "=r"(r[3]) : "r"(a));
}
__device__ __forceinline__ void ldsm4t(uint32_t a, uint32_t* r) {
    asm volatile("ldmatrix.sync.aligned.m8n8.x4.trans.shared.b16 {%0,%1,%2,%3}, [%4];"
                 : "=r"(r[0]), "=r"(r[1]), "=r"(r[2]), "=r"(r[3]) : "r"(a));
}
__device__ __forceinline__ void mma16816(float* c, const uint32_t* a,
                                         uint32_t b0, uint32_t b1) {
    asm volatile(
        "mma.sync.aligned.m16n8k16.row.col.f32.bf16.bf16.f32 "
        "{%0,%1,%2,%3}, {%4,%5,%6,%7}, {%8,%9}, {%0,%1,%2,%3};"
        : "+f"(c[0]), "+f"(c[1]), "+f"(c[2]), "+f"(c[3])
        : "r"(a[0]), "r"(a[1]), "r"(a[2]), "r"(a[3]), "r"(b0), "r"(b1));
}
__device__ __forceinline__ int sw128B(int row, int ch) {
    return (row << 7) + ((ch ^ (row & 7)) << 4);
}
// fast split: packed bf16x2 cvt
__device__ __forceinline__ void split2(float v0, float v1, uint32_t& ph, uint32_t& pl) {
    uint32_t h;
    asm("cvt.rn.bf16x2.f32 %0, %1, %2;" : "=r"(h) : "f"(v1), "f"(v0));
    float h0 = __uint_as_float(h << 16);
    float h1 = __uint_as_float(h & 0xffff0000u);
    uint32_t l;
    float r0 = v0 - h0, r1 = v1 - h1;
    asm("cvt.rn.bf16x2.f32 %0, %1, %2;" : "=r"(l) : "f"(r1), "f"(r0));
    ph = h; pl = l;
}
// cp.async
__device__ __forceinline__ void cp16(uint32_t s, const void* g) {
    asm volatile("cp.async.cg.shared.global [%0], [%1], 16;" :: "r"(s), "l"(g));
}
#define CP_COMMIT() asm volatile("cp.async.commit_group;" ::: "memory")
#define CP_WAIT(n)  asm volatile("cp.async.wait_group %0;" :: "n"(n) : "memory")

// ---------------- fused split (fp32 -> bf16 hi/lo) ----------------
__global__ void split_all(const float* __restrict__ x, const float* __restrict__ wq,
                          const float* __restrict__ wk, const float* __restrict__ wv,
                          const float* __restrict__ wo) {
    const int total = TLEN * DMODEL + 4 * DMODEL * DMODEL;
    for (int i = blockIdx.x * blockDim.x + threadIdx.x; i < total;
         i += gridDim.x * blockDim.x) {
        const float* src;
        __nv_bfloat16 *hi, *lo;
        int off;
        if (i < TLEN * DMODEL) {
            src = x; hi = g_xh; lo = g_xl; off = i;
        } else {
            int j = i - TLEN * DMODEL;
            int w = j >> 20;
            off = j & ((1 << 20) - 1);
            src = (w == 0) ? wq : (w == 1) ? wk : (w == 2) ? wv : wo;
            hi = g_wh + ((size_t)w << 20);
            lo = g_wl + ((size_t)w << 20);
        }
        float v = src[off];
        __nv_bfloat16 h = __float2bfloat16(v);
        hi[off] = h;
        lo[off] = __float2bfloat16(v - __bfloat162float(h));
    }
}

// ============================================================================
// Split-bf16 mma.sync GEMM (R6 proven shape: KC=64, 64KB stage), now with a
// 3-stage cp.async pipeline and ONE __syncthreads per k-chunk.
// ============================================================================
#define GEMM_SMEM 196608

__device__ __forceinline__ void gemm_prefetch(uint32_t sb, int s, int kc,
                                              const __nv_bfloat16* Ah, const __nv_bfloat16* Al,
                                              const __nv_bfloat16* Wh, const __nv_bfloat16* Wl,
                                              int m0, int n0, int tid) {
    uint32_t base = sb + s * 65536;
    #pragma unroll
    for (int p = 0; p < 4; p++) {
        int idx = p * 256 + tid;
        int r = idx >> 3, ch = idx & 7;
        size_t ga = (size_t)(m0 + r) * DMODEL + kc * 64 + ch * 8;
        size_t gw = (size_t)(n0 + r) * DMODEL + kc * 64 + ch * 8;
        uint32_t so = sw128B(r, ch);
        cp16(base + so,          Ah + ga);
        cp16(base + 16384 + so,  Al + ga);
        cp16(base + 32768 + so,  Wh + gw);
        cp16(base + 49152 + so,  Wl + gw);
    }
}

__global__ __launch_bounds__(256, 1)
void gemm_bf16(int a_sel, int w_fixed, const float* __restrict__ bq,
               const float* __restrict__ bk, const float* __restrict__ bv,
               float* __restrict__ dout)
{
    extern __shared__ char sm[];
    uint32_t sb = sptr(sm);
    const int c_sel = (w_fixed < 0) ? (int)blockIdx.z : 3;
    const int w_idx = (w_fixed < 0) ? (int)blockIdx.z : w_fixed;
    const float* bias = (c_sel == 0) ? bq : (c_sel == 1) ? bk : (c_sel == 2) ? bv : nullptr;

    const __nv_bfloat16* Ah = a_sel ? g_oh : g_xh;
    const __nv_bfloat16* Al = a_sel ? g_ol : g_xl;
    const __nv_bfloat16* Wh = g_wh + (size_t)w_idx * DMODEL * DMODEL;
    const __nv_bfloat16* Wl = g_wl + (size_t)w_idx * DMODEL * DMODEL;

    const int tid = threadIdx.x;
    const int lane = tid & 31, wid = tid >> 5;
    const int g = lane >> 2, tg = lane & 3;
    const int wm = wid >> 2, wn = wid & 3;
    const int m0 = blockIdx.y * 128, n0 = blockIdx.x * 128;

    float c[4][4][4];
    #pragma unroll
    for (int i = 0; i < 4; i++)
        #pragma unroll
        for (int j = 0; j < 4; j++)
            #pragma unroll
            for (int e = 0; e < 4; e++) c[i][j][e] = 0.f;

    gemm_prefetch(sb, 0, 0, Ah, Al, Wh, Wl, m0, n0, tid);
    CP_COMMIT();
    gemm_prefetch(sb, 1, 1, Ah, Al, Wh, Wl, m0, n0, tid);
    CP_COMMIT();

    const int ar = lane & 15;
    const int br = ((lane >> 4) << 3) + (lane & 7);

    for (int kc = 0; kc < 16; kc++) {
        int s = kc % 3;
        if (kc < 15) { CP_WAIT(1); } else { CP_WAIT(0); }
        __syncthreads();

        uint32_t sAh = sb + s * 65536;
        uint32_t sAl = sAh + 16384;
        uint32_t sWh = sAh + 32768;
        uint32_t sWl = sAh + 49152;

        #pragma unroll
        for (int kt = 0; kt < 4; kt++) {
            uint32_t ah[4][4], al[4][4];
            const int ac = kt * 2 + (lane >> 4);
            #pragma unroll
            for (int mi = 0; mi < 4; mi++) {
                int r = wm * 64 + mi * 16 + ar;
                int off = sw128B(r, ac);
                ldsm4(sAh + off, ah[mi]);
                ldsm4(sAl + off, al[mi]);
            }
            uint32_t bh[2][4], bl[2][4];
            const int bc = kt * 2 + ((lane >> 3) & 1);
            #pragma unroll
            for (int pr = 0; pr < 2; pr++) {
                int r = wn * 32 + pr * 16 + br;
                int off = sw128B(r, bc);
                ldsm4(sWh + off, bh[pr]);
                ldsm4(sWl + off, bl[pr]);
            }
            #pragma unroll
            for (int mi = 0; mi < 4; mi++)
                #pragma unroll
                for (int ni = 0; ni < 4; ni++) {
                    uint32_t b0h = bh[ni >> 1][(ni & 1) * 2], b1h = bh[ni >> 1][(ni & 1) * 2 + 1];
                    uint32_t b0l = bl[ni >> 1][(ni & 1) * 2], b1l = bl[ni >> 1][(ni & 1) * 2 + 1];
                    mma16816(c[mi][ni], ah[mi], b0h, b1h);
                    mma16816(c[mi][ni], ah[mi], b0l, b1l);
                    mma16816(c[mi][ni], al[mi], b0h, b1h);
                }
        }

        if (kc + 2 < 16) {
            gemm_prefetch(sb, (kc + 2) % 3, kc + 2, Ah, Al, Wh, Wl, m0, n0, tid);
            CP_COMMIT();
        }
    }

    __nv_bfloat16 *dsth = nullptr, *dstl = nullptr;
    if (c_sel == 0) { dsth = g_qh; dstl = g_ql; }
    else if (c_sel == 1) { dsth = g_kh; dstl = g_kl; }
    else if (c_sel == 2) { dsth = g_vh; dstl = g_vl; }

    #pragma unroll
    for (int mi = 0; mi < 4; mi++)
        #pragma unroll
        for (int ni = 0; ni < 4; ni++)
            #pragma unroll
            for (int inst = 0; inst < 2; inst++) {
                int m = m0 + wm * 64 + mi * 16 + inst * 8 + g;
                int n = n0 + wn * 32 + ni * 8 + 2 * tg;
                float b0 = bias ? bias[n] : 0.f;
                float b1 = bias ? bias[n + 1] : 0.f;
                float v0 = c[mi][ni][inst * 2] + b0;
                float v1 = c[mi][ni][inst * 2 + 1] + b1;
                if (c_sel < 3) {
                    uint32_t ph, pl;
                    split2(v0, v1, ph, pl);
                    size_t addr = ((size_t)(n >> 6) * TLEN + m) * HDIM + (n & 63);
                    *(uint32_t*)(dsth + addr) = ph;
                    *(uint32_t*)(dstl + addr) = pl;
                } else {
                    float2 r; r.x = v0; r.y = v1;
                    *(float2*)(dout + (size_t)m * DMODEL + n) = r;
                }
            }
}

// ============================================================================
// Warp-strip attention: 512 threads, 256 q-rows per CTA (warp w owns rows
// [w*16, w*16+16)); K/V in 64-key tiles, 3-stage cp.async, 1 sync per tile.
// SMEM: Q 64KB | 3 stages x 32KB (KH+0 KL+8K VH+16K VL+24K) = 160KB.
// ============================================================================
#define AT_QH    0
#define AT_QL    32768
#define AT_S(s)  (65536 + (s) * 32768)
#define ATTN_SMEM 163840
#define NT64     64

// one 64x64 bf16 plane, 512 threads: 1 cp16 each
__device__ __forceinline__ void cp_tile64(uint32_t sdst, const __nv_bfloat16* g, int tid) {
    int r = tid >> 3, ch = tid & 7;
    cp16(sdst + sw128B(r, ch), g + (size_t)r * HDIM + ch * 8);
}
// one 256x64 bf16 plane, 512 threads: 4 cp16 each
__device__ __forceinline__ void cp_tile256(uint32_t sdst, const __nv_bfloat16* g, int tid) {
    #pragma unroll
    for (int p = 0; p < 4; p++) {
        int idx = p * 512 + tid;
        int r = idx >> 3, ch = idx & 7;
        cp16(sdst + sw128B(r, ch), g + (size_t)r * HDIM + ch * 8);
    }
}

__global__ __launch_bounds__(512, 1)
void attn_kernel(float scaling)
{
    extern __shared__ char sm[];
    uint32_t sb = sptr(sm);
    const int tid = threadIdx.x;
    const int lane = tid & 31, wid = tid >> 5;   // wid 0..15
    const int tg = lane & 3;
    const int h = blockIdx.y;
    const int t0 = blockIdx.x * 256;

    const __nv_bfloat16* Kh  = g_kh + (size_t)h * TLEN * HDIM;
    const __nv_bfloat16* Klp = g_kl + (size_t)h * TLEN * HDIM;
    const __nv_bfloat16* Vh  = g_vh + (size_t)h * TLEN * HDIM;
    const __nv_bfloat16* Vlp = g_vl + (size_t)h * TLEN * HDIM;

    const int ar = lane & 15;
    const int br = ((lane >> 4) << 3) + (lane & 7);

    // ---- group 0: Q planes + K tile 0 (hi) ; group 1: K tile 1 (hi) ----
    cp_tile256(sb + AT_QH, g_qh + ((size_t)h * TLEN + t0) * HDIM, tid);
    cp_tile256(sb + AT_QL, g_ql + ((size_t)h * TLEN + t0) * HDIM, tid);
    cp_tile64(sb + AT_S(0), Kh, tid);
    CP_COMMIT();
    cp_tile64(sb + AT_S(1), Kh + (size_t)64 * HDIM, tid);
    CP_COMMIT();

    // wait for group 0 (Q + K0), hoist Q fragments
    CP_WAIT(1);
    __syncthreads();
    uint32_t qh[4][4], ql[4][4];
    #pragma unroll
    for (int kt = 0; kt < 4; kt++) {
        int ac = kt * 2 + (lane >> 4);
        ldsm4(sb + AT_QH + sw128B(wid * 16 + ar, ac), qh[kt]);
        ldsm4(sb + AT_QL + sw128B(wid * 16 + ar, ac), ql[kt]);
    }

    // =================== pass 1: rowmax (hi-only QK) ===================
    float rm0 = -3.402823466e38f, rm1 = -3.402823466e38f;
    for (int st = 0; st < NT64; st++) {
        if (st < NT64 - 1) { CP_WAIT(1); } else { CP_WAIT(0); }
        __syncthreads();
        uint32_t sKh = sb + AT_S(st % 3);

        #pragma unroll
        for (int n2 = 0; n2 < 4; n2++) {
            float c[2][4] = {{0.f, 0.f, 0.f, 0.f}, {0.f, 0.f, 0.f, 0.f}};
            #pragma unroll
            for (int kt = 0; kt < 4; kt++) {
                uint32_t bh[4];
                ldsm4(sKh + sw128B(n2 * 16 + br, kt * 2 + ((lane >> 3) & 1)), bh);
                mma16816(c[0], qh[kt], bh[0], bh[1]);
                mma16816(c[1], qh[kt], bh[2], bh[3]);
            }
            #pragma unroll
            for (int u = 0; u < 2; u++) {
                rm0 = fmaxf(rm0, fmaxf(__fmul_rn(c[u][0], scaling), __fmul_rn(c[u][1], scaling)));
                rm1 = fmaxf(rm1, fmaxf(__fmul_rn(c[u][2], scaling), __fmul_rn(c[u][3], scaling)));
            }
        }
        if (st + 2 < NT64) {
            cp_tile64(sb + AT_S((st + 2) % 3), Kh + (size_t)(st + 2) * 64 * HDIM, tid);
            CP_COMMIT();
        }
    }
    rm0 = fmaxf(rm0, __shfl_xor_sync(0xffffffff, rm0, 1));
    rm0 = fmaxf(rm0, __shfl_xor_sync(0xffffffff, rm0, 2));
    rm1 = fmaxf(rm1, __shfl_xor_sync(0xffffffff, rm1, 1));
    rm1 = fmaxf(rm1, __shfl_xor_sync(0xffffffff, rm1, 2));

    // =================== pass 2: exp + PV (E in registers) ===================
    float o[8][4];
    #pragma unroll
    for (int i = 0; i < 8; i++)
        #pragma unroll
        for (int e = 0; e < 4; e++) o[i][e] = 0.f;
    float rs0 = 0.f, rs1 = 0.f;

    __syncthreads();   // all pass-1 reads done before reusing stage slots
    #pragma unroll
    for (int t = 0; t < 2; t++) {
        size_t go = (size_t)t * 64 * HDIM;
        cp_tile64(sb + AT_S(t),         Kh + go, tid);
        cp_tile64(sb + AT_S(t) + 8192,  Klp + go, tid);
        cp_tile64(sb + AT_S(t) + 16384, Vh + go, tid);
        cp_tile64(sb + AT_S(t) + 24576, Vlp + go, tid);
        CP_COMMIT();
    }

    for (int st = 0; st < NT64; st++) {
        if (st < NT64 - 1) { CP_WAIT(1); } else { CP_WAIT(0); }
        __syncthreads();

        uint32_t sKh = sb + AT_S(st % 3), sKl = sKh + 8192;
        uint32_t sVh = sKh + 16384,       sVl = sKh + 24576;

        #pragma unroll
        for (int n2 = 0; n2 < 4; n2++) {
            float c[2][4] = {{0.f, 0.f, 0.f, 0.f}, {0.f, 0.f, 0.f, 0.f}};
            #pragma unroll
            for (int kt = 0; kt < 4; kt++) {
                uint32_t bh[4], bl[4];
                int soff = sw128B(n2 * 16 + br, kt * 2 + ((lane >> 3) & 1));
                ldsm4(sKh + soff, bh);
                ldsm4(sKl + soff, bl);
                mma16816(c[0], qh[kt], bh[0], bh[1]);
                mma16816(c[0], qh[kt], bl[0], bl[1]);
                mma16816(c[0], ql[kt], bh[0], bh[1]);
                mma16816(c[1], qh[kt], bh[2], bh[3]);
                mma16816(c[1], qh[kt], bl[2], bl[3]);
                mma16816(c[1], ql[kt], bh[2], bh[3]);
            }
            float e00 = fastexp_g(__fmul_rn(c[0][0], scaling) - rm0);
            float e01 = fastexp_g(__fmul_rn(c[0][1], scaling) - rm0);
            float e02 = fastexp_g(__fmul_rn(c[0][2], scaling) - rm1);
            float e03 = fastexp_g(__fmul_rn(c[0][3], scaling) - rm1);
            float e10 = fastexp_g(__fmul_rn(c[1][0], scaling) - rm0);
            float e11 = fastexp_g(__fmul_rn(c[1][1], scaling) - rm0);
            float e12 = fastexp_g(__fmul_rn(c[1][2], scaling) - rm1);
            float e13 = fastexp_g(__fmul_rn(c[1][3], scaling) - rm1);
            rs0 += e00 + e01 + e10 + e11;
            rs1 += e02 + e03 + e12 + e13;
            uint32_t eh[4], el[4];
            split2(e00, e01, eh[0], el[0]);
            split2(e02, e03, eh[1], el[1]);
            split2(e10, e11, eh[2], el[2]);
            split2(e12, e13, eh[3], el[3]);
            #pragma unroll
            for (int dg = 0; dg < 4; dg++) {
                uint32_t vh[4], vl[4];
                int voff = sw128B(n2 * 16 + ar, dg * 2 + (lane >> 4));
                ldsm4t(sVh + voff, vh);
                ldsm4t(sVl + voff, vl);
                mma16816(o[dg * 2],     eh, vh[0], vh[1]);
                mma16816(o[dg * 2],     eh, vl[0], vl[1]);
                mma16816(o[dg * 2],     el, vh[0], vh[1]);
                mma16816(o[dg * 2 + 1], eh, vh[2], vh[3]);
                mma16816(o[dg * 2 + 1], eh, vl[2], vl[3]);
                mma16816(o[dg * 2 + 1], el, vh[2], vh[3]);
            }
        }

        if (st + 2 < NT64) {
            size_t go = (size_t)(st + 2) * 64 * HDIM;
            uint32_t d = sb + AT_S((st + 2) % 3);
            cp_tile64(d,         Kh + go, tid);
            cp_tile64(d + 8192,  Klp + go, tid);
            cp_tile64(d + 16384, Vh + go, tid);
            cp_tile64(d + 24576, Vlp + go, tid);
            CP_COMMIT();
        }
    }

    // ---- rowsum reduce (shfl-only) + normalize + split-store O ----
    rs0 += __shfl_xor_sync(0xffffffff, rs0, 1);
    rs0 += __shfl_xor_sync(0xffffffff, rs0, 2);
    rs1 += __shfl_xor_sync(0xffffffff, rs1, 1);
    rs1 += __shfl_xor_sync(0xffffffff, rs1, 2);
    float inv0 = 1.0f / rs0, inv1 = 1.0f / rs1;

    int r0 = t0 + wid * 16 + (lane >> 2);
    #pragma unroll
    for (int dn = 0; dn < 8; dn++) {
        int d = h * HDIM + dn * 8 + 2 * tg;
        uint32_t ph, pl;
        split2(o[dn][0] * inv0, o[dn][1] * inv0, ph, pl);
        *(uint32_t*)(g_oh + (size_t)r0 * DMODEL + d) = ph;
        *(uint32_t*)(g_ol + (size_t)r0 * DMODEL + d) = pl;
        split2(o[dn][2] * inv1, o[dn][3] * inv1, ph, pl);
        *(uint32_t*)(g_oh + (size_t)(r0 + 8) * DMODEL + d) = ph;
        *(uint32_t*)(g_ol + (size_t)(r0 + 8) * DMODEL + d) = pl;
    }
}

// ============================================================================
extern "C" void kernel_launch(void* const* d_in, const int* in_sizes, int n_in,
                              void* d_out, int out_size)
{
    const float* x  = (const float*)d_in[0];
    const float* Wq = (const float*)d_in[1];
    const float* bq = (const float*)d_in[2];
    const float* Wk = (const float*)d_in[3];
    const float* bk = (const float*)d_in[4];
    const float* Wv = (const float*)d_in[5];
    const float* bv = (const float*)d_in[6];
    const float* Wo = (const float*)d_in[7];
    float* out = (float*)d_out;

    // Quake q_rsqrt(64) exact fp32 step order
    float xq = 64.0f;
    int ib;
    memcpy(&ib, &xq, 4);
    ib = 0x5f3759df - (ib >> 1);
    float y;
    memcpy(&y, &ib, 4);
    float t = 0.5f * xq;
    t = t * y;
    t = t * y;
    float scaling = y * (1.5f - t);

    cudaFuncSetAttribute(gemm_bf16, cudaFuncAttributeMaxDynamicSharedMemorySize, GEMM_SMEM);
    cudaFuncSetAttribute(attn_kernel, cudaFuncAttributeMaxDynamicSharedMemorySize, ATTN_SMEM);

    split_all<<<4096, 256>>>(x, Wq, Wk, Wv, Wo);

    // fused QKV projections (z = 0,1,2)
    dim3 qkv_grid(DMODEL / 128, TLEN / 128, 3);
    gemm_bf16<<<qkv_grid, 256, GEMM_SMEM>>>(0, -1, bq, bk, bv, out);

    attn_kernel<<<dim3(TLEN / 256, NHEADS), 512, ATTN_SMEM>>>(scaling);

    // output projection
    dim3 o_grid(DMODEL / 128, TLEN / 128, 1);
    gemm_bf16<<<o_grid, 256, GEMM_SMEM>>>(1, 3, nullptr, nullptr, nullptr, out);
}

// round 10
// speedup vs baseline: 1.7239x; 1.0980x over previous
#include <cuda_runtime.h>
#include <cuda_bf16.h>
#include <cstring>
#include <cstdint>

#define TLEN   4096
#define DMODEL 1024
#define NHEADS 16
#define HDIM   64

// ---------------- device scratch ----------------
__device__ __nv_bfloat16 g_xh[TLEN * DMODEL], g_xl[TLEN * DMODEL];
__device__ __nv_bfloat16 g_wh[4 * DMODEL * DMODEL], g_wl[4 * DMODEL * DMODEL];
__device__ __nv_bfloat16 g_qh[NHEADS * TLEN * HDIM], g_ql[NHEADS * TLEN * HDIM];
__device__ __nv_bfloat16 g_kh[NHEADS * TLEN * HDIM], g_kl[NHEADS * TLEN * HDIM];
__device__ __nv_bfloat16 g_vh[NHEADS * TLEN * HDIM], g_vl[NHEADS * TLEN * HDIM];
__device__ __nv_bfloat16 g_oh[TLEN * DMODEL], g_ol[TLEN * DMODEL];

// ---------------- fastexp_gist ----------------
__device__ __forceinline__ float fastexp_g(float x) {
    const float GA = (float)12102203.17133801;
    const float GB = (float)1064986823.010288;
    float y = __fadd_rn(__fmul_rn(GA, x), GB);
    int yi = (y < 8388608.0f || y > 2139095040.0f) ? 0 : __float2int_rz(y);
    return __int_as_float(yi);
}

// ---------------- helpers ----------------
__device__ __forceinline__ uint32_t sptr(const void* p) {
    return (uint32_t)__cvta_generic_to_shared(p);
}
__device__ __forceinline__ void ldsm4(uint32_t a, uint32_t* r) {
    asm volatile("ldmatrix.sync.aligned.m8n8.x4.shared.b16 {%0,%1,%2,%3}, [%4];"
                 : "=r"(r[0]), "=r"(r[1]), "=r"(r[2]), "=r"(r[3]) : "r"(a));
}
__device__ __forceinline__ void ldsm4t(uint32_t a, uint32_t* r) {
    asm volatile("ldmatrix.sync.aligned.m8n8.x4.trans.shared.b16 {%0,%1,%2,%3}, [%4];"
                 : "=r"(r[0]), "=r"(r[1]), "=r"(r[2]), "=r"(r[3]) : "r"(a));
}
__device__ __forceinline__ void mma16816(float* c, const uint32_t* a,
                                         uint32_t b0, uint32_t b1) {
    asm volatile(
        "mma.sync.aligned.m16n8k16.row.col.f32.bf16.bf16.f32 "
        "{%0,%1,%2,%3}, {%4,%5,%6,%7}, {%8,%9}, {%0,%1,%2,%3};"
        : "+f"(c[0]), "+f"(c[1]), "+f"(c[2]), "+f"(c[3])
        : "r"(a[0]), "r"(a[1]), "r"(a[2]), "r"(a[3]), "r"(b0), "r"(b1));
}
__device__ __forceinline__ int sw128B(int row, int ch) {
    return (row << 7) + ((ch ^ (row & 7)) << 4);
}
// fast split: packed bf16x2 cvt
__device__ __forceinline__ void split2(float v0, float v1, uint32_t& ph, uint32_t& pl) {
    uint32_t h;
    asm("cvt.rn.bf16x2.f32 %0, %1, %2;" : "=r"(h) : "f"(v1), "f"(v0));
    float h0 = __uint_as_float(h << 16);
    float h1 = __uint_as_float(h & 0xffff0000u);
    uint32_t l;
    float r0 = v0 - h0, r1 = v1 - h1;
    asm("cvt.rn.bf16x2.f32 %0, %1, %2;" : "=r"(l) : "f"(r1), "f"(r0));
    ph = h; pl = l;
}
// single bf16x2 pack (no lo plane)
__device__ __forceinline__ uint32_t pack_bf16x2(float v0, float v1) {
    uint32_t h;
    asm("cvt.rn.bf16x2.f32 %0, %1, %2;" : "=r"(h) : "f"(v1), "f"(v0));
    return h;
}
// cp.async
__device__ __forceinline__ void cp16(uint32_t s, const void* g) {
    asm volatile("cp.async.cg.shared.global [%0], [%1], 16;" :: "r"(s), "l"(g));
}
#define CP_COMMIT() asm volatile("cp.async.commit_group;" ::: "memory")
#define CP_WAIT(n)  asm volatile("cp.async.wait_group %0;" :: "n"(n) : "memory")

// ---------------- fused split (fp32 -> bf16 hi/lo) ----------------
__global__ void split_all(const float* __restrict__ x, const float* __restrict__ wq,
                          const float* __restrict__ wk, const float* __restrict__ wv,
                          const float* __restrict__ wo) {
    const int total = TLEN * DMODEL + 4 * DMODEL * DMODEL;
    for (int i = blockIdx.x * blockDim.x + threadIdx.x; i < total;
         i += gridDim.x * blockDim.x) {
        const float* src;
        __nv_bfloat16 *hi, *lo;
        int off;
        if (i < TLEN * DMODEL) {
            src = x; hi = g_xh; lo = g_xl; off = i;
        } else {
            int j = i - TLEN * DMODEL;
            int w = j >> 20;
            off = j & ((1 << 20) - 1);
            src = (w == 0) ? wq : (w == 1) ? wk : (w == 2) ? wv : wo;
            hi = g_wh + ((size_t)w << 20);
            lo = g_wl + ((size_t)w << 20);
        }
        float v = src[off];
        __nv_bfloat16 h = __float2bfloat16(v);
        hi[off] = h;
        lo[off] = __float2bfloat16(v - __bfloat162float(h));
    }
}

// ============================================================================
// Split-bf16 mma.sync GEMM (KC=64, 3-stage cp.async, 1 sync per chunk).
// ============================================================================
#define GEMM_SMEM 196608

__device__ __forceinline__ void gemm_prefetch(uint32_t sb, int s, int kc,
                                              const __nv_bfloat16* Ah, const __nv_bfloat16* Al,
                                              const __nv_bfloat16* Wh, const __nv_bfloat16* Wl,
                                              int m0, int n0, int tid) {
    uint32_t base = sb + s * 65536;
    #pragma unroll
    for (int p = 0; p < 4; p++) {
        int idx = p * 256 + tid;
        int r = idx >> 3, ch = idx & 7;
        size_t ga = (size_t)(m0 + r) * DMODEL + kc * 64 + ch * 8;
        size_t gw = (size_t)(n0 + r) * DMODEL + kc * 64 + ch * 8;
        uint32_t so = sw128B(r, ch);
        cp16(base + so,          Ah + ga);
        cp16(base + 16384 + so,  Al + ga);
        cp16(base + 32768 + so,  Wh + gw);
        cp16(base + 49152 + so,  Wl + gw);
    }
}

__global__ __launch_bounds__(256, 1)
void gemm_bf16(int a_sel, int w_fixed, const float* __restrict__ bq,
               const float* __restrict__ bk, const float* __restrict__ bv,
               float* __restrict__ dout)
{
    extern __shared__ char sm[];
    uint32_t sb = sptr(sm);
    const int c_sel = (w_fixed < 0) ? (int)blockIdx.z : 3;
    const int w_idx = (w_fixed < 0) ? (int)blockIdx.z : w_fixed;
    const float* bias = (c_sel == 0) ? bq : (c_sel == 1) ? bk : (c_sel == 2) ? bv : nullptr;

    const __nv_bfloat16* Ah = a_sel ? g_oh : g_xh;
    const __nv_bfloat16* Al = a_sel ? g_ol : g_xl;
    const __nv_bfloat16* Wh = g_wh + (size_t)w_idx * DMODEL * DMODEL;
    const __nv_bfloat16* Wl = g_wl + (size_t)w_idx * DMODEL * DMODEL;

    const int tid = threadIdx.x;
    const int lane = tid & 31, wid = tid >> 5;
    const int g = lane >> 2, tg = lane & 3;
    const int wm = wid >> 2, wn = wid & 3;
    const int m0 = blockIdx.y * 128, n0 = blockIdx.x * 128;

    float c[4][4][4];
    #pragma unroll
    for (int i = 0; i < 4; i++)
        #pragma unroll
        for (int j = 0; j < 4; j++)
            #pragma unroll
            for (int e = 0; e < 4; e++) c[i][j][e] = 0.f;

    gemm_prefetch(sb, 0, 0, Ah, Al, Wh, Wl, m0, n0, tid);
    CP_COMMIT();
    gemm_prefetch(sb, 1, 1, Ah, Al, Wh, Wl, m0, n0, tid);
    CP_COMMIT();

    const int ar = lane & 15;
    const int br = ((lane >> 4) << 3) + (lane & 7);

    for (int kc = 0; kc < 16; kc++) {
        int s = kc % 3;
        if (kc < 15) { CP_WAIT(1); } else { CP_WAIT(0); }
        __syncthreads();

        uint32_t sAh = sb + s * 65536;
        uint32_t sAl = sAh + 16384;
        uint32_t sWh = sAh + 32768;
        uint32_t sWl = sAh + 49152;

        #pragma unroll
        for (int kt = 0; kt < 4; kt++) {
            uint32_t ah[4][4], al[4][4];
            const int ac = kt * 2 + (lane >> 4);
            #pragma unroll
            for (int mi = 0; mi < 4; mi++) {
                int r = wm * 64 + mi * 16 + ar;
                int off = sw128B(r, ac);
                ldsm4(sAh + off, ah[mi]);
                ldsm4(sAl + off, al[mi]);
            }
            uint32_t bh[2][4], bl[2][4];
            const int bc = kt * 2 + ((lane >> 3) & 1);
            #pragma unroll
            for (int pr = 0; pr < 2; pr++) {
                int r = wn * 32 + pr * 16 + br;
                int off = sw128B(r, bc);
                ldsm4(sWh + off, bh[pr]);
                ldsm4(sWl + off, bl[pr]);
            }
            #pragma unroll
            for (int mi = 0; mi < 4; mi++)
                #pragma unroll
                for (int ni = 0; ni < 4; ni++) {
                    uint32_t b0h = bh[ni >> 1][(ni & 1) * 2], b1h = bh[ni >> 1][(ni & 1) * 2 + 1];
                    uint32_t b0l = bl[ni >> 1][(ni & 1) * 2], b1l = bl[ni >> 1][(ni & 1) * 2 + 1];
                    mma16816(c[mi][ni], ah[mi], b0h, b1h);
                    mma16816(c[mi][ni], ah[mi], b0l, b1l);
                    mma16816(c[mi][ni], al[mi], b0h, b1h);
                }
        }

        if (kc + 2 < 16) {
            gemm_prefetch(sb, (kc + 2) % 3, kc + 2, Ah, Al, Wh, Wl, m0, n0, tid);
            CP_COMMIT();
        }
    }

    __nv_bfloat16 *dsth = nullptr, *dstl = nullptr;
    if (c_sel == 0) { dsth = g_qh; dstl = g_ql; }
    else if (c_sel == 1) { dsth = g_kh; dstl = g_kl; }
    else if (c_sel == 2) { dsth = g_vh; dstl = g_vl; }

    #pragma unroll
    for (int mi = 0; mi < 4; mi++)
        #pragma unroll
        for (int ni = 0; ni < 4; ni++)
            #pragma unroll
            for (int inst = 0; inst < 2; inst++) {
                int m = m0 + wm * 64 + mi * 16 + inst * 8 + g;
                int n = n0 + wn * 32 + ni * 8 + 2 * tg;
                float b0 = bias ? bias[n] : 0.f;
                float b1 = bias ? bias[n + 1] : 0.f;
                float v0 = c[mi][ni][inst * 2] + b0;
                float v1 = c[mi][ni][inst * 2 + 1] + b1;
                if (c_sel < 3) {
                    uint32_t ph, pl;
                    split2(v0, v1, ph, pl);
                    size_t addr = ((size_t)(n >> 6) * TLEN + m) * HDIM + (n & 63);
                    *(uint32_t*)(dsth + addr) = ph;
                    *(uint32_t*)(dstl + addr) = pl;
                } else {
                    float2 r; r.x = v0; r.y = v1;
                    *(float2*)(dout + (size_t)m * DMODEL + n) = r;
                }
            }
}

// ============================================================================
// Warp-strip attention: 512 threads, 256 q-rows per CTA; 64-key tiles,
// 3-stage cp.async, 1 sync per tile. PV uses SINGLE-bf16 E (2 MMA terms).
// ============================================================================
#define AT_QH    0
#define AT_QL    32768
#define AT_S(s)  (65536 + (s) * 32768)
#define ATTN_SMEM 163840
#define NT64     64

__device__ __forceinline__ void cp_tile64(uint32_t sdst, const __nv_bfloat16* g, int tid) {
    int r = tid >> 3, ch = tid & 7;
    cp16(sdst + sw128B(r, ch), g + (size_t)r * HDIM + ch * 8);
}
__device__ __forceinline__ void cp_tile256(uint32_t sdst, const __nv_bfloat16* g, int tid) {
    #pragma unroll
    for (int p = 0; p < 4; p++) {
        int idx = p * 512 + tid;
        int r = idx >> 3, ch = idx & 7;
        cp16(sdst + sw128B(r, ch), g + (size_t)r * HDIM + ch * 8);
    }
}

__global__ __launch_bounds__(512, 1)
void attn_kernel(float scaling)
{
    extern __shared__ char sm[];
    uint32_t sb = sptr(sm);
    const int tid = threadIdx.x;
    const int lane = tid & 31, wid = tid >> 5;   // wid 0..15
    const int tg = lane & 3;
    const int h = blockIdx.y;
    const int t0 = blockIdx.x * 256;

    const __nv_bfloat16* Kh  = g_kh + (size_t)h * TLEN * HDIM;
    const __nv_bfloat16* Klp = g_kl + (size_t)h * TLEN * HDIM;
    const __nv_bfloat16* Vh  = g_vh + (size_t)h * TLEN * HDIM;
    const __nv_bfloat16* Vlp = g_vl + (size_t)h * TLEN * HDIM;

    const int ar = lane & 15;
    const int br = ((lane >> 4) << 3) + (lane & 7);

    cp_tile256(sb + AT_QH, g_qh + ((size_t)h * TLEN + t0) * HDIM, tid);
    cp_tile256(sb + AT_QL, g_ql + ((size_t)h * TLEN + t0) * HDIM, tid);
    cp_tile64(sb + AT_S(0), Kh, tid);
    CP_COMMIT();
    cp_tile64(sb + AT_S(1), Kh + (size_t)64 * HDIM, tid);
    CP_COMMIT();

    CP_WAIT(1);
    __syncthreads();
    uint32_t qh[4][4], ql[4][4];
    #pragma unroll
    for (int kt = 0; kt < 4; kt++) {
        int ac = kt * 2 + (lane >> 4);
        ldsm4(sb + AT_QH + sw128B(wid * 16 + ar, ac), qh[kt]);
        ldsm4(sb + AT_QL + sw128B(wid * 16 + ar, ac), ql[kt]);
    }

    // =================== pass 1: rowmax (hi-only QK) ===================
    float rm0 = -3.402823466e38f, rm1 = -3.402823466e38f;
    for (int st = 0; st < NT64; st++) {
        if (st < NT64 - 1) { CP_WAIT(1); } else { CP_WAIT(0); }
        __syncthreads();
        uint32_t sKh = sb + AT_S(st % 3);

        #pragma unroll
        for (int n2 = 0; n2 < 4; n2++) {
            float c[2][4] = {{0.f, 0.f, 0.f, 0.f}, {0.f, 0.f, 0.f, 0.f}};
            #pragma unroll
            for (int kt = 0; kt < 4; kt++) {
                uint32_t bh[4];
                ldsm4(sKh + sw128B(n2 * 16 + br, kt * 2 + ((lane >> 3) & 1)), bh);
                mma16816(c[0], qh[kt], bh[0], bh[1]);
                mma16816(c[1], qh[kt], bh[2], bh[3]);
            }
            #pragma unroll
            for (int u = 0; u < 2; u++) {
                rm0 = fmaxf(rm0, fmaxf(__fmul_rn(c[u][0], scaling), __fmul_rn(c[u][1], scaling)));
                rm1 = fmaxf(rm1, fmaxf(__fmul_rn(c[u][2], scaling), __fmul_rn(c[u][3], scaling)));
            }
        }
        if (st + 2 < NT64) {
            cp_tile64(sb + AT_S((st + 2) % 3), Kh + (size_t)(st + 2) * 64 * HDIM, tid);
            CP_COMMIT();
        }
    }
    rm0 = fmaxf(rm0, __shfl_xor_sync(0xffffffff, rm0, 1));
    rm0 = fmaxf(rm0, __shfl_xor_sync(0xffffffff, rm0, 2));
    rm1 = fmaxf(rm1, __shfl_xor_sync(0xffffffff, rm1, 1));
    rm1 = fmaxf(rm1, __shfl_xor_sync(0xffffffff, rm1, 2));

    // =================== pass 2: exp + PV (single-bf16 E, 2 terms) ===========
    float o[8][4];
    #pragma unroll
    for (int i = 0; i < 8; i++)
        #pragma unroll
        for (int e = 0; e < 4; e++) o[i][e] = 0.f;
    float rs0 = 0.f, rs1 = 0.f;

    __syncthreads();
    #pragma unroll
    for (int t = 0; t < 2; t++) {
        size_t go = (size_t)t * 64 * HDIM;
        cp_tile64(sb + AT_S(t),         Kh + go, tid);
        cp_tile64(sb + AT_S(t) + 8192,  Klp + go, tid);
        cp_tile64(sb + AT_S(t) + 16384, Vh + go, tid);
        cp_tile64(sb + AT_S(t) + 24576, Vlp + go, tid);
        CP_COMMIT();
    }

    for (int st = 0; st < NT64; st++) {
        if (st < NT64 - 1) { CP_WAIT(1); } else { CP_WAIT(0); }
        __syncthreads();

        uint32_t sKh = sb + AT_S(st % 3), sKl = sKh + 8192;
        uint32_t sVh = sKh + 16384,       sVl = sKh + 24576;

        #pragma unroll
        for (int n2 = 0; n2 < 4; n2++) {
            float c[2][4] = {{0.f, 0.f, 0.f, 0.f}, {0.f, 0.f, 0.f, 0.f}};
            #pragma unroll
            for (int kt = 0; kt < 4; kt++) {
                uint32_t bh[4], bl[4];
                int soff = sw128B(n2 * 16 + br, kt * 2 + ((lane >> 3) & 1));
                ldsm4(sKh + soff, bh);
                ldsm4(sKl + soff, bl);
                mma16816(c[0], qh[kt], bh[0], bh[1]);
                mma16816(c[0], qh[kt], bl[0], bl[1]);
                mma16816(c[0], ql[kt], bh[0], bh[1]);
                mma16816(c[1], qh[kt], bh[2], bh[3]);
                mma16816(c[1], qh[kt], bl[2], bl[3]);
                mma16816(c[1], ql[kt], bh[2], bh[3]);
            }
            float e00 = fastexp_g(__fmul_rn(c[0][0], scaling) - rm0);
            float e01 = fastexp_g(__fmul_rn(c[0][1], scaling) - rm0);
            float e02 = fastexp_g(__fmul_rn(c[0][2], scaling) - rm1);
            float e03 = fastexp_g(__fmul_rn(c[0][3], scaling) - rm1);
            float e10 = fastexp_g(__fmul_rn(c[1][0], scaling) - rm0);
            float e11 = fastexp_g(__fmul_rn(c[1][1], scaling) - rm0);
            float e12 = fastexp_g(__fmul_rn(c[1][2], scaling) - rm1);
            float e13 = fastexp_g(__fmul_rn(c[1][3], scaling) - rm1);
            rs0 += e00 + e01 + e10 + e11;
            rs1 += e02 + e03 + e12 + e13;
            uint32_t eh[4];
            eh[0] = pack_bf16x2(e00, e01);
            eh[1] = pack_bf16x2(e02, e03);
            eh[2] = pack_bf16x2(e10, e11);
            eh[3] = pack_bf16x2(e12, e13);
            #pragma unroll
            for (int dg = 0; dg < 4; dg++) {
                uint32_t vh[4], vl[4];
                int voff = sw128B(n2 * 16 + ar, dg * 2 + (lane >> 4));
                ldsm4t(sVh + voff, vh);
                ldsm4t(sVl + voff, vl);
                mma16816(o[dg * 2],     eh, vh[0], vh[1]);
                mma16816(o[dg * 2],     eh, vl[0], vl[1]);
                mma16816(o[dg * 2 + 1], eh, vh[2], vh[3]);
                mma16816(o[dg * 2 + 1], eh, vl[2], vl[3]);
            }
        }

        if (st + 2 < NT64) {
            size_t go = (size_t)(st + 2) * 64 * HDIM;
            uint32_t d = sb + AT_S((st + 2) % 3);
            cp_tile64(d,         Kh + go, tid);
            cp_tile64(d + 8192,  Klp + go, tid);
            cp_tile64(d + 16384, Vh + go, tid);
            cp_tile64(d + 24576, Vlp + go, tid);
            CP_COMMIT();
        }
    }

    // ---- rowsum reduce (shfl-only) + normalize + split-store O ----
    rs0 += __shfl_xor_sync(0xffffffff, rs0, 1);
    rs0 += __shfl_xor_sync(0xffffffff, rs0, 2);
    rs1 += __shfl_xor_sync(0xffffffff, rs1, 1);
    rs1 += __shfl_xor_sync(0xffffffff, rs1, 2);
    float inv0 = 1.0f / rs0, inv1 = 1.0f / rs1;

    int r0 = t0 + wid * 16 + (lane >> 2);
    #pragma unroll
    for (int dn = 0; dn < 8; dn++) {
        int d = h * HDIM + dn * 8 + 2 * tg;
        uint32_t ph, pl;
        split2(o[dn][0] * inv0, o[dn][1] * inv0, ph, pl);
        *(uint32_t*)(g_oh + (size_t)r0 * DMODEL + d) = ph;
        *(uint32_t*)(g_ol + (size_t)r0 * DMODEL + d) = pl;
        split2(o[dn][2] * inv1, o[dn][3] * inv1, ph, pl);
        *(uint32_t*)(g_oh + (size_t)(r0 + 8) * DMODEL + d) = ph;
        *(uint32_t*)(g_ol + (size_t)(r0 + 8) * DMODEL + d) = pl;
    }
}

// ============================================================================
extern "C" void kernel_launch(void* const* d_in, const int* in_sizes, int n_in,
                              void* d_out, int out_size)
{
    const float* x  = (const float*)d_in[0];
    const float* Wq = (const float*)d_in[1];
    const float* bq = (const float*)d_in[2];
    const float* Wk = (const float*)d_in[3];
    const float* bk = (const float*)d_in[4];
    const float* Wv = (const float*)d_in[5];
    const float* bv = (const float*)d_in[6];
    const float* Wo = (const float*)d_in[7];
    float* out = (float*)d_out;

    // Quake q_rsqrt(64) exact fp32 step order
    float xq = 64.0f;
    int ib;
    memcpy(&ib, &xq, 4);
    ib = 0x5f3759df - (ib >> 1);
    float y;
    memcpy(&y, &ib, 4);
    float t = 0.5f * xq;
    t = t * y;
    t = t * y;
    float scaling = y * (1.5f - t);

    cudaFuncSetAttribute(gemm_bf16, cudaFuncAttributeMaxDynamicSharedMemorySize, GEMM_SMEM);
    cudaFuncSetAttribute(attn_kernel, cudaFuncAttributeMaxDynamicSharedMemorySize, ATTN_SMEM);

    split_all<<<4096, 256>>>(x, Wq, Wk, Wv, Wo);

    dim3 qkv_grid(DMODEL / 128, TLEN / 128, 3);
    gemm_bf16<<<qkv_grid, 256, GEMM_SMEM>>>(0, -1, bq, bk, bv, out);

    attn_kernel<<<dim3(TLEN / 256, NHEADS), 512, ATTN_SMEM>>>(scaling);

    dim3 o_grid(DMODEL / 128, TLEN / 128, 1);
    gemm_bf16<<<o_grid, 256, GEMM_SMEM>>>(1, 3, nullptr, nullptr, nullptr, out);
}

// round 11
// speedup vs baseline: 1.7782x; 1.0315x over previous
#include <cuda_runtime.h>
#include <cuda_bf16.h>
#include <cstring>
#include <cstdint>

#define TLEN   4096
#define DMODEL 1024
#define NHEADS 16
#define HDIM   64

// ---------------- device scratch ----------------
__device__ __nv_bfloat16 g_xh[TLEN * DMODEL], g_xl[TLEN * DMODEL];
__device__ __nv_bfloat16 g_wh[4 * DMODEL * DMODEL], g_wl[4 * DMODEL * DMODEL];
__device__ __nv_bfloat16 g_qh[NHEADS * TLEN * HDIM], g_ql[NHEADS * TLEN * HDIM];
__device__ __nv_bfloat16 g_kh[NHEADS * TLEN * HDIM], g_kl[NHEADS * TLEN * HDIM];
__device__ __nv_bfloat16 g_vh[NHEADS * TLEN * HDIM], g_vl[NHEADS * TLEN * HDIM];
__device__ __nv_bfloat16 g_oh[TLEN * DMODEL], g_ol[TLEN * DMODEL];

// ---------------- fastexp_gist ----------------
__device__ __forceinline__ float fastexp_g(float x) {
    const float GA = (float)12102203.17133801;
    const float GB = (float)1064986823.010288;
    float y = __fadd_rn(__fmul_rn(GA, x), GB);
    int yi = (y < 8388608.0f || y > 2139095040.0f) ? 0 : __float2int_rz(y);
    return __int_as_float(yi);
}

// ---------------- helpers ----------------
__device__ __forceinline__ uint32_t sptr(const void* p) {
    return (uint32_t)__cvta_generic_to_shared(p);
}
__device__ __forceinline__ void ldsm4(uint32_t a, uint32_t* r) {
    asm volatile("ldmatrix.sync.aligned.m8n8.x4.shared.b16 {%0,%1,%2,%3}, [%4];"
                 : "=r"(r[0]), "=r"(r[1]), "=r"(r[2]), "=r"(r[3]) : "r"(a));
}
__device__ __forceinline__ void ldsm4t(uint32_t a, uint32_t* r) {
    asm volatile("ldmatrix.sync.aligned.m8n8.x4.trans.shared.b16 {%0,%1,%2,%3}, [%4];"
                 : "=r"(r[0]), "=r"(r[1]), "=r"(r[2]), "=r"(r[3]) : "r"(a));
}
__device__ __forceinline__ void mma16816(float* c, const uint32_t* a,
                                         uint32_t b0, uint32_t b1) {
    asm volatile(
        "mma.sync.aligned.m16n8k16.row.col.f32.bf16.bf16.f32 "
        "{%0,%1,%2,%3}, {%4,%5,%6,%7}, {%8,%9}, {%0,%1,%2,%3};"
        : "+f"(c[0]), "+f"(c[1]), "+f"(c[2]), "+f"(c[3])
        : "r"(a[0]), "r"(a[1]), "r"(a[2]), "r"(a[3]), "r"(b0), "r"(b1));
}
__device__ __forceinline__ int sw128B(int row, int ch) {
    return (row << 7) + ((ch ^ (row & 7)) << 4);
}
// fast split: packed bf16x2 cvt
__device__ __forceinline__ void split2(float v0, float v1, uint32_t& ph, uint32_t& pl) {
    uint32_t h;
    asm("cvt.rn.bf16x2.f32 %0, %1, %2;" : "=r"(h) : "f"(v1), "f"(v0));
    float h0 = __uint_as_float(h << 16);
    float h1 = __uint_as_float(h & 0xffff0000u);
    uint32_t l;
    float r0 = v0 - h0, r1 = v1 - h1;
    asm("cvt.rn.bf16x2.f32 %0, %1, %2;" : "=r"(l) : "f"(r1), "f"(r0));
    ph = h; pl = l;
}
__device__ __forceinline__ uint32_t pack_bf16x2(float v0, float v1) {
    uint32_t h;
    asm("cvt.rn.bf16x2.f32 %0, %1, %2;" : "=r"(h) : "f"(v1), "f"(v0));
    return h;
}
// cp.async
__device__ __forceinline__ void cp16(uint32_t s, const void* g) {
    asm volatile("cp.async.cg.shared.global [%0], [%1], 16;" :: "r"(s), "l"(g));
}
#define CP_COMMIT() asm volatile("cp.async.commit_group;" ::: "memory")
#define CP_WAIT(n)  asm volatile("cp.async.wait_group %0;" :: "n"(n) : "memory")

// ---------------- fused split (fp32 -> bf16 hi/lo) ----------------
__global__ void split_all(const float* __restrict__ x, const float* __restrict__ wq,
                          const float* __restrict__ wk, const float* __restrict__ wv,
                          const float* __restrict__ wo) {
    const int total = TLEN * DMODEL + 4 * DMODEL * DMODEL;
    for (int i = blockIdx.x * blockDim.x + threadIdx.x; i < total;
         i += gridDim.x * blockDim.x) {
        const float* src;
        __nv_bfloat16 *hi, *lo;
        int off;
        if (i < TLEN * DMODEL) {
            src = x; hi = g_xh; lo = g_xl; off = i;
        } else {
            int j = i - TLEN * DMODEL;
            int w = j >> 20;
            off = j & ((1 << 20) - 1);
            src = (w == 0) ? wq : (w == 1) ? wk : (w == 2) ? wv : wo;
            hi = g_wh + ((size_t)w << 20);
            lo = g_wl + ((size_t)w << 20);
        }
        float v = src[off];
        __nv_bfloat16 h = __float2bfloat16(v);
        hi[off] = h;
        lo[off] = __float2bfloat16(v - __bfloat162float(h));
    }
}

// ============================================================================
// Split-bf16 mma.sync GEMM (KC=64, 3-stage cp.async, 1 sync per chunk).
// (unchanged from R10 — proven)
// ============================================================================
#define GEMM_SMEM 196608

__device__ __forceinline__ void gemm_prefetch(uint32_t sb, int s, int kc,
                                              const __nv_bfloat16* Ah, const __nv_bfloat16* Al,
                                              const __nv_bfloat16* Wh, const __nv_bfloat16* Wl,
                                              int m0, int n0, int tid) {
    uint32_t base = sb + s * 65536;
    #pragma unroll
    for (int p = 0; p < 4; p++) {
        int idx = p * 256 + tid;
        int r = idx >> 3, ch = idx & 7;
        size_t ga = (size_t)(m0 + r) * DMODEL + kc * 64 + ch * 8;
        size_t gw = (size_t)(n0 + r) * DMODEL + kc * 64 + ch * 8;
        uint32_t so = sw128B(r, ch);
        cp16(base + so,          Ah + ga);
        cp16(base + 16384 + so,  Al + ga);
        cp16(base + 32768 + so,  Wh + gw);
        cp16(base + 49152 + so,  Wl + gw);
    }
}

__global__ __launch_bounds__(256, 1)
void gemm_bf16(int a_sel, int w_fixed, const float* __restrict__ bq,
               const float* __restrict__ bk, const float* __restrict__ bv,
               float* __restrict__ dout)
{
    extern __shared__ char sm[];
    uint32_t sb = sptr(sm);
    const int c_sel = (w_fixed < 0) ? (int)blockIdx.z : 3;
    const int w_idx = (w_fixed < 0) ? (int)blockIdx.z : w_fixed;
    const float* bias = (c_sel == 0) ? bq : (c_sel == 1) ? bk : (c_sel == 2) ? bv : nullptr;

    const __nv_bfloat16* Ah = a_sel ? g_oh : g_xh;
    const __nv_bfloat16* Al = a_sel ? g_ol : g_xl;
    const __nv_bfloat16* Wh = g_wh + (size_t)w_idx * DMODEL * DMODEL;
    const __nv_bfloat16* Wl = g_wl + (size_t)w_idx * DMODEL * DMODEL;

    const int tid = threadIdx.x;
    const int lane = tid & 31, wid = tid >> 5;
    const int g = lane >> 2, tg = lane & 3;
    const int wm = wid >> 2, wn = wid & 3;
    const int m0 = blockIdx.y * 128, n0 = blockIdx.x * 128;

    float c[4][4][4];
    #pragma unroll
    for (int i = 0; i < 4; i++)
        #pragma unroll
        for (int j = 0; j < 4; j++)
            #pragma unroll
            for (int e = 0; e < 4; e++) c[i][j][e] = 0.f;

    gemm_prefetch(sb, 0, 0, Ah, Al, Wh, Wl, m0, n0, tid);
    CP_COMMIT();
    gemm_prefetch(sb, 1, 1, Ah, Al, Wh, Wl, m0, n0, tid);
    CP_COMMIT();

    const int ar = lane & 15;
    const int br = ((lane >> 4) << 3) + (lane & 7);

    for (int kc = 0; kc < 16; kc++) {
        int s = kc % 3;
        if (kc < 15) { CP_WAIT(1); } else { CP_WAIT(0); }
        __syncthreads();

        uint32_t sAh = sb + s * 65536;
        uint32_t sAl = sAh + 16384;
        uint32_t sWh = sAh + 32768;
        uint32_t sWl = sAh + 49152;

        #pragma unroll
        for (int kt = 0; kt < 4; kt++) {
            uint32_t ah[4][4], al[4][4];
            const int ac = kt * 2 + (lane >> 4);
            #pragma unroll
            for (int mi = 0; mi < 4; mi++) {
                int r = wm * 64 + mi * 16 + ar;
                int off = sw128B(r, ac);
                ldsm4(sAh + off, ah[mi]);
                ldsm4(sAl + off, al[mi]);
            }
            uint32_t bh[2][4], bl[2][4];
            const int bc = kt * 2 + ((lane >> 3) & 1);
            #pragma unroll
            for (int pr = 0; pr < 2; pr++) {
                int r = wn * 32 + pr * 16 + br;
                int off = sw128B(r, bc);
                ldsm4(sWh + off, bh[pr]);
                ldsm4(sWl + off, bl[pr]);
            }
            #pragma unroll
            for (int mi = 0; mi < 4; mi++)
                #pragma unroll
                for (int ni = 0; ni < 4; ni++) {
                    uint32_t b0h = bh[ni >> 1][(ni & 1) * 2], b1h = bh[ni >> 1][(ni & 1) * 2 + 1];
                    uint32_t b0l = bl[ni >> 1][(ni & 1) * 2], b1l = bl[ni >> 1][(ni & 1) * 2 + 1];
                    mma16816(c[mi][ni], ah[mi], b0h, b1h);
                    mma16816(c[mi][ni], ah[mi], b0l, b1l);
                    mma16816(c[mi][ni], al[mi], b0h, b1h);
                }
        }

        if (kc + 2 < 16) {
            gemm_prefetch(sb, (kc + 2) % 3, kc + 2, Ah, Al, Wh, Wl, m0, n0, tid);
            CP_COMMIT();
        }
    }

    __nv_bfloat16 *dsth = nullptr, *dstl = nullptr;
    if (c_sel == 0) { dsth = g_qh; dstl = g_ql; }
    else if (c_sel == 1) { dsth = g_kh; dstl = g_kl; }
    else if (c_sel == 2) { dsth = g_vh; dstl = g_vl; }

    #pragma unroll
    for (int mi = 0; mi < 4; mi++)
        #pragma unroll
        for (int ni = 0; ni < 4; ni++)
            #pragma unroll
            for (int inst = 0; inst < 2; inst++) {
                int m = m0 + wm * 64 + mi * 16 + inst * 8 + g;
                int n = n0 + wn * 32 + ni * 8 + 2 * tg;
                float b0 = bias ? bias[n] : 0.f;
                float b1 = bias ? bias[n + 1] : 0.f;
                float v0 = c[mi][ni][inst * 2] + b0;
                float v1 = c[mi][ni][inst * 2 + 1] + b1;
                if (c_sel < 3) {
                    uint32_t ph, pl;
                    split2(v0, v1, ph, pl);
                    size_t addr = ((size_t)(n >> 6) * TLEN + m) * HDIM + (n & 63);
                    *(uint32_t*)(dsth + addr) = ph;
                    *(uint32_t*)(dstl + addr) = pl;
                } else {
                    float2 r; r.x = v0; r.y = v1;
                    *(float2*)(dout + (size_t)m * DMODEL + n) = r;
                }
            }
}

// ============================================================================
// Warp-strip attention v2: 256 threads (8 warps), each warp owns 32 q-rows
// (mi=0,1) x all keys -> K/V fragment reads amortized over 2x the MMAs.
// 64-key tiles, 3-stage cp.async, 1 sync per tile. PV: single-bf16 E, 2 terms.
// SMEM: Q 64KB | 3 stages x 32KB = 160KB.
// ============================================================================
#define AT_QH    0
#define AT_QL    32768
#define AT_S(s)  (65536 + (s) * 32768)
#define ATTN_SMEM 163840
#define NT64     64

// one 64x64 bf16 plane, 256 threads: 2 cp16 each
__device__ __forceinline__ void cp_tile64(uint32_t sdst, const __nv_bfloat16* g, int tid) {
    #pragma unroll
    for (int p = 0; p < 2; p++) {
        int idx = p * 256 + tid;
        int r = idx >> 3, ch = idx & 7;
        cp16(sdst + sw128B(r, ch), g + (size_t)r * HDIM + ch * 8);
    }
}
// one 256x64 bf16 plane, 256 threads: 8 cp16 each
__device__ __forceinline__ void cp_tile256(uint32_t sdst, const __nv_bfloat16* g, int tid) {
    #pragma unroll
    for (int p = 0; p < 8; p++) {
        int idx = p * 256 + tid;
        int r = idx >> 3, ch = idx & 7;
        cp16(sdst + sw128B(r, ch), g + (size_t)r * HDIM + ch * 8);
    }
}

__global__ __launch_bounds__(256, 1)
void attn_kernel(float scaling)
{
    extern __shared__ char sm[];
    uint32_t sb = sptr(sm);
    const int tid = threadIdx.x;
    const int lane = tid & 31, wid = tid >> 5;   // wid 0..7, owns rows [wid*32, wid*32+32)
    const int tg = lane & 3;
    const int h = blockIdx.y;
    const int t0 = blockIdx.x * 256;

    const __nv_bfloat16* Kh  = g_kh + (size_t)h * TLEN * HDIM;
    const __nv_bfloat16* Klp = g_kl + (size_t)h * TLEN * HDIM;
    const __nv_bfloat16* Vh  = g_vh + (size_t)h * TLEN * HDIM;
    const __nv_bfloat16* Vlp = g_vl + (size_t)h * TLEN * HDIM;

    const int ar = lane & 15;
    const int br = ((lane >> 4) << 3) + (lane & 7);

    cp_tile256(sb + AT_QH, g_qh + ((size_t)h * TLEN + t0) * HDIM, tid);
    cp_tile256(sb + AT_QL, g_ql + ((size_t)h * TLEN + t0) * HDIM, tid);
    cp_tile64(sb + AT_S(0), Kh, tid);
    CP_COMMIT();
    cp_tile64(sb + AT_S(1), Kh + (size_t)64 * HDIM, tid);
    CP_COMMIT();

    CP_WAIT(1);
    __syncthreads();
    uint32_t qh[2][4][4], ql[2][4][4];
    #pragma unroll
    for (int mi = 0; mi < 2; mi++)
        #pragma unroll
        for (int kt = 0; kt < 4; kt++) {
            int ac = kt * 2 + (lane >> 4);
            int r = wid * 32 + mi * 16 + ar;
            ldsm4(sb + AT_QH + sw128B(r, ac), qh[mi][kt]);
            ldsm4(sb + AT_QL + sw128B(r, ac), ql[mi][kt]);
        }

    // =================== pass 1: rowmax (hi-only QK) ===================
    float rm[2][2];
    #pragma unroll
    for (int mi = 0; mi < 2; mi++) { rm[mi][0] = -3.402823466e38f; rm[mi][1] = -3.402823466e38f; }

    for (int st = 0; st < NT64; st++) {
        if (st < NT64 - 1) { CP_WAIT(1); } else { CP_WAIT(0); }
        __syncthreads();
        uint32_t sKh = sb + AT_S(st % 3);

        #pragma unroll
        for (int n2 = 0; n2 < 4; n2++) {
            float c[2][2][4];
            #pragma unroll
            for (int mi = 0; mi < 2; mi++)
                #pragma unroll
                for (int u = 0; u < 2; u++)
                    #pragma unroll
                    for (int e = 0; e < 4; e++) c[mi][u][e] = 0.f;
            #pragma unroll
            for (int kt = 0; kt < 4; kt++) {
                uint32_t bh[4];
                ldsm4(sKh + sw128B(n2 * 16 + br, kt * 2 + ((lane >> 3) & 1)), bh);
                #pragma unroll
                for (int mi = 0; mi < 2; mi++) {
                    mma16816(c[mi][0], qh[mi][kt], bh[0], bh[1]);
                    mma16816(c[mi][1], qh[mi][kt], bh[2], bh[3]);
                }
            }
            #pragma unroll
            for (int mi = 0; mi < 2; mi++)
                #pragma unroll
                for (int u = 0; u < 2; u++) {
                    rm[mi][0] = fmaxf(rm[mi][0], fmaxf(__fmul_rn(c[mi][u][0], scaling), __fmul_rn(c[mi][u][1], scaling)));
                    rm[mi][1] = fmaxf(rm[mi][1], fmaxf(__fmul_rn(c[mi][u][2], scaling), __fmul_rn(c[mi][u][3], scaling)));
                }
        }
        if (st + 2 < NT64) {
            cp_tile64(sb + AT_S((st + 2) % 3), Kh + (size_t)(st + 2) * 64 * HDIM, tid);
            CP_COMMIT();
        }
    }
    #pragma unroll
    for (int mi = 0; mi < 2; mi++)
        #pragma unroll
        for (int i = 0; i < 2; i++) {
            rm[mi][i] = fmaxf(rm[mi][i], __shfl_xor_sync(0xffffffff, rm[mi][i], 1));
            rm[mi][i] = fmaxf(rm[mi][i], __shfl_xor_sync(0xffffffff, rm[mi][i], 2));
        }

    // =================== pass 2: exp + PV (single-bf16 E, 2 terms) ===========
    float o[2][8][4];
    #pragma unroll
    for (int mi = 0; mi < 2; mi++)
        #pragma unroll
        for (int i = 0; i < 8; i++)
            #pragma unroll
            for (int e = 0; e < 4; e++) o[mi][i][e] = 0.f;
    float rs[2][2] = {{0.f, 0.f}, {0.f, 0.f}};

    __syncthreads();
    #pragma unroll
    for (int t = 0; t < 2; t++) {
        size_t go = (size_t)t * 64 * HDIM;
        cp_tile64(sb + AT_S(t),         Kh + go, tid);
        cp_tile64(sb + AT_S(t) + 8192,  Klp + go, tid);
        cp_tile64(sb + AT_S(t) + 16384, Vh + go, tid);
        cp_tile64(sb + AT_S(t) + 24576, Vlp + go, tid);
        CP_COMMIT();
    }

    for (int st = 0; st < NT64; st++) {
        if (st < NT64 - 1) { CP_WAIT(1); } else { CP_WAIT(0); }
        __syncthreads();

        uint32_t sKh = sb + AT_S(st % 3), sKl = sKh + 8192;
        uint32_t sVh = sKh + 16384,       sVl = sKh + 24576;

        #pragma unroll
        for (int n2 = 0; n2 < 4; n2++) {
            float c[2][2][4];
            #pragma unroll
            for (int mi = 0; mi < 2; mi++)
                #pragma unroll
                for (int u = 0; u < 2; u++)
                    #pragma unroll
                    for (int e = 0; e < 4; e++) c[mi][u][e] = 0.f;
            #pragma unroll
            for (int kt = 0; kt < 4; kt++) {
                uint32_t bh[4], bl[4];
                int soff = sw128B(n2 * 16 + br, kt * 2 + ((lane >> 3) & 1));
                ldsm4(sKh + soff, bh);
                ldsm4(sKl + soff, bl);
                #pragma unroll
                for (int mi = 0; mi < 2; mi++) {
                    mma16816(c[mi][0], qh[mi][kt], bh[0], bh[1]);
                    mma16816(c[mi][0], qh[mi][kt], bl[0], bl[1]);
                    mma16816(c[mi][0], ql[mi][kt], bh[0], bh[1]);
                    mma16816(c[mi][1], qh[mi][kt], bh[2], bh[3]);
                    mma16816(c[mi][1], qh[mi][kt], bl[2], bl[3]);
                    mma16816(c[mi][1], ql[mi][kt], bh[2], bh[3]);
                }
            }
            uint32_t eh[2][4];
            #pragma unroll
            for (int mi = 0; mi < 2; mi++) {
                float e00 = fastexp_g(__fmul_rn(c[mi][0][0], scaling) - rm[mi][0]);
                float e01 = fastexp_g(__fmul_rn(c[mi][0][1], scaling) - rm[mi][0]);
                float e02 = fastexp_g(__fmul_rn(c[mi][0][2], scaling) - rm[mi][1]);
                float e03 = fastexp_g(__fmul_rn(c[mi][0][3], scaling) - rm[mi][1]);
                float e10 = fastexp_g(__fmul_rn(c[mi][1][0], scaling) - rm[mi][0]);
                float e11 = fastexp_g(__fmul_rn(c[mi][1][1], scaling) - rm[mi][0]);
                float e12 = fastexp_g(__fmul_rn(c[mi][1][2], scaling) - rm[mi][1]);
                float e13 = fastexp_g(__fmul_rn(c[mi][1][3], scaling) - rm[mi][1]);
                rs[mi][0] += e00 + e01 + e10 + e11;
                rs[mi][1] += e02 + e03 + e12 + e13;
                eh[mi][0] = pack_bf16x2(e00, e01);
                eh[mi][1] = pack_bf16x2(e02, e03);
                eh[mi][2] = pack_bf16x2(e10, e11);
                eh[mi][3] = pack_bf16x2(e12, e13);
            }
            #pragma unroll
            for (int dg = 0; dg < 4; dg++) {
                uint32_t vh[4], vl[4];
                int voff = sw128B(n2 * 16 + ar, dg * 2 + (lane >> 4));
                ldsm4t(sVh + voff, vh);
                ldsm4t(sVl + voff, vl);
                #pragma unroll
                for (int mi = 0; mi < 2; mi++) {
                    mma16816(o[mi][dg * 2],     eh[mi], vh[0], vh[1]);
                    mma16816(o[mi][dg * 2],     eh[mi], vl[0], vl[1]);
                    mma16816(o[mi][dg * 2 + 1], eh[mi], vh[2], vh[3]);
                    mma16816(o[mi][dg * 2 + 1], eh[mi], vl[2], vl[3]);
                }
            }
        }

        if (st + 2 < NT64) {
            size_t go = (size_t)(st + 2) * 64 * HDIM;
            uint32_t d = sb + AT_S((st + 2) % 3);
            cp_tile64(d,         Kh + go, tid);
            cp_tile64(d + 8192,  Klp + go, tid);
            cp_tile64(d + 16384, Vh + go, tid);
            cp_tile64(d + 24576, Vlp + go, tid);
            CP_COMMIT();
        }
    }

    // ---- rowsum reduce (shfl-only) + normalize + split-store O ----
    #pragma unroll
    for (int mi = 0; mi < 2; mi++) {
        #pragma unroll
        for (int i = 0; i < 2; i++) {
            rs[mi][i] += __shfl_xor_sync(0xffffffff, rs[mi][i], 1);
            rs[mi][i] += __shfl_xor_sync(0xffffffff, rs[mi][i], 2);
        }
        float inv0 = 1.0f / rs[mi][0], inv1 = 1.0f / rs[mi][1];
        int r0 = t0 + wid * 32 + mi * 16 + (lane >> 2);
        #pragma unroll
        for (int dn = 0; dn < 8; dn++) {
            int d = h * HDIM + dn * 8 + 2 * tg;
            uint32_t ph, pl;
            split2(o[mi][dn][0] * inv0, o[mi][dn][1] * inv0, ph, pl);
            *(uint32_t*)(g_oh + (size_t)r0 * DMODEL + d) = ph;
            *(uint32_t*)(g_ol + (size_t)r0 * DMODEL + d) = pl;
            split2(o[mi][dn][2] * inv1, o[mi][dn][3] * inv1, ph, pl);
            *(uint32_t*)(g_oh + (size_t)(r0 + 8) * DMODEL + d) = ph;
            *(uint32_t*)(g_ol + (size_t)(r0 + 8) * DMODEL + d) = pl;
        }
    }
}

// ============================================================================
extern "C" void kernel_launch(void* const* d_in, const int* in_sizes, int n_in,
                              void* d_out, int out_size)
{
    const float* x  = (const float*)d_in[0];
    const float* Wq = (const float*)d_in[1];
    const float* bq = (const float*)d_in[2];
    const float* Wk = (const float*)d_in[3];
    const float* bk = (const float*)d_in[4];
    const float* Wv = (const float*)d_in[5];
    const float* bv = (const float*)d_in[6];
    const float* Wo = (const float*)d_in[7];
    float* out = (float*)d_out;

    // Quake q_rsqrt(64) exact fp32 step order
    float xq = 64.0f;
    int ib;
    memcpy(&ib, &xq, 4);
    ib = 0x5f3759df - (ib >> 1);
    float y;
    memcpy(&y, &ib, 4);
    float t = 0.5f * xq;
    t = t * y;
    t = t * y;
    float scaling = y * (1.5f - t);

    cudaFuncSetAttribute(gemm_bf16, cudaFuncAttributeMaxDynamicSharedMemorySize, GEMM_SMEM);
    cudaFuncSetAttribute(attn_kernel, cudaFuncAttributeMaxDynamicSharedMemorySize, ATTN_SMEM);

    split_all<<<4096, 256>>>(x, Wq, Wk, Wv, Wo);

    dim3 qkv_grid(DMODEL / 128, TLEN / 128, 3);
    gemm_bf16<<<qkv_grid, 256, GEMM_SMEM>>>(0, -1, bq, bk, bv, out);

    attn_kernel<<<dim3(TLEN / 256, NHEADS), 256, ATTN_SMEM>>>(scaling);

    dim3 o_grid(DMODEL / 128, TLEN / 128, 1);
    gemm_bf16<<<o_grid, 256, GEMM_SMEM>>>(1, 3, nullptr, nullptr, nullptr, out);
}

// round 12
// speedup vs baseline: 1.8478x; 1.0392x over previous
#include <cuda_runtime.h>
#include <cuda_bf16.h>
#include <cstring>
#include <cstdint>

#define TLEN   4096
#define DMODEL 1024
#define NHEADS 16
#define HDIM   64

// ---------------- device scratch ----------------
__device__ __nv_bfloat16 g_xh[TLEN * DMODEL], g_xl[TLEN * DMODEL];
__device__ __nv_bfloat16 g_wh[4 * DMODEL * DMODEL], g_wl[4 * DMODEL * DMODEL];
__device__ __nv_bfloat16 g_qh[NHEADS * TLEN * HDIM], g_ql[NHEADS * TLEN * HDIM];
__device__ __nv_bfloat16 g_kh[NHEADS * TLEN * HDIM], g_kl[NHEADS * TLEN * HDIM];
__device__ __nv_bfloat16 g_vh[NHEADS * TLEN * HDIM], g_vl[NHEADS * TLEN * HDIM];
__device__ __nv_bfloat16 g_oh[TLEN * DMODEL], g_ol[TLEN * DMODEL];

// ---------------- fastexp_gist (exact form, used outside hot loop) ----------
__device__ __forceinline__ float fastexp_g(float x) {
    const float GA = (float)12102203.17133801;
    const float GB = (float)1064986823.010288;
    float y = __fadd_rn(__fmul_rn(GA, x), GB);
    int yi = (y < 8388608.0f || y > 2139095040.0f) ? 0 : __float2int_rz(y);
    return __int_as_float(yi);
}
// hot-loop fused form: y = fma(s, GA*scal, GB - GA*rm). Upper clamp provably
// unreachable (s <= rm + ~1e-3  =>  y <= GB + ~1e4 << GD).
__device__ __forceinline__ float fexp_fused(float s, float gas, float crow) {
    float y = __fmaf_rn(s, gas, crow);
    int yi = (y < 8388608.0f) ? 0 : __float2int_rz(y);
    return __int_as_float(yi);
}

// ---------------- helpers ----------------
__device__ __forceinline__ uint32_t sptr(const void* p) {
    return (uint32_t)__cvta_generic_to_shared(p);
}
__device__ __forceinline__ void ldsm4(uint32_t a, uint32_t* r) {
    asm volatile("ldmatrix.sync.aligned.m8n8.x4.shared.b16 {%0,%1,%2,%3}, [%4];"
                 : "=r"(r[0]), "=r"(r[1]), "=r"(r[2]), "=r"(r[3]) : "r"(a));
}
__device__ __forceinline__ void ldsm4t(uint32_t a, uint32_t* r) {
    asm volatile("ldmatrix.sync.aligned.m8n8.x4.trans.shared.b16 {%0,%1,%2,%3}, [%4];"
                 : "=r"(r[0]), "=r"(r[1]), "=r"(r[2]), "=r"(r[3]) : "r"(a));
}
__device__ __forceinline__ void mma16816(float* c, const uint32_t* a,
                                         uint32_t b0, uint32_t b1) {
    asm volatile(
        "mma.sync.aligned.m16n8k16.row.col.f32.bf16.bf16.f32 "
        "{%0,%1,%2,%3}, {%4,%5,%6,%7}, {%8,%9}, {%0,%1,%2,%3};"
        : "+f"(c[0]), "+f"(c[1]), "+f"(c[2]), "+f"(c[3])
        : "r"(a[0]), "r"(a[1]), "r"(a[2]), "r"(a[3]), "r"(b0), "r"(b1));
}
__device__ __forceinline__ int sw128B(int row, int ch) {
    return (row << 7) + ((ch ^ (row & 7)) << 4);
}
// fast split: packed bf16x2 cvt
__device__ __forceinline__ void split2(float v0, float v1, uint32_t& ph, uint32_t& pl) {
    uint32_t h;
    asm("cvt.rn.bf16x2.f32 %0, %1, %2;" : "=r"(h) : "f"(v1), "f"(v0));
    float h0 = __uint_as_float(h << 16);
    float h1 = __uint_as_float(h & 0xffff0000u);
    uint32_t l;
    float r0 = v0 - h0, r1 = v1 - h1;
    asm("cvt.rn.bf16x2.f32 %0, %1, %2;" : "=r"(l) : "f"(r1), "f"(r0));
    ph = h; pl = l;
}
__device__ __forceinline__ uint32_t pack_bf16x2(float v0, float v1) {
    uint32_t h;
    asm("cvt.rn.bf16x2.f32 %0, %1, %2;" : "=r"(h) : "f"(v1), "f"(v0));
    return h;
}
// cp.async
__device__ __forceinline__ void cp16(uint32_t s, const void* g) {
    asm volatile("cp.async.cg.shared.global [%0], [%1], 16;" :: "r"(s), "l"(g));
}
#define CP_COMMIT() asm volatile("cp.async.commit_group;" ::: "memory")
#define CP_WAIT(n)  asm volatile("cp.async.wait_group %0;" :: "n"(n) : "memory")

// ---------------- fused split (fp32 -> bf16 hi/lo) ----------------
__global__ void split_all(const float* __restrict__ x, const float* __restrict__ wq,
                          const float* __restrict__ wk, const float* __restrict__ wv,
                          const float* __restrict__ wo) {
    const int total = TLEN * DMODEL + 4 * DMODEL * DMODEL;
    for (int i = blockIdx.x * blockDim.x + threadIdx.x; i < total;
         i += gridDim.x * blockDim.x) {
        const float* src;
        __nv_bfloat16 *hi, *lo;
        int off;
        if (i < TLEN * DMODEL) {
            src = x; hi = g_xh; lo = g_xl; off = i;
        } else {
            int j = i - TLEN * DMODEL;
            int w = j >> 20;
            off = j & ((1 << 20) - 1);
            src = (w == 0) ? wq : (w == 1) ? wk : (w == 2) ? wv : wo;
            hi = g_wh + ((size_t)w << 20);
            lo = g_wl + ((size_t)w << 20);
        }
        float v = src[off];
        __nv_bfloat16 h = __float2bfloat16(v);
        hi[off] = h;
        lo[off] = __float2bfloat16(v - __bfloat162float(h));
    }
}

// ============================================================================
// Split-bf16 mma.sync GEMM (KC=64, 3-stage cp.async, 1 sync per chunk).
// (unchanged — proven)
// ============================================================================
#define GEMM_SMEM 196608

__device__ __forceinline__ void gemm_prefetch(uint32_t sb, int s, int kc,
                                              const __nv_bfloat16* Ah, const __nv_bfloat16* Al,
                                              const __nv_bfloat16* Wh, const __nv_bfloat16* Wl,
                                              int m0, int n0, int tid) {
    uint32_t base = sb + s * 65536;
    #pragma unroll
    for (int p = 0; p < 4; p++) {
        int idx = p * 256 + tid;
        int r = idx >> 3, ch = idx & 7;
        size_t ga = (size_t)(m0 + r) * DMODEL + kc * 64 + ch * 8;
        size_t gw = (size_t)(n0 + r) * DMODEL + kc * 64 + ch * 8;
        uint32_t so = sw128B(r, ch);
        cp16(base + so,          Ah + ga);
        cp16(base + 16384 + so,  Al + ga);
        cp16(base + 32768 + so,  Wh + gw);
        cp16(base + 49152 + so,  Wl + gw);
    }
}

__global__ __launch_bounds__(256, 1)
void gemm_bf16(int a_sel, int w_fixed, const float* __restrict__ bq,
               const float* __restrict__ bk, const float* __restrict__ bv,
               float* __restrict__ dout)
{
    extern __shared__ char sm[];
    uint32_t sb = sptr(sm);
    const int c_sel = (w_fixed < 0) ? (int)blockIdx.z : 3;
    const int w_idx = (w_fixed < 0) ? (int)blockIdx.z : w_fixed;
    const float* bias = (c_sel == 0) ? bq : (c_sel == 1) ? bk : (c_sel == 2) ? bv : nullptr;

    const __nv_bfloat16* Ah = a_sel ? g_oh : g_xh;
    const __nv_bfloat16* Al = a_sel ? g_ol : g_xl;
    const __nv_bfloat16* Wh = g_wh + (size_t)w_idx * DMODEL * DMODEL;
    const __nv_bfloat16* Wl = g_wl + (size_t)w_idx * DMODEL * DMODEL;

    const int tid = threadIdx.x;
    const int lane = tid & 31, wid = tid >> 5;
    const int g = lane >> 2, tg = lane & 3;
    const int wm = wid >> 2, wn = wid & 3;
    const int m0 = blockIdx.y * 128, n0 = blockIdx.x * 128;

    float c[4][4][4];
    #pragma unroll
    for (int i = 0; i < 4; i++)
        #pragma unroll
        for (int j = 0; j < 4; j++)
            #pragma unroll
            for (int e = 0; e < 4; e++) c[i][j][e] = 0.f;

    gemm_prefetch(sb, 0, 0, Ah, Al, Wh, Wl, m0, n0, tid);
    CP_COMMIT();
    gemm_prefetch(sb, 1, 1, Ah, Al, Wh, Wl, m0, n0, tid);
    CP_COMMIT();

    const int ar = lane & 15;
    const int br = ((lane >> 4) << 3) + (lane & 7);

    for (int kc = 0; kc < 16; kc++) {
        int s = kc % 3;
        if (kc < 15) { CP_WAIT(1); } else { CP_WAIT(0); }
        __syncthreads();

        uint32_t sAh = sb + s * 65536;
        uint32_t sAl = sAh + 16384;
        uint32_t sWh = sAh + 32768;
        uint32_t sWl = sAh + 49152;

        #pragma unroll
        for (int kt = 0; kt < 4; kt++) {
            uint32_t ah[4][4], al[4][4];
            const int ac = kt * 2 + (lane >> 4);
            #pragma unroll
            for (int mi = 0; mi < 4; mi++) {
                int r = wm * 64 + mi * 16 + ar;
                int off = sw128B(r, ac);
                ldsm4(sAh + off, ah[mi]);
                ldsm4(sAl + off, al[mi]);
            }
            uint32_t bh[2][4], bl[2][4];
            const int bc = kt * 2 + ((lane >> 3) & 1);
            #pragma unroll
            for (int pr = 0; pr < 2; pr++) {
                int r = wn * 32 + pr * 16 + br;
                int off = sw128B(r, bc);
                ldsm4(sWh + off, bh[pr]);
                ldsm4(sWl + off, bl[pr]);
            }
            #pragma unroll
            for (int mi = 0; mi < 4; mi++)
                #pragma unroll
                for (int ni = 0; ni < 4; ni++) {
                    uint32_t b0h = bh[ni >> 1][(ni & 1) * 2], b1h = bh[ni >> 1][(ni & 1) * 2 + 1];
                    uint32_t b0l = bl[ni >> 1][(ni & 1) * 2], b1l = bl[ni >> 1][(ni & 1) * 2 + 1];
                    mma16816(c[mi][ni], ah[mi], b0h, b1h);
                    mma16816(c[mi][ni], ah[mi], b0l, b1l);
                    mma16816(c[mi][ni], al[mi], b0h, b1h);
                }
        }

        if (kc + 2 < 16) {
            gemm_prefetch(sb, (kc + 2) % 3, kc + 2, Ah, Al, Wh, Wl, m0, n0, tid);
            CP_COMMIT();
        }
    }

    __nv_bfloat16 *dsth = nullptr, *dstl = nullptr;
    if (c_sel == 0) { dsth = g_qh; dstl = g_ql; }
    else if (c_sel == 1) { dsth = g_kh; dstl = g_kl; }
    else if (c_sel == 2) { dsth = g_vh; dstl = g_vl; }

    #pragma unroll
    for (int mi = 0; mi < 4; mi++)
        #pragma unroll
        for (int ni = 0; ni < 4; ni++)
            #pragma unroll
            for (int inst = 0; inst < 2; inst++) {
                int m = m0 + wm * 64 + mi * 16 + inst * 8 + g;
                int n = n0 + wn * 32 + ni * 8 + 2 * tg;
                float b0 = bias ? bias[n] : 0.f;
                float b1 = bias ? bias[n + 1] : 0.f;
                float v0 = c[mi][ni][inst * 2] + b0;
                float v1 = c[mi][ni][inst * 2 + 1] + b1;
                if (c_sel < 3) {
                    uint32_t ph, pl;
                    split2(v0, v1, ph, pl);
                    size_t addr = ((size_t)(n >> 6) * TLEN + m) * HDIM + (n & 63);
                    *(uint32_t*)(dsth + addr) = ph;
                    *(uint32_t*)(dstl + addr) = pl;
                } else {
                    float2 r; r.x = v0; r.y = v1;
                    *(float2*)(dout + (size_t)m * DMODEL + n) = r;
                }
            }
}

// ============================================================================
// Warp-strip attention v3: 256 threads (8 warps), warp owns 32 q-rows.
// Pass-1 rowmax on RAW scores (scale folded once at the end).
// Pass-2 exp path fused to ONE FFMA per element: e = fexp(c, GAS, Crow).
// ============================================================================
#define AT_QH    0
#define AT_QL    32768
#define AT_S(s)  (65536 + (s) * 32768)
#define ATTN_SMEM 163840
#define NT64     64

__device__ __forceinline__ void cp_tile64(uint32_t sdst, const __nv_bfloat16* g, int tid) {
    #pragma unroll
    for (int p = 0; p < 2; p++) {
        int idx = p * 256 + tid;
        int r = idx >> 3, ch = idx & 7;
        cp16(sdst + sw128B(r, ch), g + (size_t)r * HDIM + ch * 8);
    }
}
__device__ __forceinline__ void cp_tile256(uint32_t sdst, const __nv_bfloat16* g, int tid) {
    #pragma unroll
    for (int p = 0; p < 8; p++) {
        int idx = p * 256 + tid;
        int r = idx >> 3, ch = idx & 7;
        cp16(sdst + sw128B(r, ch), g + (size_t)r * HDIM + ch * 8);
    }
}

__global__ __launch_bounds__(256, 1)
void attn_kernel(float scaling)
{
    extern __shared__ char sm[];
    uint32_t sb = sptr(sm);
    const int tid = threadIdx.x;
    const int lane = tid & 31, wid = tid >> 5;   // wid 0..7, rows [wid*32, wid*32+32)
    const int tg = lane & 3;
    const int h = blockIdx.y;
    const int t0 = blockIdx.x * 256;

    const float GA = (float)12102203.17133801;
    const float GB = (float)1064986823.010288;
    const float GAS = __fmul_rn(GA, scaling);

    const __nv_bfloat16* Kh  = g_kh + (size_t)h * TLEN * HDIM;
    const __nv_bfloat16* Klp = g_kl + (size_t)h * TLEN * HDIM;
    const __nv_bfloat16* Vh  = g_vh + (size_t)h * TLEN * HDIM;
    const __nv_bfloat16* Vlp = g_vl + (size_t)h * TLEN * HDIM;

    const int ar = lane & 15;
    const int br = ((lane >> 4) << 3) + (lane & 7);

    cp_tile256(sb + AT_QH, g_qh + ((size_t)h * TLEN + t0) * HDIM, tid);
    cp_tile256(sb + AT_QL, g_ql + ((size_t)h * TLEN + t0) * HDIM, tid);
    cp_tile64(sb + AT_S(0), Kh, tid);
    CP_COMMIT();
    cp_tile64(sb + AT_S(1), Kh + (size_t)64 * HDIM, tid);
    CP_COMMIT();

    CP_WAIT(1);
    __syncthreads();
    uint32_t qh[2][4][4], ql[2][4][4];
    #pragma unroll
    for (int mi = 0; mi < 2; mi++)
        #pragma unroll
        for (int kt = 0; kt < 4; kt++) {
            int ac = kt * 2 + (lane >> 4);
            int r = wid * 32 + mi * 16 + ar;
            ldsm4(sb + AT_QH + sw128B(r, ac), qh[mi][kt]);
            ldsm4(sb + AT_QL + sw128B(r, ac), ql[mi][kt]);
        }

    // =================== pass 1: rowmax on RAW scores ===================
    float rm[2][2];
    #pragma unroll
    for (int mi = 0; mi < 2; mi++) { rm[mi][0] = -3.402823466e38f; rm[mi][1] = -3.402823466e38f; }

    for (int st = 0; st < NT64; st++) {
        if (st < NT64 - 1) { CP_WAIT(1); } else { CP_WAIT(0); }
        __syncthreads();
        uint32_t sKh = sb + AT_S(st % 3);

        #pragma unroll
        for (int n2 = 0; n2 < 4; n2++) {
            float c[2][2][4];
            #pragma unroll
            for (int mi = 0; mi < 2; mi++)
                #pragma unroll
                for (int u = 0; u < 2; u++)
                    #pragma unroll
                    for (int e = 0; e < 4; e++) c[mi][u][e] = 0.f;
            #pragma unroll
            for (int kt = 0; kt < 4; kt++) {
                uint32_t bh[4];
                ldsm4(sKh + sw128B(n2 * 16 + br, kt * 2 + ((lane >> 3) & 1)), bh);
                #pragma unroll
                for (int mi = 0; mi < 2; mi++) {
                    mma16816(c[mi][0], qh[mi][kt], bh[0], bh[1]);
                    mma16816(c[mi][1], qh[mi][kt], bh[2], bh[3]);
                }
            }
            #pragma unroll
            for (int mi = 0; mi < 2; mi++)
                #pragma unroll
                for (int u = 0; u < 2; u++) {
                    rm[mi][0] = fmaxf(rm[mi][0], fmaxf(c[mi][u][0], c[mi][u][1]));
                    rm[mi][1] = fmaxf(rm[mi][1], fmaxf(c[mi][u][2], c[mi][u][3]));
                }
        }
        if (st + 2 < NT64) {
            cp_tile64(sb + AT_S((st + 2) % 3), Kh + (size_t)(st + 2) * 64 * HDIM, tid);
            CP_COMMIT();
        }
    }
    // fold scale once; build per-row fused constants Crow = GB - GA*(scal*max)
    float cr[2][2];
    #pragma unroll
    for (int mi = 0; mi < 2; mi++)
        #pragma unroll
        for (int i = 0; i < 2; i++) {
            float v = rm[mi][i];
            v = fmaxf(v, __shfl_xor_sync(0xffffffff, v, 1));
            v = fmaxf(v, __shfl_xor_sync(0xffffffff, v, 2));
            float rmx = __fmul_rn(v, scaling);
            rm[mi][i] = rmx;
            cr[mi][i] = __fmaf_rn(-GA, rmx, GB);
        }

    // =================== pass 2: fused exp + PV ===================
    float o[2][8][4];
    #pragma unroll
    for (int mi = 0; mi < 2; mi++)
        #pragma unroll
        for (int i = 0; i < 8; i++)
            #pragma unroll
            for (int e = 0; e < 4; e++) o[mi][i][e] = 0.f;
    float rs[2][2] = {{0.f, 0.f}, {0.f, 0.f}};

    __syncthreads();
    #pragma unroll
    for (int t = 0; t < 2; t++) {
        size_t go = (size_t)t * 64 * HDIM;
        cp_tile64(sb + AT_S(t),         Kh + go, tid);
        cp_tile64(sb + AT_S(t) + 8192,  Klp + go, tid);
        cp_tile64(sb + AT_S(t) + 16384, Vh + go, tid);
        cp_tile64(sb + AT_S(t) + 24576, Vlp + go, tid);
        CP_COMMIT();
    }

    for (int st = 0; st < NT64; st++) {
        if (st < NT64 - 1) { CP_WAIT(1); } else { CP_WAIT(0); }
        __syncthreads();

        uint32_t sKh = sb + AT_S(st % 3), sKl = sKh + 8192;
        uint32_t sVh = sKh + 16384,       sVl = sKh + 24576;

        #pragma unroll
        for (int n2 = 0; n2 < 4; n2++) {
            float c[2][2][4];
            #pragma unroll
            for (int mi = 0; mi < 2; mi++)
                #pragma unroll
                for (int u = 0; u < 2; u++)
                    #pragma unroll
                    for (int e = 0; e < 4; e++) c[mi][u][e] = 0.f;
            #pragma unroll
            for (int kt = 0; kt < 4; kt++) {
                uint32_t bh[4], bl[4];
                int soff = sw128B(n2 * 16 + br, kt * 2 + ((lane >> 3) & 1));
                ldsm4(sKh + soff, bh);
                ldsm4(sKl + soff, bl);
                #pragma unroll
                for (int mi = 0; mi < 2; mi++) {
                    mma16816(c[mi][0], qh[mi][kt], bh[0], bh[1]);
                    mma16816(c[mi][0], qh[mi][kt], bl[0], bl[1]);
                    mma16816(c[mi][0], ql[mi][kt], bh[0], bh[1]);
                    mma16816(c[mi][1], qh[mi][kt], bh[2], bh[3]);
                    mma16816(c[mi][1], qh[mi][kt], bl[2], bl[3]);
                    mma16816(c[mi][1], ql[mi][kt], bh[2], bh[3]);
                }
            }
            uint32_t eh[2][4];
            #pragma unroll
            for (int mi = 0; mi < 2; mi++) {
                float e00 = fexp_fused(c[mi][0][0], GAS, cr[mi][0]);
                float e01 = fexp_fused(c[mi][0][1], GAS, cr[mi][0]);
                float e02 = fexp_fused(c[mi][0][2], GAS, cr[mi][1]);
                float e03 = fexp_fused(c[mi][0][3], GAS, cr[mi][1]);
                float e10 = fexp_fused(c[mi][1][0], GAS, cr[mi][0]);
                float e11 = fexp_fused(c[mi][1][1], GAS, cr[mi][0]);
                float e12 = fexp_fused(c[mi][1][2], GAS, cr[mi][1]);
                float e13 = fexp_fused(c[mi][1][3], GAS, cr[mi][1]);
                rs[mi][0] += e00 + e01 + e10 + e11;
                rs[mi][1] += e02 + e03 + e12 + e13;
                eh[mi][0] = pack_bf16x2(e00, e01);
                eh[mi][1] = pack_bf16x2(e02, e03);
                eh[mi][2] = pack_bf16x2(e10, e11);
                eh[mi][3] = pack_bf16x2(e12, e13);
            }
            #pragma unroll
            for (int dg = 0; dg < 4; dg++) {
                uint32_t vh[4], vl[4];
                int voff = sw128B(n2 * 16 + ar, dg * 2 + (lane >> 4));
                ldsm4t(sVh + voff, vh);
                ldsm4t(sVl + voff, vl);
                #pragma unroll
                for (int mi = 0; mi < 2; mi++) {
                    mma16816(o[mi][dg * 2],     eh[mi], vh[0], vh[1]);
                    mma16816(o[mi][dg * 2],     eh[mi], vl[0], vl[1]);
                    mma16816(o[mi][dg * 2 + 1], eh[mi], vh[2], vh[3]);
                    mma16816(o[mi][dg * 2 + 1], eh[mi], vl[2], vl[3]);
                }
            }
        }

        if (st + 2 < NT64) {
            size_t go = (size_t)(st + 2) * 64 * HDIM;
            uint32_t d = sb + AT_S((st + 2) % 3);
            cp_tile64(d,         Kh + go, tid);
            cp_tile64(d + 8192,  Klp + go, tid);
            cp_tile64(d + 16384, Vh + go, tid);
            cp_tile64(d + 24576, Vlp + go, tid);
            CP_COMMIT();
        }
    }

    // ---- rowsum reduce (shfl-only) + normalize + split-store O ----
    #pragma unroll
    for (int mi = 0; mi < 2; mi++) {
        #pragma unroll
        for (int i = 0; i < 2; i++) {
            rs[mi][i] += __shfl_xor_sync(0xffffffff, rs[mi][i], 1);
            rs[mi][i] += __shfl_xor_sync(0xffffffff, rs[mi][i], 2);
        }
        float inv0 = 1.0f / rs[mi][0], inv1 = 1.0f / rs[mi][1];
        int r0 = t0 + wid * 32 + mi * 16 + (lane >> 2);
        #pragma unroll
        for (int dn = 0; dn < 8; dn++) {
            int d = h * HDIM + dn * 8 + 2 * tg;
            uint32_t ph, pl;
            split2(o[mi][dn][0] * inv0, o[mi][dn][1] * inv0, ph, pl);
            *(uint32_t*)(g_oh + (size_t)r0 * DMODEL + d) = ph;
            *(uint32_t*)(g_ol + (size_t)r0 * DMODEL + d) = pl;
            split2(o[mi][dn][2] * inv1, o[mi][dn][3] * inv1, ph, pl);
            *(uint32_t*)(g_oh + (size_t)(r0 + 8) * DMODEL + d) = ph;
            *(uint32_t*)(g_ol + (size_t)(r0 + 8) * DMODEL + d) = pl;
        }
    }
}

// ============================================================================
extern "C" void kernel_launch(void* const* d_in, const int* in_sizes, int n_in,
                              void* d_out, int out_size)
{
    const float* x  = (const float*)d_in[0];
    const float* Wq = (const float*)d_in[1];
    const float* bq = (const float*)d_in[2];
    const float* Wk = (const float*)d_in[3];
    const float* bk = (const float*)d_in[4];
    const float* Wv = (const float*)d_in[5];
    const float* bv = (const float*)d_in[6];
    const float* Wo = (const float*)d_in[7];
    float* out = (float*)d_out;

    // Quake q_rsqrt(64) exact fp32 step order
    float xq = 64.0f;
    int ib;
    memcpy(&ib, &xq, 4);
    ib = 0x5f3759df - (ib >> 1);
    float y;
    memcpy(&y, &ib, 4);
    float t = 0.5f * xq;
    t = t * y;
    t = t * y;
    float scaling = y * (1.5f - t);

    cudaFuncSetAttribute(gemm_bf16, cudaFuncAttributeMaxDynamicSharedMemorySize, GEMM_SMEM);
    cudaFuncSetAttribute(attn_kernel, cudaFuncAttributeMaxDynamicSharedMemorySize, ATTN_SMEM);

    split_all<<<4096, 256>>>(x, Wq, Wk, Wv, Wo);

    dim3 qkv_grid(DMODEL / 128, TLEN / 128, 3);
    gemm_bf16<<<qkv_grid, 256, GEMM_SMEM>>>(0, -1, bq, bk, bv, out);

    attn_kernel<<<dim3(TLEN / 256, NHEADS), 256, ATTN_SMEM>>>(scaling);

    dim3 o_grid(DMODEL / 128, TLEN / 128, 1);
    gemm_bf16<<<o_grid, 256, GEMM_SMEM>>>(1, 3, nullptr, nullptr, nullptr, out);
}